// round 7
// baseline (speedup 1.0000x reference)
#include <cuda_runtime.h>
#include <cooperative_groups.h>
#include <math.h>
#include <stdint.h>

namespace cg = cooperative_groups;

#define NN      96
#define NSQ     9216
#define NOFF    13
#define NNZ     119808
#define SIDE    816
#define BORD    24
#define KCONST  6.683942601602444f   /* 2*pi/0.94 */
#define OUTSIDE 768
#define OUTPLANE (OUTSIDE*OUTSIDE)

typedef unsigned long long u64;

// ---------------- scratch (static device globals; no allocation) ------------
__device__ float  g_hs[NSQ];
__device__ float  g_Eys[NSQ];
__device__ float  g_neff[NSQ];
__device__ float2 g_U0[NSQ];
__device__ float2 g_Uz[NSQ];
__device__ float  g_craw[NNZ];
__device__ float  g_kraw[NNZ];
__device__ float  g_m[NNZ];
__device__ float  g_ci[NNZ];

// ---------------- packed fp32x2 + approx tanh helpers ------------------------
__device__ __forceinline__ u64 fma2(u64 a, u64 b, u64 c)
{
    u64 d;
    asm("fma.rn.f32x2 %0, %1, %2, %3;" : "=l"(d) : "l"(a), "l"(b), "l"(c));
    return d;
}
__device__ __forceinline__ u64 dup2(float x)
{
    u64 d;
    unsigned r = __float_as_uint(x);
    asm("mov.b64 %0, {%1, %1};" : "=l"(d) : "r"(r));
    return d;
}
__device__ __forceinline__ float lo32(u64 v) { return __uint_as_float((unsigned)v); }
__device__ __forceinline__ float hi32(u64 v) { return __uint_as_float((unsigned)(v >> 32)); }
__device__ __forceinline__ float tanha(float x)
{
    float y;
    asm("tanh.approx.f32 %0, %1;" : "=f"(y) : "f"(x));
    return y;
}

// ---------------- kernel 1: hs / Eys / U0 (8x8 pooling) ---------------------
__global__ __launch_bounds__(256) void prep_kernel(const float* __restrict__ h_paras,
                                                   const float* __restrict__ E0)
{
    int p = blockIdx.x * 256 + threadIdx.x;
    if (p >= NSQ) return;
    float h  = h_paras[p];
    float s  = 1.f / (1.f + expf(-h));
    float hs = s * 0.6f + 0.2f;            // H_MIN + sig*(H_MAX-H_MIN)
    g_hs[p]  = hs;
    g_Eys[p] = 1.0f + 0.1f * tanhf(hs);
    float coupl = 0.5f + 0.5f * (1.f / (1.f + expf(-hs)));

    int i = p / NN, j = p % NN;
    const float* base = E0 + (size_t)(BORD + 8 * i) * SIDE + (BORD + 8 * j);
    float sum = 0.f;
    #pragma unroll
    for (int pi = 0; pi < 8; pi++) {
        float4 a = *(const float4*)(base + pi * SIDE);
        float4 b = *(const float4*)(base + pi * SIDE + 4);
        sum += (a.x + a.y) + (a.z + a.w) + (b.x + b.y) + (b.z + b.w);
    }
    g_U0[p] = make_float2(sum * (1.f / 64.f) * coupl, 0.f);
}

// ---------------- kernel 2: fused 3-layer MLP (mode 0=neff, 1=c, 2=k) -------
// 128 rows/block; 256 threads; 8x8 tiles via f32x2 packed FMA (pairs over rows).
// Edge MLPs (mode!=0) use hw tanh.approx; neff (mode 0) keeps accurate tanhf.
__global__ __launch_bounds__(256) void mlp_kernel(int mode,
    const float* __restrict__ w1, const float* __restrict__ b1,
    const float* __restrict__ w2, const float* __restrict__ b2,
    const float* __restrict__ w3, const float* __restrict__ b3,
    const float* __restrict__ dis, const int* __restrict__ coo)
{
    __shared__ float h1s[32 * 128];
    __shared__ float w2s[32 * 128];
    __shared__ float xs[4 * 128];
    __shared__ float red[16 * 128];

    int tid  = threadIdx.x;
    int base = blockIdx.x * 128;

    if (tid < 128) {
        int e = base + tid;
        if (mode == 0) {
            xs[tid] = g_hs[e];
        } else {
            int r = coo[e];
            int c = coo[NNZ + e];
            xs[tid]       = g_hs[r];
            xs[128 + tid] = g_hs[c];
            xs[256 + tid] = dis[2 * e];
            xs[384 + tid] = dis[2 * e + 1];
        }
    }
    __syncthreads();

    int tx = tid & 15, ty = tid >> 4;
    u64 acc2[4][8];
    #pragma unroll
    for (int p = 0; p < 4; p++)
        #pragma unroll
        for (int j = 0; j < 8; j++) acc2[p][j] = 0ull;

    for (int kb = 0; kb < 4; kb++) {
        // fill h1 chunk (layer-1 + tanh) and w2 chunk
        #pragma unroll
        for (int it = 0; it < 16; it++) {
            int idx = tid + it * 256;           // 0..4095
            int kk  = idx >> 7;                 // 0..31
            int e   = idx & 127;                // 0..127
            int k   = kb * 32 + kk;
            float a = b1[k] + xs[e] * w1[k];
            if (mode != 0) {
                a += xs[128 + e] * w1[128 + k] + xs[256 + e] * w1[256 + k]
                   + xs[384 + e] * w1[384 + k];
                h1s[kk * 128 + e] = tanha(a);
            } else {
                h1s[kk * 128 + e] = tanhf(a);
            }
            w2s[idx] = w2[kb * 4096 + idx];
        }
        __syncthreads();

        #pragma unroll 4
        for (int k = 0; k < 32; k++) {
            ulonglong2 A0 = *(const ulonglong2*)&h1s[k * 128 + tx * 8];
            ulonglong2 A1 = *(const ulonglong2*)&h1s[k * 128 + tx * 8 + 4];
            float4 c0 = *(const float4*)&w2s[k * 128 + ty * 8];
            float4 c1 = *(const float4*)&w2s[k * 128 + ty * 8 + 4];
            u64 ap[4] = {A0.x, A0.y, A1.x, A1.y};
            u64 bp[8] = {dup2(c0.x), dup2(c0.y), dup2(c0.z), dup2(c0.w),
                         dup2(c1.x), dup2(c1.y), dup2(c1.z), dup2(c1.w)};
            #pragma unroll
            for (int p = 0; p < 4; p++)
                #pragma unroll
                for (int j = 0; j < 8; j++)
                    acc2[p][j] = fma2(ap[p], bp[j], acc2[p][j]);
        }
        __syncthreads();
    }

    // layer 3: tanh + dot with w3, partial reduce over ty groups
    #pragma unroll
    for (int i = 0; i < 8; i++) {
        float part = 0.f;
        #pragma unroll
        for (int j = 0; j < 8; j++) {
            u64 v = acc2[i >> 1][j];
            float pre = ((i & 1) ? hi32(v) : lo32(v)) + b2[ty * 8 + j];
            float h2 = (mode != 0) ? tanha(pre) : tanhf(pre);
            part = fmaf(h2, w3[ty * 8 + j], part);
        }
        red[ty * 128 + tx * 8 + i] = part;
    }
    __syncthreads();
    if (tid < 128) {
        float s = b3[0];
        #pragma unroll
        for (int t = 0; t < 16; t++) s += red[t * 128 + tid];
        int e = base + tid;
        if (mode == 0)      g_neff[e] = s;
        else if (mode == 1) g_craw[e] = s;
        else                g_kraw[e] = s;
    }
}

// ---------------- kernel 3: edge coefficients -------------------------------
__global__ __launch_bounds__(256) void coeff_kernel(const float* __restrict__ mask,
                                                    const float* __restrict__ is_center)
{
    int e = blockIdx.x * 256 + threadIdx.x;
    if (e >= NNZ) return;
    float msk = mask[e];
    float ic  = is_center[e];
    float c   = msk * 0.05f * tanhf(g_craw[e]) + ic;
    float kv  = msk * 0.10f * tanhf(g_kraw[e]);
    int   r   = e / NOFF;                 // row (center point) by construction
    g_m[e]  = KCONST * g_neff[r] * c + kv;
    g_ci[e] = 2.0f * ic - c;
}

// ---------------- kernel 4: Euler loop --------------------------------------
// Out-of-grid taps have exactly-zero coefficients, so zero halos are correct.

__device__ __forceinline__ float2 sten13(const float* __restrict__ cf,
                                         const float2* __restrict__ buf,
                                         int s, int c)
{
    const int DI[13] = {0, 1, -1, 0, 0, 1, 1, -1, -1, 2, -2, 0, 0};
    const int DJ[13] = {0, 0, 0, 1, -1, 1, -1, 1, -1, 0, 0, 2, -2};
    float2 acc = make_float2(0.f, 0.f);
    #pragma unroll
    for (int o = 0; o < 13; o++) {
        float2 v = buf[(s + DI[o]) * 100 + (c + DJ[o])];
        acc.x = fmaf(cf[o], v.x, acc.x);
        acc.y = fmaf(cf[o], v.y, acc.y);
    }
    return acc;
}

__device__ __forceinline__ void nbar_wait(uint32_t addr, int parity)
{
    asm volatile(
        "{\n\t"
        ".reg .pred P;\n\t"
        "NW_%=:\n\t"
        "mbarrier.try_wait.parity.acquire.cluster.shared::cta.b64 P, [%0], %1, 0x989680;\n\t"
        "@P bra NWD_%=;\n\t"
        "bra NW_%=;\n\t"
        "NWD_%=:\n\t"
        "}"
        :: "r"(addr), "r"((unsigned)parity) : "memory");
}

__device__ __forceinline__ void nbar_arrive_remote(uint32_t remote_addr)
{
    asm volatile("mbarrier.arrive.release.cluster.shared::cluster.b64 _, [%0];"
                 :: "r"(remote_addr) : "memory");
}

// --- 16-CTA cluster: 6 rows/CTA, 1 point/thread, mbarrier neighbor sync -----
__global__ void __launch_bounds__(576, 1)
euler16_kernel(const int* __restrict__ steps_ptr)
{
    __shared__ float2 u_s[10 * 100];
    __shared__ float2 t_s[10 * 100];
    __shared__ __align__(8) unsigned long long nbar;

    cg::cluster_group cl = cg::this_cluster();
    int tid   = threadIdx.x;
    int rank  = blockIdx.x;
    int steps = *steps_ptr;
    float dz  = 1.5f / (float)steps;

    int n_nb = (rank > 0) + (rank < 15);

    uint32_t nbar_local = (uint32_t)__cvta_generic_to_shared(&nbar);
    if (tid == 0) {
        asm volatile("mbarrier.init.shared.b64 [%0], %1;"
                     :: "r"(nbar_local), "r"((unsigned)n_nb) : "memory");
    }

    for (int idx = tid; idx < 1000; idx += 576) {
        int s = idx / 100, c = idx % 100;
        int gi = rank * 6 + s - 2;
        int gj = c - 2;
        float2 v = make_float2(0.f, 0.f);
        if (gi >= 0 && gi < NN && gj >= 0 && gj < NN) v = g_U0[gi * NN + gj];
        u_s[idx] = v;
        t_s[idx] = make_float2(0.f, 0.f);
    }

    int li = tid / NN;           // 0..5
    int lj = tid % NN;           // 0..95
    int s  = li + 2, c = lj + 2;
    int p  = (rank * 6 + li) * NN + lj;

    float m[13], ci[13];
    #pragma unroll
    for (int o = 0; o < 13; o++) {
        m[o]  = g_m [p * NOFF + o];
        ci[o] = g_ci[p * NOFF + o];
    }

    float2* up_u = (rank > 0)  ? cl.map_shared_rank(u_s, rank - 1) : (float2*)0;
    float2* up_t = (rank > 0)  ? cl.map_shared_rank(t_s, rank - 1) : (float2*)0;
    float2* dn_u = (rank < 15) ? cl.map_shared_rank(u_s, rank + 1) : (float2*)0;
    float2* dn_t = (rank < 15) ? cl.map_shared_rank(t_s, rank + 1) : (float2*)0;

    uint32_t up_bar = 0, dn_bar = 0;
    if (rank > 0)
        asm("mapa.shared::cluster.u32 %0, %1, %2;" : "=r"(up_bar) : "r"(nbar_local), "r"(rank - 1));
    if (rank < 15)
        asm("mapa.shared::cluster.u32 %0, %1, %2;" : "=r"(dn_bar) : "r"(nbar_local), "r"(rank + 1));

    bool push_up = (rank > 0)  && (li < 2);   // local rows 0,1 -> up rank rows 8,9
    bool push_dn = (rank < 15) && (li >= 4);  // local rows 4,5 -> down rank rows 0,1
    int  up_off  = (li + 8) * 100 + c;
    int  dn_off  = (li - 4) * 100 + c;

    cl.sync();   // init (smem + mbarriers) visible cluster-wide

    int parity = 0;
    for (int st = 0; st < steps; st++) {
        float2 t0 = sten13(m, u_s, s, c);
        t_s[s * 100 + c] = t0;
        if (push_up) up_t[up_off] = t0;
        if (push_dn) dn_t[dn_off] = t0;
        __syncthreads();
        if (tid == 0) {
            asm volatile("fence.acq_rel.cluster;" ::: "memory");
            if (rank > 0)  nbar_arrive_remote(up_bar);
            if (rank < 15) nbar_arrive_remote(dn_bar);
        }
        nbar_wait(nbar_local, parity);
        parity ^= 1;

        float2 v0 = sten13(ci, t_s, s, c);
        float2 u0 = u_s[s * 100 + c];
        u0.x = fmaf(-dz, v0.y, u0.x);
        u0.y = fmaf( dz, v0.x, u0.y);
        u_s[s * 100 + c] = u0;
        if (push_up) up_u[up_off] = u0;
        if (push_dn) dn_u[dn_off] = u0;
        __syncthreads();
        if (tid == 0) {
            asm volatile("fence.acq_rel.cluster;" ::: "memory");
            if (rank > 0)  nbar_arrive_remote(up_bar);
            if (rank < 15) nbar_arrive_remote(dn_bar);
        }
        nbar_wait(nbar_local, parity);
        parity ^= 1;
    }

    g_Uz[p] = u_s[s * 100 + c];
    cl.sync();   // keep cluster alive until all CTAs done reading halos
}

// --- 8-CTA fallback (proven): 12 rows/CTA, 2 points/thread, cluster.sync ----
__global__ void __cluster_dims__(8, 1, 1) __launch_bounds__(576, 1)
euler8_kernel(const int* __restrict__ steps_ptr)
{
    __shared__ float2 u_s[16 * 100];
    __shared__ float2 t_s[16 * 100];

    cg::cluster_group cl = cg::this_cluster();
    int tid   = threadIdx.x;
    int rank  = blockIdx.x;
    int steps = *steps_ptr;
    float dz  = 1.5f / (float)steps;

    for (int idx = tid; idx < 1600; idx += 576) {
        int s = idx / 100, c = idx % 100;
        int gi = rank * 12 + s - 2;
        int gj = c - 2;
        float2 v = make_float2(0.f, 0.f);
        if (gi >= 0 && gi < NN && gj >= 0 && gj < NN) v = g_U0[gi * NN + gj];
        u_s[idx] = v;
        t_s[idx] = make_float2(0.f, 0.f);
    }

    int li0 = tid / NN, lj = tid % NN;
    int li1 = li0 + 6;
    int s0  = li0 + 2, s1 = li1 + 2, c = lj + 2;
    int p0  = (rank * 12 + li0) * NN + lj;
    int p1  = p0 + 6 * NN;

    float m0[13], ci0[13], m1[13], ci1[13];
    #pragma unroll
    for (int o = 0; o < 13; o++) {
        m0[o]  = g_m [p0 * NOFF + o];
        ci0[o] = g_ci[p0 * NOFF + o];
        m1[o]  = g_m [p1 * NOFF + o];
        ci1[o] = g_ci[p1 * NOFF + o];
    }

    float2* up_u = (rank > 0) ? cl.map_shared_rank(u_s, rank - 1) : (float2*)0;
    float2* up_t = (rank > 0) ? cl.map_shared_rank(t_s, rank - 1) : (float2*)0;
    float2* dn_u = (rank < 7) ? cl.map_shared_rank(u_s, rank + 1) : (float2*)0;
    float2* dn_t = (rank < 7) ? cl.map_shared_rank(t_s, rank + 1) : (float2*)0;

    bool push_up = (rank > 0) && (li0 < 2);
    bool push_dn = (rank < 7) && (li0 >= 4);
    int  up_off  = (li0 + 14) * 100 + c;
    int  dn_off  = (li1 - 10) * 100 + c;

    cl.sync();

    for (int st = 0; st < steps; st++) {
        float2 t0 = sten13(m0, u_s, s0, c);
        float2 t1 = sten13(m1, u_s, s1, c);
        t_s[s0 * 100 + c] = t0;
        t_s[s1 * 100 + c] = t1;
        if (push_up) up_t[up_off] = t0;
        if (push_dn) dn_t[dn_off] = t1;
        cl.sync();

        float2 v0 = sten13(ci0, t_s, s0, c);
        float2 v1 = sten13(ci1, t_s, s1, c);
        float2 u0 = u_s[s0 * 100 + c];
        float2 u1 = u_s[s1 * 100 + c];
        u0.x = fmaf(-dz, v0.y, u0.x); u0.y = fmaf(dz, v0.x, u0.y);
        u1.x = fmaf(-dz, v1.y, u1.x); u1.y = fmaf(dz, v1.x, u1.y);
        u_s[s0 * 100 + c] = u0;
        u_s[s1 * 100 + c] = u1;
        if (push_up) up_u[up_off] = u0;
        if (push_dn) dn_u[dn_off] = u1;
        cl.sync();
    }

    g_Uz[p0] = u_s[s0 * 100 + c];
    g_Uz[p1] = u_s[s1 * 100 + c];
}

// ---------------- kernel 5: outer-product expansion -------------------------
__global__ __launch_bounds__(256) void expand_kernel(const float* __restrict__ prof_re,
                                                     const float* __restrict__ prof_im,
                                                     float* __restrict__ out)
{
    int gid = blockIdx.x * 256 + threadIdx.x;
    if (gid >= OUTPLANE) return;
    int y = gid / OUTSIDE, x = gid - y * OUTSIDE;
    int i = y >> 3, p = y & 7;
    int j = x >> 3, q = x & 7;
    int cell = i * NN + j;
    float2 u = g_Uz[cell];
    float  e = g_Eys[cell];
    float gr = u.x * e, gi = u.y * e;
    float pr = prof_re[p * 8 + q];
    float pi = prof_im[p * 8 + q];
    out[gid]            = gr * pr - gi * pi;
    out[OUTPLANE + gid] = gr * pi + gi * pr;
}

// ---------------- launch ----------------------------------------------------
extern "C" void kernel_launch(void* const* d_in, const int* in_sizes, int n_in,
                              void* d_out, int out_size)
{
    const float* h_paras = (const float*)d_in[0];
    const float* E0      = (const float*)d_in[1];
    const float* w1n = (const float*)d_in[2];
    const float* b1n = (const float*)d_in[3];
    const float* w2n = (const float*)d_in[4];
    const float* b2n = (const float*)d_in[5];
    const float* w3n = (const float*)d_in[6];
    const float* b3n = (const float*)d_in[7];
    const float* w1c = (const float*)d_in[8];
    const float* b1c = (const float*)d_in[9];
    const float* w2c = (const float*)d_in[10];
    const float* b2c = (const float*)d_in[11];
    const float* w3c = (const float*)d_in[12];
    const float* b3c = (const float*)d_in[13];
    const float* w1k = (const float*)d_in[14];
    const float* b1k = (const float*)d_in[15];
    const float* w2k = (const float*)d_in[16];
    const float* b2k = (const float*)d_in[17];
    const float* w3k = (const float*)d_in[18];
    const float* b3k = (const float*)d_in[19];
    const float* prof_re = (const float*)d_in[20];
    const float* prof_im = (const float*)d_in[21];
    const float* dis     = (const float*)d_in[22];
    const float* mask    = (const float*)d_in[23];
    const float* is_ctr  = (const float*)d_in[24];
    const int*   coo     = (const int*)d_in[25];
    const int*   steps   = (const int*)d_in[26];
    float* out = (float*)d_out;

    prep_kernel<<<(NSQ + 255) / 256, 256>>>(h_paras, E0);
    mlp_kernel<<<NSQ / 128, 256>>>(0, w1n, b1n, w2n, b2n, w3n, b3n, dis, coo);
    mlp_kernel<<<NNZ / 128, 256>>>(1, w1c, b1c, w2c, b2c, w3c, b3c, dis, coo);
    mlp_kernel<<<NNZ / 128, 256>>>(2, w1k, b1k, w2k, b2k, w3k, b3k, dis, coo);
    coeff_kernel<<<(NNZ + 255) / 256, 256>>>(mask, is_ctr);

    // Euler: try 16-CTA cluster (nonportable), deterministic fallback to 8-CTA.
    cudaError_t err = cudaFuncSetAttribute(
        euler16_kernel, cudaFuncAttributeNonPortableClusterSizeAllowed, 1);
    if (err == cudaSuccess) {
        cudaLaunchConfig_t cfg = {};
        cfg.gridDim  = dim3(16, 1, 1);
        cfg.blockDim = dim3(576, 1, 1);
        cfg.dynamicSmemBytes = 0;
        cfg.stream = 0;
        cudaLaunchAttribute attrs[1];
        attrs[0].id = cudaLaunchAttributeClusterDimension;
        attrs[0].val.clusterDim.x = 16;
        attrs[0].val.clusterDim.y = 1;
        attrs[0].val.clusterDim.z = 1;
        cfg.attrs = attrs;
        cfg.numAttrs = 1;
        err = cudaLaunchKernelEx(&cfg, euler16_kernel, steps);
    }
    if (err != cudaSuccess) {
        cudaGetLastError();   // clear sticky state from the failed attempt
        euler8_kernel<<<8, 576>>>(steps);
    }

    expand_kernel<<<(OUTPLANE + 255) / 256, 256>>>(prof_re, prof_im, out);
}

// round 8
// speedup vs baseline: 1.3442x; 1.3442x over previous
#include <cuda_runtime.h>
#include <cooperative_groups.h>
#include <math.h>
#include <stdint.h>

namespace cg = cooperative_groups;

#define NN      96
#define NSQ     9216
#define NOFF    13
#define NNZ     119808
#define SIDE    816
#define BORD    24
#define KCONST  6.683942601602444f   /* 2*pi/0.94 */
#define OUTSIDE 768
#define OUTPLANE (OUTSIDE*OUTSIDE)

typedef unsigned long long u64;

// ---------------- scratch (static device globals; no allocation) ------------
__device__ float  g_hs[NSQ];
__device__ float  g_Eys[NSQ];
__device__ float  g_neff[NSQ];
__device__ float2 g_U0[NSQ];
__device__ float2 g_Uz[NSQ];
__device__ float  g_craw[NNZ];
__device__ float  g_kraw[NNZ];
__device__ float  g_m[NNZ];
__device__ float  g_ci[NNZ];

// ---------------- packed fp32x2 + approx tanh helpers ------------------------
__device__ __forceinline__ u64 fma2(u64 a, u64 b, u64 c)
{
    u64 d;
    asm("fma.rn.f32x2 %0, %1, %2, %3;" : "=l"(d) : "l"(a), "l"(b), "l"(c));
    return d;
}
__device__ __forceinline__ u64 dup2(float x)
{
    u64 d;
    unsigned r = __float_as_uint(x);
    asm("mov.b64 %0, {%1, %1};" : "=l"(d) : "r"(r));
    return d;
}
__device__ __forceinline__ float lo32(u64 v) { return __uint_as_float((unsigned)v); }
__device__ __forceinline__ float hi32(u64 v) { return __uint_as_float((unsigned)(v >> 32)); }
__device__ __forceinline__ float tanha(float x)
{
    float y;
    asm("tanh.approx.f32 %0, %1;" : "=f"(y) : "f"(x));
    return y;
}

// ---------------- kernel 1: hs / Eys / U0 (8x8 pooling) ---------------------
__global__ __launch_bounds__(256) void prep_kernel(const float* __restrict__ h_paras,
                                                   const float* __restrict__ E0)
{
    int p = blockIdx.x * 256 + threadIdx.x;
    if (p >= NSQ) return;
    float h  = h_paras[p];
    float s  = 1.f / (1.f + expf(-h));
    float hs = s * 0.6f + 0.2f;            // H_MIN + sig*(H_MAX-H_MIN)
    g_hs[p]  = hs;
    g_Eys[p] = 1.0f + 0.1f * tanhf(hs);
    float coupl = 0.5f + 0.5f * (1.f / (1.f + expf(-hs)));

    int i = p / NN, j = p % NN;
    const float* base = E0 + (size_t)(BORD + 8 * i) * SIDE + (BORD + 8 * j);
    float sum = 0.f;
    #pragma unroll
    for (int pi = 0; pi < 8; pi++) {
        float4 a = *(const float4*)(base + pi * SIDE);
        float4 b = *(const float4*)(base + pi * SIDE + 4);
        sum += (a.x + a.y) + (a.z + a.w) + (b.x + b.y) + (b.z + b.w);
    }
    g_U0[p] = make_float2(sum * (1.f / 64.f) * coupl, 0.f);
}

// ---------------- kernel 2: fused 3-layer MLP (mode 0=neff, 1=c, 2=k) -------
// 128 rows/block; 256 threads; 8x8 tiles via f32x2 packed FMA (pairs over rows).
// Edge MLPs (mode!=0) use hw tanh.approx; neff (mode 0) keeps accurate tanhf.
__global__ __launch_bounds__(256) void mlp_kernel(int mode,
    const float* __restrict__ w1, const float* __restrict__ b1,
    const float* __restrict__ w2, const float* __restrict__ b2,
    const float* __restrict__ w3, const float* __restrict__ b3,
    const float* __restrict__ dis, const int* __restrict__ coo)
{
    __shared__ float h1s[32 * 128];
    __shared__ float w2s[32 * 128];
    __shared__ float xs[4 * 128];
    __shared__ float red[16 * 128];

    int tid  = threadIdx.x;
    int base = blockIdx.x * 128;

    if (tid < 128) {
        int e = base + tid;
        if (mode == 0) {
            xs[tid] = g_hs[e];
        } else {
            int r = coo[e];
            int c = coo[NNZ + e];
            xs[tid]       = g_hs[r];
            xs[128 + tid] = g_hs[c];
            xs[256 + tid] = dis[2 * e];
            xs[384 + tid] = dis[2 * e + 1];
        }
    }
    __syncthreads();

    int tx = tid & 15, ty = tid >> 4;
    u64 acc2[4][8];
    #pragma unroll
    for (int p = 0; p < 4; p++)
        #pragma unroll
        for (int j = 0; j < 8; j++) acc2[p][j] = 0ull;

    for (int kb = 0; kb < 4; kb++) {
        // fill h1 chunk (layer-1 + tanh) and w2 chunk
        #pragma unroll
        for (int it = 0; it < 16; it++) {
            int idx = tid + it * 256;           // 0..4095
            int kk  = idx >> 7;                 // 0..31
            int e   = idx & 127;                // 0..127
            int k   = kb * 32 + kk;
            float a = b1[k] + xs[e] * w1[k];
            if (mode != 0) {
                a += xs[128 + e] * w1[128 + k] + xs[256 + e] * w1[256 + k]
                   + xs[384 + e] * w1[384 + k];
                h1s[kk * 128 + e] = tanha(a);
            } else {
                h1s[kk * 128 + e] = tanhf(a);
            }
            w2s[idx] = w2[kb * 4096 + idx];
        }
        __syncthreads();

        #pragma unroll 4
        for (int k = 0; k < 32; k++) {
            ulonglong2 A0 = *(const ulonglong2*)&h1s[k * 128 + tx * 8];
            ulonglong2 A1 = *(const ulonglong2*)&h1s[k * 128 + tx * 8 + 4];
            float4 c0 = *(const float4*)&w2s[k * 128 + ty * 8];
            float4 c1 = *(const float4*)&w2s[k * 128 + ty * 8 + 4];
            u64 ap[4] = {A0.x, A0.y, A1.x, A1.y};
            u64 bp[8] = {dup2(c0.x), dup2(c0.y), dup2(c0.z), dup2(c0.w),
                         dup2(c1.x), dup2(c1.y), dup2(c1.z), dup2(c1.w)};
            #pragma unroll
            for (int p = 0; p < 4; p++)
                #pragma unroll
                for (int j = 0; j < 8; j++)
                    acc2[p][j] = fma2(ap[p], bp[j], acc2[p][j]);
        }
        __syncthreads();
    }

    // layer 3: tanh + dot with w3, partial reduce over ty groups
    #pragma unroll
    for (int i = 0; i < 8; i++) {
        float part = 0.f;
        #pragma unroll
        for (int j = 0; j < 8; j++) {
            u64 v = acc2[i >> 1][j];
            float pre = ((i & 1) ? hi32(v) : lo32(v)) + b2[ty * 8 + j];
            float h2 = (mode != 0) ? tanha(pre) : tanhf(pre);
            part = fmaf(h2, w3[ty * 8 + j], part);
        }
        red[ty * 128 + tx * 8 + i] = part;
    }
    __syncthreads();
    if (tid < 128) {
        float s = b3[0];
        #pragma unroll
        for (int t = 0; t < 16; t++) s += red[t * 128 + tid];
        int e = base + tid;
        if (mode == 0)      g_neff[e] = s;
        else if (mode == 1) g_craw[e] = s;
        else                g_kraw[e] = s;
    }
}

// ---------------- kernel 3: edge coefficients -------------------------------
__global__ __launch_bounds__(256) void coeff_kernel(const float* __restrict__ mask,
                                                    const float* __restrict__ is_center)
{
    int e = blockIdx.x * 256 + threadIdx.x;
    if (e >= NNZ) return;
    float msk = mask[e];
    float ic  = is_center[e];
    float c   = msk * 0.05f * tanhf(g_craw[e]) + ic;
    float kv  = msk * 0.10f * tanhf(g_kraw[e]);
    int   r   = e / NOFF;                 // row (center point) by construction
    g_m[e]  = KCONST * g_neff[r] * c + kv;
    g_ci[e] = 2.0f * ic - c;
}

// ---------------- kernel 4: Euler loop --------------------------------------
// Out-of-grid taps have exactly-zero coefficients, so zero halos are correct.

__device__ __forceinline__ float2 sten13(const float* __restrict__ cf,
                                         const float2* __restrict__ buf,
                                         int s, int c)
{
    const int DI[13] = {0, 1, -1, 0, 0, 1, 1, -1, -1, 2, -2, 0, 0};
    const int DJ[13] = {0, 0, 0, 1, -1, 1, -1, 1, -1, 0, 0, 2, -2};
    float2 acc = make_float2(0.f, 0.f);
    #pragma unroll
    for (int o = 0; o < 13; o++) {
        float2 v = buf[(s + DI[o]) * 100 + (c + DJ[o])];
        acc.x = fmaf(cf[o], v.x, acc.x);
        acc.y = fmaf(cf[o], v.y, acc.y);
    }
    return acc;
}

#define CL_ARRIVE() asm volatile("barrier.cluster.arrive.aligned;" ::: "memory")
#define CL_WAIT()   asm volatile("barrier.cluster.wait.aligned;"   ::: "memory")

// --- 16-CTA cluster: 6 rows/CTA, 1 point/thread, split-barrier overlap ------
// Interior rows (li 2,3) read only own-CTA smem rows (taps +-2 within s=2..7),
// so they compute between arrive (release) + __syncthreads (CTA order) and the
// cluster wait (acquire of neighbor halos). Boundary rows compute after wait.
__global__ void __launch_bounds__(576, 1)
euler16_kernel(const int* __restrict__ steps_ptr)
{
    __shared__ float2 u_s[10 * 100];
    __shared__ float2 t_s[10 * 100];

    int tid   = threadIdx.x;
    int rank  = blockIdx.x;
    int steps = *steps_ptr;
    float dz  = 1.5f / (float)steps;

    for (int idx = tid; idx < 1000; idx += 576) {
        int s = idx / 100, c = idx % 100;
        int gi = rank * 6 + s - 2;
        int gj = c - 2;
        float2 v = make_float2(0.f, 0.f);
        if (gi >= 0 && gi < NN && gj >= 0 && gj < NN) v = g_U0[gi * NN + gj];
        u_s[idx] = v;
        t_s[idx] = make_float2(0.f, 0.f);
    }

    int li = tid / NN;           // 0..5
    int lj = tid % NN;           // 0..95
    int s  = li + 2, c = lj + 2;
    int p  = (rank * 6 + li) * NN + lj;
    bool interior = (li == 2) || (li == 3);

    float m[13], ci[13];
    #pragma unroll
    for (int o = 0; o < 13; o++) {
        m[o]  = g_m [p * NOFF + o];
        ci[o] = g_ci[p * NOFF + o];
    }

    cg::cluster_group cl = cg::this_cluster();
    float2* up_u = (rank > 0)  ? cl.map_shared_rank(u_s, rank - 1) : (float2*)0;
    float2* up_t = (rank > 0)  ? cl.map_shared_rank(t_s, rank - 1) : (float2*)0;
    float2* dn_u = (rank < 15) ? cl.map_shared_rank(u_s, rank + 1) : (float2*)0;
    float2* dn_t = (rank < 15) ? cl.map_shared_rank(t_s, rank + 1) : (float2*)0;

    bool push_up = (rank > 0)  && (li < 2);   // local rows 0,1 -> up rank rows 8,9
    bool push_dn = (rank < 15) && (li >= 4);  // local rows 4,5 -> down rank rows 0,1
    int  up_off  = (li + 8) * 100 + c;
    int  dn_off  = (li - 4) * 100 + c;

    CL_ARRIVE(); CL_WAIT();   // init visible cluster-wide

    for (int st = 0; st < steps; st++) {
        // ---- t = A1 * u ----
        float2 t0 = sten13(m, u_s, s, c);
        t_s[s * 100 + c] = t0;
        if (push_up) up_t[up_off] = t0;
        if (push_dn) dn_t[dn_off] = t0;
        CL_ARRIVE();
        __syncthreads();                      // own-CTA t stores visible
        float2 v0;
        if (interior) v0 = sten13(ci, t_s, s, c);
        CL_WAIT();                            // neighbor t halos visible
        if (!interior) v0 = sten13(ci, t_s, s, c);

        // ---- u += i*dz * (A2 * t) ----
        float2 u0 = u_s[s * 100 + c];
        u0.x = fmaf(-dz, v0.y, u0.x);
        u0.y = fmaf( dz, v0.x, u0.y);
        u_s[s * 100 + c] = u0;
        if (push_up) up_u[up_off] = u0;
        if (push_dn) dn_u[dn_off] = u0;
        CL_ARRIVE();
        __syncthreads();                      // own-CTA u stores visible
        float2 t1;
        if (st + 1 < steps) {
            if (interior) t1 = sten13(m, u_s, s, c);
            CL_WAIT();                        // neighbor u halos visible
            if (!interior) t1 = sten13(m, u_s, s, c);
            // feed next iteration's first stencil result
            t_s[s * 100 + c] = t1;
            if (push_up) up_t[up_off] = t1;
            if (push_dn) dn_t[dn_off] = t1;
            CL_ARRIVE();
            __syncthreads();
            if (interior) v0 = sten13(ci, t_s, s, c);
            CL_WAIT();
            if (!interior) v0 = sten13(ci, t_s, s, c);
            u0 = u_s[s * 100 + c];
            u0.x = fmaf(-dz, v0.y, u0.x);
            u0.y = fmaf( dz, v0.x, u0.y);
            u_s[s * 100 + c] = u0;
            if (push_up) up_u[up_off] = u0;
            if (push_dn) dn_u[dn_off] = u0;
            CL_ARRIVE();
            __syncthreads();
            CL_WAIT();
            st++;                             // did two steps this trip
        } else {
            CL_WAIT();
        }
    }

    g_Uz[p] = u_s[s * 100 + c];
}

// --- 8-CTA fallback (proven): 12 rows/CTA, 2 points/thread, cluster.sync ----
__global__ void __cluster_dims__(8, 1, 1) __launch_bounds__(576, 1)
euler8_kernel(const int* __restrict__ steps_ptr)
{
    __shared__ float2 u_s[16 * 100];
    __shared__ float2 t_s[16 * 100];

    cg::cluster_group cl = cg::this_cluster();
    int tid   = threadIdx.x;
    int rank  = blockIdx.x;
    int steps = *steps_ptr;
    float dz  = 1.5f / (float)steps;

    for (int idx = tid; idx < 1600; idx += 576) {
        int s = idx / 100, c = idx % 100;
        int gi = rank * 12 + s - 2;
        int gj = c - 2;
        float2 v = make_float2(0.f, 0.f);
        if (gi >= 0 && gi < NN && gj >= 0 && gj < NN) v = g_U0[gi * NN + gj];
        u_s[idx] = v;
        t_s[idx] = make_float2(0.f, 0.f);
    }

    int li0 = tid / NN, lj = tid % NN;
    int li1 = li0 + 6;
    int s0  = li0 + 2, s1 = li1 + 2, c = lj + 2;
    int p0  = (rank * 12 + li0) * NN + lj;
    int p1  = p0 + 6 * NN;

    float m0[13], ci0[13], m1[13], ci1[13];
    #pragma unroll
    for (int o = 0; o < 13; o++) {
        m0[o]  = g_m [p0 * NOFF + o];
        ci0[o] = g_ci[p0 * NOFF + o];
        m1[o]  = g_m [p1 * NOFF + o];
        ci1[o] = g_ci[p1 * NOFF + o];
    }

    float2* up_u = (rank > 0) ? cl.map_shared_rank(u_s, rank - 1) : (float2*)0;
    float2* up_t = (rank > 0) ? cl.map_shared_rank(t_s, rank - 1) : (float2*)0;
    float2* dn_u = (rank < 7) ? cl.map_shared_rank(u_s, rank + 1) : (float2*)0;
    float2* dn_t = (rank < 7) ? cl.map_shared_rank(t_s, rank + 1) : (float2*)0;

    bool push_up = (rank > 0) && (li0 < 2);
    bool push_dn = (rank < 7) && (li0 >= 4);
    int  up_off  = (li0 + 14) * 100 + c;
    int  dn_off  = (li1 - 10) * 100 + c;

    cl.sync();

    for (int st = 0; st < steps; st++) {
        float2 t0 = sten13(m0, u_s, s0, c);
        float2 t1 = sten13(m1, u_s, s1, c);
        t_s[s0 * 100 + c] = t0;
        t_s[s1 * 100 + c] = t1;
        if (push_up) up_t[up_off] = t0;
        if (push_dn) dn_t[dn_off] = t1;
        cl.sync();

        float2 v0 = sten13(ci0, t_s, s0, c);
        float2 v1 = sten13(ci1, t_s, s1, c);
        float2 u0 = u_s[s0 * 100 + c];
        float2 u1 = u_s[s1 * 100 + c];
        u0.x = fmaf(-dz, v0.y, u0.x); u0.y = fmaf(dz, v0.x, u0.y);
        u1.x = fmaf(-dz, v1.y, u1.x); u1.y = fmaf(dz, v1.x, u1.y);
        u_s[s0 * 100 + c] = u0;
        u_s[s1 * 100 + c] = u1;
        if (push_up) up_u[up_off] = u0;
        if (push_dn) dn_u[dn_off] = u1;
        cl.sync();
    }

    g_Uz[p0] = u_s[s0 * 100 + c];
    g_Uz[p1] = u_s[s1 * 100 + c];
}

// ---------------- kernel 5: outer-product expansion -------------------------
__global__ __launch_bounds__(256) void expand_kernel(const float* __restrict__ prof_re,
                                                     const float* __restrict__ prof_im,
                                                     float* __restrict__ out)
{
    int gid = blockIdx.x * 256 + threadIdx.x;
    if (gid >= OUTPLANE) return;
    int y = gid / OUTSIDE, x = gid - y * OUTSIDE;
    int i = y >> 3, p = y & 7;
    int j = x >> 3, q = x & 7;
    int cell = i * NN + j;
    float2 u = g_Uz[cell];
    float  e = g_Eys[cell];
    float gr = u.x * e, gi = u.y * e;
    float pr = prof_re[p * 8 + q];
    float pi = prof_im[p * 8 + q];
    out[gid]            = gr * pr - gi * pi;
    out[OUTPLANE + gid] = gr * pi + gi * pr;
}

// ---------------- launch ----------------------------------------------------
extern "C" void kernel_launch(void* const* d_in, const int* in_sizes, int n_in,
                              void* d_out, int out_size)
{
    const float* h_paras = (const float*)d_in[0];
    const float* E0      = (const float*)d_in[1];
    const float* w1n = (const float*)d_in[2];
    const float* b1n = (const float*)d_in[3];
    const float* w2n = (const float*)d_in[4];
    const float* b2n = (const float*)d_in[5];
    const float* w3n = (const float*)d_in[6];
    const float* b3n = (const float*)d_in[7];
    const float* w1c = (const float*)d_in[8];
    const float* b1c = (const float*)d_in[9];
    const float* w2c = (const float*)d_in[10];
    const float* b2c = (const float*)d_in[11];
    const float* w3c = (const float*)d_in[12];
    const float* b3c = (const float*)d_in[13];
    const float* w1k = (const float*)d_in[14];
    const float* b1k = (const float*)d_in[15];
    const float* w2k = (const float*)d_in[16];
    const float* b2k = (const float*)d_in[17];
    const float* w3k = (const float*)d_in[18];
    const float* b3k = (const float*)d_in[19];
    const float* prof_re = (const float*)d_in[20];
    const float* prof_im = (const float*)d_in[21];
    const float* dis     = (const float*)d_in[22];
    const float* mask    = (const float*)d_in[23];
    const float* is_ctr  = (const float*)d_in[24];
    const int*   coo     = (const int*)d_in[25];
    const int*   steps   = (const int*)d_in[26];
    float* out = (float*)d_out;

    prep_kernel<<<(NSQ + 255) / 256, 256>>>(h_paras, E0);
    mlp_kernel<<<NSQ / 128, 256>>>(0, w1n, b1n, w2n, b2n, w3n, b3n, dis, coo);
    mlp_kernel<<<NNZ / 128, 256>>>(1, w1c, b1c, w2c, b2c, w3c, b3c, dis, coo);
    mlp_kernel<<<NNZ / 128, 256>>>(2, w1k, b1k, w2k, b2k, w3k, b3k, dis, coo);
    coeff_kernel<<<(NNZ + 255) / 256, 256>>>(mask, is_ctr);

    // Euler: try 16-CTA cluster (nonportable), deterministic fallback to 8-CTA.
    cudaError_t err = cudaFuncSetAttribute(
        euler16_kernel, cudaFuncAttributeNonPortableClusterSizeAllowed, 1);
    if (err == cudaSuccess) {
        cudaLaunchConfig_t cfg = {};
        cfg.gridDim  = dim3(16, 1, 1);
        cfg.blockDim = dim3(576, 1, 1);
        cfg.dynamicSmemBytes = 0;
        cfg.stream = 0;
        cudaLaunchAttribute attrs[1];
        attrs[0].id = cudaLaunchAttributeClusterDimension;
        attrs[0].val.clusterDim.x = 16;
        attrs[0].val.clusterDim.y = 1;
        attrs[0].val.clusterDim.z = 1;
        cfg.attrs = attrs;
        cfg.numAttrs = 1;
        err = cudaLaunchKernelEx(&cfg, euler16_kernel, steps);
    }
    if (err != cudaSuccess) {
        cudaGetLastError();   // clear sticky state from the failed attempt
        euler8_kernel<<<8, 576>>>(steps);
    }

    expand_kernel<<<(OUTPLANE + 255) / 256, 256>>>(prof_re, prof_im, out);
}

// round 9
// speedup vs baseline: 1.3941x; 1.0372x over previous
#include <cuda_runtime.h>
#include <cooperative_groups.h>
#include <math.h>
#include <stdint.h>

namespace cg = cooperative_groups;

#define NN      96
#define NSQ     9216
#define NOFF    13
#define NNZ     119808
#define SIDE    816
#define BORD    24
#define KCONST  6.683942601602444f   /* 2*pi/0.94 */
#define OUTSIDE 768
#define OUTPLANE (OUTSIDE*OUTSIDE)

typedef unsigned long long u64;

// ---------------- scratch (static device globals; no allocation) ------------
__device__ float  g_hs[NSQ];
__device__ float  g_Eys[NSQ];
__device__ float  g_neff[NSQ];
__device__ float2 g_U0[NSQ];
__device__ float2 g_Uz[NSQ];
__device__ float  g_craw[NNZ];
__device__ float  g_kraw[NNZ];
__device__ float  g_m[NNZ];
__device__ float  g_ci[NNZ];

// ---------------- packed fp32x2 + approx tanh helpers ------------------------
__device__ __forceinline__ u64 fma2(u64 a, u64 b, u64 c)
{
    u64 d;
    asm("fma.rn.f32x2 %0, %1, %2, %3;" : "=l"(d) : "l"(a), "l"(b), "l"(c));
    return d;
}
__device__ __forceinline__ u64 dup2(float x)
{
    u64 d;
    unsigned r = __float_as_uint(x);
    asm("mov.b64 %0, {%1, %1};" : "=l"(d) : "r"(r));
    return d;
}
__device__ __forceinline__ float lo32(u64 v) { return __uint_as_float((unsigned)v); }
__device__ __forceinline__ float hi32(u64 v) { return __uint_as_float((unsigned)(v >> 32)); }
__device__ __forceinline__ float tanha(float x)
{
    float y;
    asm("tanh.approx.f32 %0, %1;" : "=f"(y) : "f"(x));
    return y;
}

// ---------------- kernel 1: hs / Eys / U0 (8x8 pooling) ---------------------
__global__ __launch_bounds__(256) void prep_kernel(const float* __restrict__ h_paras,
                                                   const float* __restrict__ E0)
{
    int p = blockIdx.x * 256 + threadIdx.x;
    if (p >= NSQ) return;
    float h  = h_paras[p];
    float s  = 1.f / (1.f + expf(-h));
    float hs = s * 0.6f + 0.2f;            // H_MIN + sig*(H_MAX-H_MIN)
    g_hs[p]  = hs;
    g_Eys[p] = 1.0f + 0.1f * tanhf(hs);
    float coupl = 0.5f + 0.5f * (1.f / (1.f + expf(-hs)));

    int i = p / NN, j = p % NN;
    const float* base = E0 + (size_t)(BORD + 8 * i) * SIDE + (BORD + 8 * j);
    float sum = 0.f;
    #pragma unroll
    for (int pi = 0; pi < 8; pi++) {
        float4 a = *(const float4*)(base + pi * SIDE);
        float4 b = *(const float4*)(base + pi * SIDE + 4);
        sum += (a.x + a.y) + (a.z + a.w) + (b.x + b.y) + (b.z + b.w);
    }
    g_U0[p] = make_float2(sum * (1.f / 64.f) * coupl, 0.f);
}

// ---------------- kernel 2: fused 3-layer MLP (mode 0=neff, 1=c, 2=k) -------
// 128 rows/block; 256 threads; 8x8 tiles via f32x2 packed FMA (pairs over rows).
// Edge MLPs (mode!=0) use hw tanh.approx; neff (mode 0) keeps accurate tanhf.
__global__ __launch_bounds__(256) void mlp_kernel(int mode,
    const float* __restrict__ w1, const float* __restrict__ b1,
    const float* __restrict__ w2, const float* __restrict__ b2,
    const float* __restrict__ w3, const float* __restrict__ b3,
    const float* __restrict__ dis, const int* __restrict__ coo)
{
    __shared__ float h1s[32 * 128];
    __shared__ float w2s[32 * 128];
    __shared__ float xs[4 * 128];
    __shared__ float red[16 * 128];

    int tid  = threadIdx.x;
    int base = blockIdx.x * 128;

    if (tid < 128) {
        int e = base + tid;
        if (mode == 0) {
            xs[tid] = g_hs[e];
        } else {
            int r = coo[e];
            int c = coo[NNZ + e];
            xs[tid]       = g_hs[r];
            xs[128 + tid] = g_hs[c];
            xs[256 + tid] = dis[2 * e];
            xs[384 + tid] = dis[2 * e + 1];
        }
    }
    __syncthreads();

    int tx = tid & 15, ty = tid >> 4;
    u64 acc2[4][8];
    #pragma unroll
    for (int p = 0; p < 4; p++)
        #pragma unroll
        for (int j = 0; j < 8; j++) acc2[p][j] = 0ull;

    for (int kb = 0; kb < 4; kb++) {
        // fill h1 chunk (layer-1 + tanh) and w2 chunk
        #pragma unroll
        for (int it = 0; it < 16; it++) {
            int idx = tid + it * 256;           // 0..4095
            int kk  = idx >> 7;                 // 0..31
            int e   = idx & 127;                // 0..127
            int k   = kb * 32 + kk;
            float a = b1[k] + xs[e] * w1[k];
            if (mode != 0) {
                a += xs[128 + e] * w1[128 + k] + xs[256 + e] * w1[256 + k]
                   + xs[384 + e] * w1[384 + k];
                h1s[kk * 128 + e] = tanha(a);
            } else {
                h1s[kk * 128 + e] = tanhf(a);
            }
            w2s[idx] = w2[kb * 4096 + idx];
        }
        __syncthreads();

        #pragma unroll 4
        for (int k = 0; k < 32; k++) {
            ulonglong2 A0 = *(const ulonglong2*)&h1s[k * 128 + tx * 8];
            ulonglong2 A1 = *(const ulonglong2*)&h1s[k * 128 + tx * 8 + 4];
            float4 c0 = *(const float4*)&w2s[k * 128 + ty * 8];
            float4 c1 = *(const float4*)&w2s[k * 128 + ty * 8 + 4];
            u64 ap[4] = {A0.x, A0.y, A1.x, A1.y};
            u64 bp[8] = {dup2(c0.x), dup2(c0.y), dup2(c0.z), dup2(c0.w),
                         dup2(c1.x), dup2(c1.y), dup2(c1.z), dup2(c1.w)};
            #pragma unroll
            for (int p = 0; p < 4; p++)
                #pragma unroll
                for (int j = 0; j < 8; j++)
                    acc2[p][j] = fma2(ap[p], bp[j], acc2[p][j]);
        }
        __syncthreads();
    }

    // layer 3: tanh + dot with w3, partial reduce over ty groups
    #pragma unroll
    for (int i = 0; i < 8; i++) {
        float part = 0.f;
        #pragma unroll
        for (int j = 0; j < 8; j++) {
            u64 v = acc2[i >> 1][j];
            float pre = ((i & 1) ? hi32(v) : lo32(v)) + b2[ty * 8 + j];
            float h2 = (mode != 0) ? tanha(pre) : tanhf(pre);
            part = fmaf(h2, w3[ty * 8 + j], part);
        }
        red[ty * 128 + tx * 8 + i] = part;
    }
    __syncthreads();
    if (tid < 128) {
        float s = b3[0];
        #pragma unroll
        for (int t = 0; t < 16; t++) s += red[t * 128 + tid];
        int e = base + tid;
        if (mode == 0)      g_neff[e] = s;
        else if (mode == 1) g_craw[e] = s;
        else                g_kraw[e] = s;
    }
}

// ---------------- kernel 3: edge coefficients -------------------------------
__global__ __launch_bounds__(256) void coeff_kernel(const float* __restrict__ mask,
                                                    const float* __restrict__ is_center)
{
    int e = blockIdx.x * 256 + threadIdx.x;
    if (e >= NNZ) return;
    float msk = mask[e];
    float ic  = is_center[e];
    float c   = msk * 0.05f * tanhf(g_craw[e]) + ic;
    float kv  = msk * 0.10f * tanhf(g_kraw[e]);
    int   r   = e / NOFF;                 // row (center point) by construction
    g_m[e]  = KCONST * g_neff[r] * c + kv;
    g_ci[e] = 2.0f * ic - c;
}

// ---------------- kernel 4: Euler loop --------------------------------------
// Out-of-grid taps have exactly-zero coefficients, so zero halos are correct.

#define CL_ARRIVE() asm volatile("barrier.cluster.arrive.aligned;" ::: "memory")
#define CL_WAIT()   asm volatile("barrier.cluster.wait.aligned;"   ::: "memory")

// 2x2-point register-tiled 13-tap stencil. 14 conflict-free LDS.128.
// Tap order o=0..12 identical to the edge/coefficient order.
__device__ __forceinline__ void sten2x2(const float cf[4][13],
                                        const float2* __restrict__ buf,
                                        int s, int c0, float2* __restrict__ out)
{
    float2 wm2[2], wm1[6], w0[6], wp1[6], wp2[6], wp3[2];
    {
        const float2* b;
        b = buf + (s - 2) * 100;
        *(float4*)&wm2[0] = *(const float4*)&b[c0];
        b = buf + (s - 1) * 100;
        *(float4*)&wm1[0] = *(const float4*)&b[c0 - 2];
        *(float4*)&wm1[2] = *(const float4*)&b[c0];
        *(float4*)&wm1[4] = *(const float4*)&b[c0 + 2];
        b = buf + s * 100;
        *(float4*)&w0[0]  = *(const float4*)&b[c0 - 2];
        *(float4*)&w0[2]  = *(const float4*)&b[c0];
        *(float4*)&w0[4]  = *(const float4*)&b[c0 + 2];
        b = buf + (s + 1) * 100;
        *(float4*)&wp1[0] = *(const float4*)&b[c0 - 2];
        *(float4*)&wp1[2] = *(const float4*)&b[c0];
        *(float4*)&wp1[4] = *(const float4*)&b[c0 + 2];
        b = buf + (s + 2) * 100;
        *(float4*)&wp2[0] = *(const float4*)&b[c0 - 2];
        *(float4*)&wp2[2] = *(const float4*)&b[c0];
        *(float4*)&wp2[4] = *(const float4*)&b[c0 + 2];
        b = buf + (s + 3) * 100;
        *(float4*)&wp3[0] = *(const float4*)&b[c0];
    }

#define ACC(o, v) { acc.x = fmaf(f[o], (v).x, acc.x); acc.y = fmaf(f[o], (v).y, acc.y); }

    #pragma unroll
    for (int k = 0; k < 2; k++) {
        // point (row r, col j+k)
        {
            const float* f = cf[k];
            float2 acc = make_float2(0.f, 0.f);
            ACC(0,  w0 [k + 2]);
            ACC(1,  wp1[k + 2]);
            ACC(2,  wm1[k + 2]);
            ACC(3,  w0 [k + 3]);
            ACC(4,  w0 [k + 1]);
            ACC(5,  wp1[k + 3]);
            ACC(6,  wp1[k + 1]);
            ACC(7,  wm1[k + 3]);
            ACC(8,  wm1[k + 1]);
            ACC(9,  wp2[k + 2]);
            ACC(10, wm2[k]);
            ACC(11, w0 [k + 4]);
            ACC(12, w0 [k]);
            out[k] = acc;
        }
        // point (row r+1, col j+k)
        {
            const float* f = cf[2 + k];
            float2 acc = make_float2(0.f, 0.f);
            ACC(0,  wp1[k + 2]);
            ACC(1,  wp2[k + 2]);
            ACC(2,  w0 [k + 2]);
            ACC(3,  wp1[k + 3]);
            ACC(4,  wp1[k + 1]);
            ACC(5,  wp2[k + 3]);
            ACC(6,  wp2[k + 1]);
            ACC(7,  w0 [k + 3]);
            ACC(8,  w0 [k + 1]);
            ACC(9,  wp3[k]);
            ACC(10, wm1[k + 2]);
            ACC(11, wp1[k + 4]);
            ACC(12, wp1[k]);
            out[2 + k] = acc;
        }
    }
#undef ACC
}

// --- 16-CTA cluster: 6 rows/CTA, 2x2 points/thread (144 thr), split barrier -
__global__ void __launch_bounds__(144, 1)
euler16_kernel(const int* __restrict__ steps_ptr)
{
    __shared__ float2 u_s[10 * 100];
    __shared__ float2 t_s[10 * 100];

    int tid   = threadIdx.x;
    int rank  = blockIdx.x;
    int steps = *steps_ptr;
    float dz  = 1.5f / (float)steps;

    // init own rows + halos from global U0 (out-of-grid -> 0); zero t
    for (int idx = tid; idx < 1000; idx += 144) {
        int s = idx / 100, c = idx % 100;
        int gi = rank * 6 + s - 2;
        int gj = c - 2;
        float2 v = make_float2(0.f, 0.f);
        if (gi >= 0 && gi < NN && gj >= 0 && gj < NN) v = g_U0[gi * NN + gj];
        u_s[idx] = v;
        t_s[idx] = make_float2(0.f, 0.f);
    }

    int tj = tid % 48;           // col pair 0..47
    int ti = tid / 48;           // row pair 0..2
    int li = 2 * ti;             // top row of pair: 0,2,4
    int j0 = 2 * tj;             // left grid col
    int s  = li + 2;             // smem row of point row
    int c0 = j0 + 2;             // smem col (even -> 16B aligned)
    bool interior = (ti == 1);   // rows 2,3: taps stay within own rows 0..5

    // per-point coefficients: pt 0=(r,j) 1=(r,j+1) 2=(r+1,j) 3=(r+1,j+1)
    float m[4][13], ci[4][13];
    #pragma unroll
    for (int pt = 0; pt < 4; pt++) {
        int row = li + (pt >> 1);
        int col = j0 + (pt & 1);
        int p   = (rank * 6 + row) * NN + col;
        #pragma unroll
        for (int o = 0; o < NOFF; o++) {
            m[pt][o]  = g_m [p * NOFF + o];
            ci[pt][o] = g_ci[p * NOFF + o];
        }
    }

    // own u in registers for the whole integration
    float2 uv[4];
    {
        int pr0 = (rank * 6 + li) * NN + j0;
        uv[0] = g_U0[pr0];
        uv[1] = g_U0[pr0 + 1];
        uv[2] = g_U0[pr0 + NN];
        uv[3] = g_U0[pr0 + NN + 1];
    }

    cg::cluster_group cl = cg::this_cluster();
    float2* up_u = (rank > 0)  ? cl.map_shared_rank(u_s, rank - 1) : (float2*)0;
    float2* up_t = (rank > 0)  ? cl.map_shared_rank(t_s, rank - 1) : (float2*)0;
    float2* dn_u = (rank < 15) ? cl.map_shared_rank(u_s, rank + 1) : (float2*)0;
    float2* dn_t = (rank < 15) ? cl.map_shared_rank(t_s, rank + 1) : (float2*)0;

    bool push_up = (rank > 0)  && (ti == 0);   // rows 0,1 -> up rank rows 8,9
    bool push_dn = (rank < 15) && (ti == 2);   // rows 4,5 -> down rank rows 0,1
    int  up_off0 = 8 * 100 + c0, up_off1 = 9 * 100 + c0;
    int  dn_off0 = 0 * 100 + c0, dn_off1 = 1 * 100 + c0;

#define STORE_PAIR(dst, v)                                     \
    { *(float4*)&(dst)[s * 100 + c0]       = *(float4*)&(v)[0]; \
      *(float4*)&(dst)[(s + 1) * 100 + c0] = *(float4*)&(v)[2]; }
#define PUSH_PAIR(up, dn, v)                                          \
    { if (push_up) { *(float4*)&(up)[up_off0] = *(float4*)&(v)[0];     \
                     *(float4*)&(up)[up_off1] = *(float4*)&(v)[2]; }   \
      if (push_dn) { *(float4*)&(dn)[dn_off0] = *(float4*)&(v)[0];     \
                     *(float4*)&(dn)[dn_off1] = *(float4*)&(v)[2]; } }

    __syncthreads();
    CL_ARRIVE(); CL_WAIT();        // all CTAs' smem init done before any push

    float2 tv[4], vv[4];
    // prologue: t0 = A1 * u  (halos valid from init)
    sten2x2(m, u_s, s, c0, tv);
    STORE_PAIR(t_s, tv);
    PUSH_PAIR(up_t, dn_t, tv);
    CL_ARRIVE();
    __syncthreads();

    for (int st = 0; ; st++) {
        // ---- v = A2 * t ; u += i*dz*v ----
        if (interior) sten2x2(ci, t_s, s, c0, vv);
        CL_WAIT();                               // neighbor t halos visible
        if (!interior) sten2x2(ci, t_s, s, c0, vv);
        #pragma unroll
        for (int q = 0; q < 4; q++) {
            uv[q].x = fmaf(-dz, vv[q].y, uv[q].x);
            uv[q].y = fmaf( dz, vv[q].x, uv[q].y);
        }
        if (st + 1 == steps) break;

        STORE_PAIR(u_s, uv);
        PUSH_PAIR(up_u, dn_u, uv);
        CL_ARRIVE();
        __syncthreads();

        // ---- t = A1 * u ----
        if (interior) sten2x2(m, u_s, s, c0, tv);
        CL_WAIT();                               // neighbor u halos visible
        if (!interior) sten2x2(m, u_s, s, c0, tv);
        STORE_PAIR(t_s, tv);
        PUSH_PAIR(up_t, dn_t, tv);
        CL_ARRIVE();
        __syncthreads();
    }

    // final u lives in registers
    {
        int pr0 = (rank * 6 + li) * NN + j0;
        g_Uz[pr0]          = uv[0];
        g_Uz[pr0 + 1]      = uv[1];
        g_Uz[pr0 + NN]     = uv[2];
        g_Uz[pr0 + NN + 1] = uv[3];
    }
#undef STORE_PAIR
#undef PUSH_PAIR
}

// --- 8-CTA fallback (proven): 12 rows/CTA, 2 points/thread, cluster.sync ----
__device__ __forceinline__ float2 sten13(const float* __restrict__ cf,
                                         const float2* __restrict__ buf,
                                         int s, int c)
{
    const int DI[13] = {0, 1, -1, 0, 0, 1, 1, -1, -1, 2, -2, 0, 0};
    const int DJ[13] = {0, 0, 0, 1, -1, 1, -1, 1, -1, 0, 0, 2, -2};
    float2 acc = make_float2(0.f, 0.f);
    #pragma unroll
    for (int o = 0; o < 13; o++) {
        float2 v = buf[(s + DI[o]) * 100 + (c + DJ[o])];
        acc.x = fmaf(cf[o], v.x, acc.x);
        acc.y = fmaf(cf[o], v.y, acc.y);
    }
    return acc;
}

__global__ void __cluster_dims__(8, 1, 1) __launch_bounds__(576, 1)
euler8_kernel(const int* __restrict__ steps_ptr)
{
    __shared__ float2 u_s[16 * 100];
    __shared__ float2 t_s[16 * 100];

    cg::cluster_group cl = cg::this_cluster();
    int tid   = threadIdx.x;
    int rank  = blockIdx.x;
    int steps = *steps_ptr;
    float dz  = 1.5f / (float)steps;

    for (int idx = tid; idx < 1600; idx += 576) {
        int s = idx / 100, c = idx % 100;
        int gi = rank * 12 + s - 2;
        int gj = c - 2;
        float2 v = make_float2(0.f, 0.f);
        if (gi >= 0 && gi < NN && gj >= 0 && gj < NN) v = g_U0[gi * NN + gj];
        u_s[idx] = v;
        t_s[idx] = make_float2(0.f, 0.f);
    }

    int li0 = tid / NN, lj = tid % NN;
    int li1 = li0 + 6;
    int s0  = li0 + 2, s1 = li1 + 2, c = lj + 2;
    int p0  = (rank * 12 + li0) * NN + lj;
    int p1  = p0 + 6 * NN;

    float m0[13], ci0[13], m1[13], ci1[13];
    #pragma unroll
    for (int o = 0; o < 13; o++) {
        m0[o]  = g_m [p0 * NOFF + o];
        ci0[o] = g_ci[p0 * NOFF + o];
        m1[o]  = g_m [p1 * NOFF + o];
        ci1[o] = g_ci[p1 * NOFF + o];
    }

    float2* up_u = (rank > 0) ? cl.map_shared_rank(u_s, rank - 1) : (float2*)0;
    float2* up_t = (rank > 0) ? cl.map_shared_rank(t_s, rank - 1) : (float2*)0;
    float2* dn_u = (rank < 7) ? cl.map_shared_rank(u_s, rank + 1) : (float2*)0;
    float2* dn_t = (rank < 7) ? cl.map_shared_rank(t_s, rank + 1) : (float2*)0;

    bool push_up = (rank > 0) && (li0 < 2);
    bool push_dn = (rank < 7) && (li0 >= 4);
    int  up_off  = (li0 + 14) * 100 + c;
    int  dn_off  = (li1 - 10) * 100 + c;

    cl.sync();

    for (int st = 0; st < steps; st++) {
        float2 t0 = sten13(m0, u_s, s0, c);
        float2 t1 = sten13(m1, u_s, s1, c);
        t_s[s0 * 100 + c] = t0;
        t_s[s1 * 100 + c] = t1;
        if (push_up) up_t[up_off] = t0;
        if (push_dn) dn_t[dn_off] = t1;
        cl.sync();

        float2 v0 = sten13(ci0, t_s, s0, c);
        float2 v1 = sten13(ci1, t_s, s1, c);
        float2 u0 = u_s[s0 * 100 + c];
        float2 u1 = u_s[s1 * 100 + c];
        u0.x = fmaf(-dz, v0.y, u0.x); u0.y = fmaf(dz, v0.x, u0.y);
        u1.x = fmaf(-dz, v1.y, u1.x); u1.y = fmaf(dz, v1.x, u1.y);
        u_s[s0 * 100 + c] = u0;
        u_s[s1 * 100 + c] = u1;
        if (push_up) up_u[up_off] = u0;
        if (push_dn) dn_u[dn_off] = u1;
        cl.sync();
    }

    g_Uz[p0] = u_s[s0 * 100 + c];
    g_Uz[p1] = u_s[s1 * 100 + c];
}

// ---------------- kernel 5: outer-product expansion -------------------------
__global__ __launch_bounds__(256) void expand_kernel(const float* __restrict__ prof_re,
                                                     const float* __restrict__ prof_im,
                                                     float* __restrict__ out)
{
    int gid = blockIdx.x * 256 + threadIdx.x;
    if (gid >= OUTPLANE) return;
    int y = gid / OUTSIDE, x = gid - y * OUTSIDE;
    int i = y >> 3, p = y & 7;
    int j = x >> 3, q = x & 7;
    int cell = i * NN + j;
    float2 u = g_Uz[cell];
    float  e = g_Eys[cell];
    float gr = u.x * e, gi = u.y * e;
    float pr = prof_re[p * 8 + q];
    float pi = prof_im[p * 8 + q];
    out[gid]            = gr * pr - gi * pi;
    out[OUTPLANE + gid] = gr * pi + gi * pr;
}

// ---------------- launch ----------------------------------------------------
extern "C" void kernel_launch(void* const* d_in, const int* in_sizes, int n_in,
                              void* d_out, int out_size)
{
    const float* h_paras = (const float*)d_in[0];
    const float* E0      = (const float*)d_in[1];
    const float* w1n = (const float*)d_in[2];
    const float* b1n = (const float*)d_in[3];
    const float* w2n = (const float*)d_in[4];
    const float* b2n = (const float*)d_in[5];
    const float* w3n = (const float*)d_in[6];
    const float* b3n = (const float*)d_in[7];
    const float* w1c = (const float*)d_in[8];
    const float* b1c = (const float*)d_in[9];
    const float* w2c = (const float*)d_in[10];
    const float* b2c = (const float*)d_in[11];
    const float* w3c = (const float*)d_in[12];
    const float* b3c = (const float*)d_in[13];
    const float* w1k = (const float*)d_in[14];
    const float* b1k = (const float*)d_in[15];
    const float* w2k = (const float*)d_in[16];
    const float* b2k = (const float*)d_in[17];
    const float* w3k = (const float*)d_in[18];
    const float* b3k = (const float*)d_in[19];
    const float* prof_re = (const float*)d_in[20];
    const float* prof_im = (const float*)d_in[21];
    const float* dis     = (const float*)d_in[22];
    const float* mask    = (const float*)d_in[23];
    const float* is_ctr  = (const float*)d_in[24];
    const int*   coo     = (const int*)d_in[25];
    const int*   steps   = (const int*)d_in[26];
    float* out = (float*)d_out;

    prep_kernel<<<(NSQ + 255) / 256, 256>>>(h_paras, E0);
    mlp_kernel<<<NSQ / 128, 256>>>(0, w1n, b1n, w2n, b2n, w3n, b3n, dis, coo);
    mlp_kernel<<<NNZ / 128, 256>>>(1, w1c, b1c, w2c, b2c, w3c, b3c, dis, coo);
    mlp_kernel<<<NNZ / 128, 256>>>(2, w1k, b1k, w2k, b2k, w3k, b3k, dis, coo);
    coeff_kernel<<<(NNZ + 255) / 256, 256>>>(mask, is_ctr);

    // Euler: try 16-CTA cluster (nonportable), deterministic fallback to 8-CTA.
    cudaError_t err = cudaFuncSetAttribute(
        euler16_kernel, cudaFuncAttributeNonPortableClusterSizeAllowed, 1);
    if (err == cudaSuccess) {
        cudaLaunchConfig_t cfg = {};
        cfg.gridDim  = dim3(16, 1, 1);
        cfg.blockDim = dim3(144, 1, 1);
        cfg.dynamicSmemBytes = 0;
        cfg.stream = 0;
        cudaLaunchAttribute attrs[1];
        attrs[0].id = cudaLaunchAttributeClusterDimension;
        attrs[0].val.clusterDim.x = 16;
        attrs[0].val.clusterDim.y = 1;
        attrs[0].val.clusterDim.z = 1;
        cfg.attrs = attrs;
        cfg.numAttrs = 1;
        err = cudaLaunchKernelEx(&cfg, euler16_kernel, steps);
    }
    if (err != cudaSuccess) {
        cudaGetLastError();   // clear sticky state from the failed attempt
        euler8_kernel<<<8, 576>>>(steps);
    }

    expand_kernel<<<(OUTPLANE + 255) / 256, 256>>>(prof_re, prof_im, out);
}

// round 10
// speedup vs baseline: 1.5199x; 1.0902x over previous
#include <cuda_runtime.h>
#include <cooperative_groups.h>
#include <math.h>
#include <stdint.h>

namespace cg = cooperative_groups;

#define NN      96
#define NSQ     9216
#define NOFF    13
#define NNZ     119808
#define SIDE    816
#define BORD    24
#define KCONST  6.683942601602444f   /* 2*pi/0.94 */
#define OUTSIDE 768
#define OUTPLANE (OUTSIDE*OUTSIDE)

typedef unsigned long long u64;

// ---------------- scratch (static device globals; no allocation) ------------
__device__ float  g_hs[NSQ];
__device__ float  g_Eys[NSQ];
__device__ float  g_neff[NSQ];
__device__ float2 g_U0[NSQ];
__device__ float2 g_Uz[NSQ];
__device__ float  g_craw[NNZ];
__device__ float  g_kraw[NNZ];
__device__ float  g_m[NNZ];
__device__ float  g_ci[NNZ];

// ---------------- packed fp32x2 + approx tanh helpers ------------------------
__device__ __forceinline__ u64 fma2(u64 a, u64 b, u64 c)
{
    u64 d;
    asm("fma.rn.f32x2 %0, %1, %2, %3;" : "=l"(d) : "l"(a), "l"(b), "l"(c));
    return d;
}
__device__ __forceinline__ u64 dup2(float x)
{
    u64 d;
    unsigned r = __float_as_uint(x);
    asm("mov.b64 %0, {%1, %1};" : "=l"(d) : "r"(r));
    return d;
}
__device__ __forceinline__ float lo32(u64 v) { return __uint_as_float((unsigned)v); }
__device__ __forceinline__ float hi32(u64 v) { return __uint_as_float((unsigned)(v >> 32)); }
__device__ __forceinline__ float tanha(float x)
{
    float y;
    asm("tanh.approx.f32 %0, %1;" : "=f"(y) : "f"(x));
    return y;
}

// ---------------- kernel 1: hs / Eys / U0 (8x8 pooling) ---------------------
__global__ __launch_bounds__(256) void prep_kernel(const float* __restrict__ h_paras,
                                                   const float* __restrict__ E0)
{
    int p = blockIdx.x * 256 + threadIdx.x;
    if (p >= NSQ) return;
    float h  = h_paras[p];
    float s  = 1.f / (1.f + expf(-h));
    float hs = s * 0.6f + 0.2f;            // H_MIN + sig*(H_MAX-H_MIN)
    g_hs[p]  = hs;
    g_Eys[p] = 1.0f + 0.1f * tanhf(hs);
    float coupl = 0.5f + 0.5f * (1.f / (1.f + expf(-hs)));

    int i = p / NN, j = p % NN;
    const float* base = E0 + (size_t)(BORD + 8 * i) * SIDE + (BORD + 8 * j);
    float sum = 0.f;
    #pragma unroll
    for (int pi = 0; pi < 8; pi++) {
        float4 a = *(const float4*)(base + pi * SIDE);
        float4 b = *(const float4*)(base + pi * SIDE + 4);
        sum += (a.x + a.y) + (a.z + a.w) + (b.x + b.y) + (b.z + b.w);
    }
    g_U0[p] = make_float2(sum * (1.f / 64.f) * coupl, 0.f);
}

// ---------------- kernel 2: fused 3-layer MLP (mode 0=neff, 1=c, 2=k) -------
// 128 rows/block; 256 threads; 8x8 tiles via f32x2 packed FMA (pairs over rows).
// Edge MLPs (mode!=0) use hw tanh.approx; neff (mode 0) keeps accurate tanhf.
__global__ __launch_bounds__(256) void mlp_kernel(int mode,
    const float* __restrict__ w1, const float* __restrict__ b1,
    const float* __restrict__ w2, const float* __restrict__ b2,
    const float* __restrict__ w3, const float* __restrict__ b3,
    const float* __restrict__ dis, const int* __restrict__ coo)
{
    __shared__ float h1s[32 * 128];
    __shared__ float w2s[32 * 128];
    __shared__ float xs[4 * 128];
    __shared__ float red[16 * 128];

    int tid  = threadIdx.x;
    int base = blockIdx.x * 128;

    if (tid < 128) {
        int e = base + tid;
        if (mode == 0) {
            xs[tid] = g_hs[e];
        } else {
            int r = coo[e];
            int c = coo[NNZ + e];
            xs[tid]       = g_hs[r];
            xs[128 + tid] = g_hs[c];
            xs[256 + tid] = dis[2 * e];
            xs[384 + tid] = dis[2 * e + 1];
        }
    }
    __syncthreads();

    int tx = tid & 15, ty = tid >> 4;
    u64 acc2[4][8];
    #pragma unroll
    for (int p = 0; p < 4; p++)
        #pragma unroll
        for (int j = 0; j < 8; j++) acc2[p][j] = 0ull;

    for (int kb = 0; kb < 4; kb++) {
        // fill h1 chunk (layer-1 + tanh) and w2 chunk
        #pragma unroll
        for (int it = 0; it < 16; it++) {
            int idx = tid + it * 256;           // 0..4095
            int kk  = idx >> 7;                 // 0..31
            int e   = idx & 127;                // 0..127
            int k   = kb * 32 + kk;
            float a = b1[k] + xs[e] * w1[k];
            if (mode != 0) {
                a += xs[128 + e] * w1[128 + k] + xs[256 + e] * w1[256 + k]
                   + xs[384 + e] * w1[384 + k];
                h1s[kk * 128 + e] = tanha(a);
            } else {
                h1s[kk * 128 + e] = tanhf(a);
            }
            w2s[idx] = w2[kb * 4096 + idx];
        }
        __syncthreads();

        #pragma unroll 4
        for (int k = 0; k < 32; k++) {
            ulonglong2 A0 = *(const ulonglong2*)&h1s[k * 128 + tx * 8];
            ulonglong2 A1 = *(const ulonglong2*)&h1s[k * 128 + tx * 8 + 4];
            float4 c0 = *(const float4*)&w2s[k * 128 + ty * 8];
            float4 c1 = *(const float4*)&w2s[k * 128 + ty * 8 + 4];
            u64 ap[4] = {A0.x, A0.y, A1.x, A1.y};
            u64 bp[8] = {dup2(c0.x), dup2(c0.y), dup2(c0.z), dup2(c0.w),
                         dup2(c1.x), dup2(c1.y), dup2(c1.z), dup2(c1.w)};
            #pragma unroll
            for (int p = 0; p < 4; p++)
                #pragma unroll
                for (int j = 0; j < 8; j++)
                    acc2[p][j] = fma2(ap[p], bp[j], acc2[p][j]);
        }
        __syncthreads();
    }

    // layer 3: tanh + dot with w3, partial reduce over ty groups
    #pragma unroll
    for (int i = 0; i < 8; i++) {
        float part = 0.f;
        #pragma unroll
        for (int j = 0; j < 8; j++) {
            u64 v = acc2[i >> 1][j];
            float pre = ((i & 1) ? hi32(v) : lo32(v)) + b2[ty * 8 + j];
            float h2 = (mode != 0) ? tanha(pre) : tanhf(pre);
            part = fmaf(h2, w3[ty * 8 + j], part);
        }
        red[ty * 128 + tx * 8 + i] = part;
    }
    __syncthreads();
    if (tid < 128) {
        float s = b3[0];
        #pragma unroll
        for (int t = 0; t < 16; t++) s += red[t * 128 + tid];
        int e = base + tid;
        if (mode == 0)      g_neff[e] = s;
        else if (mode == 1) g_craw[e] = s;
        else                g_kraw[e] = s;
    }
}

// ---------------- kernel 3: edge coefficients -------------------------------
__global__ __launch_bounds__(256) void coeff_kernel(const float* __restrict__ mask,
                                                    const float* __restrict__ is_center)
{
    int e = blockIdx.x * 256 + threadIdx.x;
    if (e >= NNZ) return;
    float msk = mask[e];
    float ic  = is_center[e];
    float c   = msk * 0.05f * tanhf(g_craw[e]) + ic;
    float kv  = msk * 0.10f * tanhf(g_kraw[e]);
    int   r   = e / NOFF;                 // row (center point) by construction
    g_m[e]  = KCONST * g_neff[r] * c + kv;
    g_ci[e] = 2.0f * ic - c;
}

// ---------------- kernel 4: Euler loop --------------------------------------
// Out-of-grid taps have exactly-zero coefficients, so zero halos are correct.

#define CL_ARRIVE() asm volatile("barrier.cluster.arrive.aligned;" ::: "memory")
#define CL_WAIT()   asm volatile("barrier.cluster.wait.aligned;"   ::: "memory")

// 2x2-point register-tiled 13-tap stencil. 14 conflict-free LDS.128.
// Tap order o=0..12 identical to the edge/coefficient order.
__device__ __forceinline__ void sten2x2(const float cf[4][13],
                                        const float2* __restrict__ buf,
                                        int s, int c0, float2* __restrict__ out)
{
    float2 wm2[2], wm1[6], w0[6], wp1[6], wp2[6], wp3[2];
    {
        const float2* b;
        b = buf + (s - 2) * 100;
        *(float4*)&wm2[0] = *(const float4*)&b[c0];
        b = buf + (s - 1) * 100;
        *(float4*)&wm1[0] = *(const float4*)&b[c0 - 2];
        *(float4*)&wm1[2] = *(const float4*)&b[c0];
        *(float4*)&wm1[4] = *(const float4*)&b[c0 + 2];
        b = buf + s * 100;
        *(float4*)&w0[0]  = *(const float4*)&b[c0 - 2];
        *(float4*)&w0[2]  = *(const float4*)&b[c0];
        *(float4*)&w0[4]  = *(const float4*)&b[c0 + 2];
        b = buf + (s + 1) * 100;
        *(float4*)&wp1[0] = *(const float4*)&b[c0 - 2];
        *(float4*)&wp1[2] = *(const float4*)&b[c0];
        *(float4*)&wp1[4] = *(const float4*)&b[c0 + 2];
        b = buf + (s + 2) * 100;
        *(float4*)&wp2[0] = *(const float4*)&b[c0 - 2];
        *(float4*)&wp2[2] = *(const float4*)&b[c0];
        *(float4*)&wp2[4] = *(const float4*)&b[c0 + 2];
        b = buf + (s + 3) * 100;
        *(float4*)&wp3[0] = *(const float4*)&b[c0];
    }

#define ACC(o, v) { acc.x = fmaf(f[o], (v).x, acc.x); acc.y = fmaf(f[o], (v).y, acc.y); }

    #pragma unroll
    for (int k = 0; k < 2; k++) {
        // point (row r, col j+k)
        {
            const float* f = cf[k];
            float2 acc = make_float2(0.f, 0.f);
            ACC(0,  w0 [k + 2]);
            ACC(1,  wp1[k + 2]);
            ACC(2,  wm1[k + 2]);
            ACC(3,  w0 [k + 3]);
            ACC(4,  w0 [k + 1]);
            ACC(5,  wp1[k + 3]);
            ACC(6,  wp1[k + 1]);
            ACC(7,  wm1[k + 3]);
            ACC(8,  wm1[k + 1]);
            ACC(9,  wp2[k + 2]);
            ACC(10, wm2[k]);
            ACC(11, w0 [k + 4]);
            ACC(12, w0 [k]);
            out[k] = acc;
        }
        // point (row r+1, col j+k)
        {
            const float* f = cf[2 + k];
            float2 acc = make_float2(0.f, 0.f);
            ACC(0,  wp1[k + 2]);
            ACC(1,  wp2[k + 2]);
            ACC(2,  w0 [k + 2]);
            ACC(3,  wp1[k + 3]);
            ACC(4,  wp1[k + 1]);
            ACC(5,  wp2[k + 3]);
            ACC(6,  wp2[k + 1]);
            ACC(7,  w0 [k + 3]);
            ACC(8,  w0 [k + 1]);
            ACC(9,  wp3[k]);
            ACC(10, wm1[k + 2]);
            ACC(11, wp1[k + 4]);
            ACC(12, wp1[k]);
            out[2 + k] = acc;
        }
    }
#undef ACC
}

// --- 16-CTA cluster, ONE exchange/step via redundant t-halo compute ---------
// u_s: 14 rows (local rows -4..9), t_s: 10 rows (local rows -2..7).
// 240 threads: ti=0..4 row-pairs {-2,-1}{0,1}{2,3}{4,5}{6,7}, tj=0..47 col pairs.
// t computed on all 10 rows (halo rows use neighbor-point coefficients from
// g_m, zero if out-of-grid). Only u is exchanged: 4 rows to each neighbor.
__global__ void __launch_bounds__(240, 1)
euler16_kernel(const int* __restrict__ steps_ptr)
{
    __shared__ float2 u_s[14 * 100];
    __shared__ float2 t_s[10 * 100];

    int tid   = threadIdx.x;
    int rank  = blockIdx.x;
    int steps = *steps_ptr;
    float dz  = 1.5f / (float)steps;

    // init u (incl. 4-row halos) from global U0; zero t (borders stay 0)
    for (int idx = tid; idx < 1400; idx += 240) {
        int su = idx / 100, c = idx % 100;
        int gi = rank * 6 + su - 4;
        int gj = c - 2;
        float2 v = make_float2(0.f, 0.f);
        if (gi >= 0 && gi < NN && gj >= 0 && gj < NN) v = g_U0[gi * NN + gj];
        u_s[idx] = v;
    }
    for (int idx = tid; idx < 1000; idx += 240)
        t_s[idx] = make_float2(0.f, 0.f);

    int tj = tid % 48;            // col pair
    int ti = tid / 48;            // row pair 0..4
    int lr = 2 * ti - 2;          // top local row: -2,0,2,4,6
    int j0 = 2 * tj;
    int c0 = j0 + 2;
    int su = lr + 4;              // u_s row of top point
    int st = lr + 2;              // t_s row of top point
    bool own = (ti >= 1 && ti <= 3);

    // t-pass coefficients (m) for this 2x2 tile; zero when out of grid
    float m[4][13], ci[4][13];
    #pragma unroll
    for (int pt = 0; pt < 4; pt++) {
        int grow = rank * 6 + lr + (pt >> 1);
        int col  = j0 + (pt & 1);
        bool val = (grow >= 0) && (grow < NN);
        int p    = val ? (grow * NN + col) : 0;
        #pragma unroll
        for (int o = 0; o < NOFF; o++)
            m[pt][o] = val ? g_m[p * NOFF + o] : 0.f;
    }
    // u-pass coefficients (ci) + own u registers: only ti 1..3
    float2 uv[4];
    if (own) {
        #pragma unroll
        for (int pt = 0; pt < 4; pt++) {
            int p = (rank * 6 + lr + (pt >> 1)) * NN + (j0 + (pt & 1));
            #pragma unroll
            for (int o = 0; o < NOFF; o++)
                ci[pt][o] = g_ci[p * NOFF + o];
        }
        int pr0 = (rank * 6 + lr) * NN + j0;
        uv[0] = g_U0[pr0];
        uv[1] = g_U0[pr0 + 1];
        uv[2] = g_U0[pr0 + NN];
        uv[3] = g_U0[pr0 + NN + 1];
    }

    cg::cluster_group cl = cg::this_cluster();
    float2* up_u = (rank > 0)  ? cl.map_shared_rank(u_s, rank - 1) : (float2*)0;
    float2* dn_u = (rank < 15) ? cl.map_shared_rank(u_s, rank + 1) : (float2*)0;

    // push map: rows 0..3 -> up-neighbor su 10..13 ; rows 2..5 -> down su 0..3
    bool push_up = (rank > 0)  && (ti == 1 || ti == 2);
    bool push_dn = (rank < 15) && (ti == 2 || ti == 3);
    int  up_r0 = (ti == 1 ? 10 : 12) * 100 + c0;   // and +100 for second row
    int  dn_r0 = (ti == 2 ? 0 : 2) * 100 + c0;

    __syncthreads();
    CL_ARRIVE(); CL_WAIT();        // all CTAs' u_s init visible before pushes

    float2 tv[4], vv[4];
    for (int st_i = 0; st_i < steps; st_i++) {
        // ---- t = A1 * u on all 10 rows (ti==2 already did it pre-wait) ----
        if (!(ti == 2 && st_i > 0)) {
            sten2x2(m, u_s, su, c0, tv);
            *(float4*)&t_s[st * 100 + c0]       = *(float4*)&tv[0];
            *(float4*)&t_s[(st + 1) * 100 + c0] = *(float4*)&tv[2];
        }
        __syncthreads();

        // ---- u += i*dz * (A2 * t) on own rows ----
        if (own) {
            sten2x2(ci, t_s, st, c0, vv);
            #pragma unroll
            for (int q = 0; q < 4; q++) {
                uv[q].x = fmaf(-dz, vv[q].y, uv[q].x);
                uv[q].y = fmaf( dz, vv[q].x, uv[q].y);
            }
        }
        if (st_i + 1 == steps) break;

        if (own) {
            *(float4*)&u_s[su * 100 + c0]       = *(float4*)&uv[0];
            *(float4*)&u_s[(su + 1) * 100 + c0] = *(float4*)&uv[2];
            if (push_up) {
                *(float4*)&up_u[up_r0]       = *(float4*)&uv[0];
                *(float4*)&up_u[up_r0 + 100] = *(float4*)&uv[2];
            }
            if (push_dn) {
                *(float4*)&dn_u[dn_r0]       = *(float4*)&uv[0];
                *(float4*)&dn_u[dn_r0 + 100] = *(float4*)&uv[2];
            }
        }
        CL_ARRIVE();
        __syncthreads();           // own-CTA u stores visible

        // overlap: ti==2 tile (t rows 2,3) taps only own u rows 0..5
        if (ti == 2) {
            sten2x2(m, u_s, su, c0, tv);
            *(float4*)&t_s[st * 100 + c0]       = *(float4*)&tv[0];
            *(float4*)&t_s[(st + 1) * 100 + c0] = *(float4*)&tv[2];
        }
        CL_WAIT();                 // neighbor u halos visible
    }

    if (own) {
        int pr0 = (rank * 6 + lr) * NN + j0;
        g_Uz[pr0]          = uv[0];
        g_Uz[pr0 + 1]      = uv[1];
        g_Uz[pr0 + NN]     = uv[2];
        g_Uz[pr0 + NN + 1] = uv[3];
    }
}

// --- 8-CTA fallback (proven): 12 rows/CTA, 2 points/thread, cluster.sync ----
__device__ __forceinline__ float2 sten13(const float* __restrict__ cf,
                                         const float2* __restrict__ buf,
                                         int s, int c)
{
    const int DI[13] = {0, 1, -1, 0, 0, 1, 1, -1, -1, 2, -2, 0, 0};
    const int DJ[13] = {0, 0, 0, 1, -1, 1, -1, 1, -1, 0, 0, 2, -2};
    float2 acc = make_float2(0.f, 0.f);
    #pragma unroll
    for (int o = 0; o < 13; o++) {
        float2 v = buf[(s + DI[o]) * 100 + (c + DJ[o])];
        acc.x = fmaf(cf[o], v.x, acc.x);
        acc.y = fmaf(cf[o], v.y, acc.y);
    }
    return acc;
}

__global__ void __cluster_dims__(8, 1, 1) __launch_bounds__(576, 1)
euler8_kernel(const int* __restrict__ steps_ptr)
{
    __shared__ float2 u_s[16 * 100];
    __shared__ float2 t_s[16 * 100];

    cg::cluster_group cl = cg::this_cluster();
    int tid   = threadIdx.x;
    int rank  = blockIdx.x;
    int steps = *steps_ptr;
    float dz  = 1.5f / (float)steps;

    for (int idx = tid; idx < 1600; idx += 576) {
        int s = idx / 100, c = idx % 100;
        int gi = rank * 12 + s - 2;
        int gj = c - 2;
        float2 v = make_float2(0.f, 0.f);
        if (gi >= 0 && gi < NN && gj >= 0 && gj < NN) v = g_U0[gi * NN + gj];
        u_s[idx] = v;
        t_s[idx] = make_float2(0.f, 0.f);
    }

    int li0 = tid / NN, lj = tid % NN;
    int li1 = li0 + 6;
    int s0  = li0 + 2, s1 = li1 + 2, c = lj + 2;
    int p0  = (rank * 12 + li0) * NN + lj;
    int p1  = p0 + 6 * NN;

    float m0[13], ci0[13], m1[13], ci1[13];
    #pragma unroll
    for (int o = 0; o < 13; o++) {
        m0[o]  = g_m [p0 * NOFF + o];
        ci0[o] = g_ci[p0 * NOFF + o];
        m1[o]  = g_m [p1 * NOFF + o];
        ci1[o] = g_ci[p1 * NOFF + o];
    }

    float2* up_u = (rank > 0) ? cl.map_shared_rank(u_s, rank - 1) : (float2*)0;
    float2* up_t = (rank > 0) ? cl.map_shared_rank(t_s, rank - 1) : (float2*)0;
    float2* dn_u = (rank < 7) ? cl.map_shared_rank(u_s, rank + 1) : (float2*)0;
    float2* dn_t = (rank < 7) ? cl.map_shared_rank(t_s, rank + 1) : (float2*)0;

    bool push_up = (rank > 0) && (li0 < 2);
    bool push_dn = (rank < 7) && (li0 >= 4);
    int  up_off  = (li0 + 14) * 100 + c;
    int  dn_off  = (li1 - 10) * 100 + c;

    cl.sync();

    for (int st = 0; st < steps; st++) {
        float2 t0 = sten13(m0, u_s, s0, c);
        float2 t1 = sten13(m1, u_s, s1, c);
        t_s[s0 * 100 + c] = t0;
        t_s[s1 * 100 + c] = t1;
        if (push_up) up_t[up_off] = t0;
        if (push_dn) dn_t[dn_off] = t1;
        cl.sync();

        float2 v0 = sten13(ci0, t_s, s0, c);
        float2 v1 = sten13(ci1, t_s, s1, c);
        float2 u0 = u_s[s0 * 100 + c];
        float2 u1 = u_s[s1 * 100 + c];
        u0.x = fmaf(-dz, v0.y, u0.x); u0.y = fmaf(dz, v0.x, u0.y);
        u1.x = fmaf(-dz, v1.y, u1.x); u1.y = fmaf(dz, v1.x, u1.y);
        u_s[s0 * 100 + c] = u0;
        u_s[s1 * 100 + c] = u1;
        if (push_up) up_u[up_off] = u0;
        if (push_dn) dn_u[dn_off] = u1;
        cl.sync();
    }

    g_Uz[p0] = u_s[s0 * 100 + c];
    g_Uz[p1] = u_s[s1 * 100 + c];
}

// ---------------- kernel 5: outer-product expansion -------------------------
__global__ __launch_bounds__(256) void expand_kernel(const float* __restrict__ prof_re,
                                                     const float* __restrict__ prof_im,
                                                     float* __restrict__ out)
{
    int gid = blockIdx.x * 256 + threadIdx.x;
    if (gid >= OUTPLANE) return;
    int y = gid / OUTSIDE, x = gid - y * OUTSIDE;
    int i = y >> 3, p = y & 7;
    int j = x >> 3, q = x & 7;
    int cell = i * NN + j;
    float2 u = g_Uz[cell];
    float  e = g_Eys[cell];
    float gr = u.x * e, gi = u.y * e;
    float pr = prof_re[p * 8 + q];
    float pi = prof_im[p * 8 + q];
    out[gid]            = gr * pr - gi * pi;
    out[OUTPLANE + gid] = gr * pi + gi * pr;
}

// ---------------- launch ----------------------------------------------------
extern "C" void kernel_launch(void* const* d_in, const int* in_sizes, int n_in,
                              void* d_out, int out_size)
{
    const float* h_paras = (const float*)d_in[0];
    const float* E0      = (const float*)d_in[1];
    const float* w1n = (const float*)d_in[2];
    const float* b1n = (const float*)d_in[3];
    const float* w2n = (const float*)d_in[4];
    const float* b2n = (const float*)d_in[5];
    const float* w3n = (const float*)d_in[6];
    const float* b3n = (const float*)d_in[7];
    const float* w1c = (const float*)d_in[8];
    const float* b1c = (const float*)d_in[9];
    const float* w2c = (const float*)d_in[10];
    const float* b2c = (const float*)d_in[11];
    const float* w3c = (const float*)d_in[12];
    const float* b3c = (const float*)d_in[13];
    const float* w1k = (const float*)d_in[14];
    const float* b1k = (const float*)d_in[15];
    const float* w2k = (const float*)d_in[16];
    const float* b2k = (const float*)d_in[17];
    const float* w3k = (const float*)d_in[18];
    const float* b3k = (const float*)d_in[19];
    const float* prof_re = (const float*)d_in[20];
    const float* prof_im = (const float*)d_in[21];
    const float* dis     = (const float*)d_in[22];
    const float* mask    = (const float*)d_in[23];
    const float* is_ctr  = (const float*)d_in[24];
    const int*   coo     = (const int*)d_in[25];
    const int*   steps   = (const int*)d_in[26];
    float* out = (float*)d_out;

    prep_kernel<<<(NSQ + 255) / 256, 256>>>(h_paras, E0);
    mlp_kernel<<<NSQ / 128, 256>>>(0, w1n, b1n, w2n, b2n, w3n, b3n, dis, coo);
    mlp_kernel<<<NNZ / 128, 256>>>(1, w1c, b1c, w2c, b2c, w3c, b3c, dis, coo);
    mlp_kernel<<<NNZ / 128, 256>>>(2, w1k, b1k, w2k, b2k, w3k, b3k, dis, coo);
    coeff_kernel<<<(NNZ + 255) / 256, 256>>>(mask, is_ctr);

    // Euler: try 16-CTA cluster (nonportable), deterministic fallback to 8-CTA.
    cudaError_t err = cudaFuncSetAttribute(
        euler16_kernel, cudaFuncAttributeNonPortableClusterSizeAllowed, 1);
    if (err == cudaSuccess) {
        cudaLaunchConfig_t cfg = {};
        cfg.gridDim  = dim3(16, 1, 1);
        cfg.blockDim = dim3(240, 1, 1);
        cfg.dynamicSmemBytes = 0;
        cfg.stream = 0;
        cudaLaunchAttribute attrs[1];
        attrs[0].id = cudaLaunchAttributeClusterDimension;
        attrs[0].val.clusterDim.x = 16;
        attrs[0].val.clusterDim.y = 1;
        attrs[0].val.clusterDim.z = 1;
        cfg.attrs = attrs;
        cfg.numAttrs = 1;
        err = cudaLaunchKernelEx(&cfg, euler16_kernel, steps);
    }
    if (err != cudaSuccess) {
        cudaGetLastError();   // clear sticky state from the failed attempt
        euler8_kernel<<<8, 576>>>(steps);
    }

    expand_kernel<<<(OUTPLANE + 255) / 256, 256>>>(prof_re, prof_im, out);
}

// round 12
// speedup vs baseline: 1.5217x; 1.0012x over previous
#include <cuda_runtime.h>
#include <cooperative_groups.h>
#include <math.h>
#include <stdint.h>

namespace cg = cooperative_groups;

#define NN      96
#define NSQ     9216
#define NOFF    13
#define NNZ     119808
#define SIDE    816
#define BORD    24
#define KCONST  6.683942601602444f   /* 2*pi/0.94 */
#define OUTSIDE 768
#define OUTPLANE (OUTSIDE*OUTSIDE)

typedef unsigned long long u64;

// ---------------- scratch (static device globals; no allocation) ------------
__device__ float  g_hs[NSQ];
__device__ float  g_Eys[NSQ];
__device__ float  g_neff[NSQ];
__device__ float2 g_U0[NSQ];
__device__ float2 g_Uz[NSQ];
__device__ float  g_craw[NNZ];
__device__ float  g_kraw[NNZ];
__device__ float  g_m[NNZ];
__device__ float  g_ci[NNZ];

// ---------------- packed fp32x2 + approx tanh helpers ------------------------
__device__ __forceinline__ u64 fma2(u64 a, u64 b, u64 c)
{
    u64 d;
    asm("fma.rn.f32x2 %0, %1, %2, %3;" : "=l"(d) : "l"(a), "l"(b), "l"(c));
    return d;
}
__device__ __forceinline__ u64 dup2(float x)
{
    u64 d;
    unsigned r = __float_as_uint(x);
    asm("mov.b64 %0, {%1, %1};" : "=l"(d) : "r"(r));
    return d;
}
__device__ __forceinline__ float lo32(u64 v) { return __uint_as_float((unsigned)v); }
__device__ __forceinline__ float hi32(u64 v) { return __uint_as_float((unsigned)(v >> 32)); }
__device__ __forceinline__ float tanha(float x)
{
    float y;
    asm("tanh.approx.f32 %0, %1;" : "=f"(y) : "f"(x));
    return y;
}

// ---------------- kernel 1: hs / Eys / U0 (8x8 pooling) ---------------------
__global__ __launch_bounds__(256) void prep_kernel(const float* __restrict__ h_paras,
                                                   const float* __restrict__ E0)
{
    int p = blockIdx.x * 256 + threadIdx.x;
    if (p >= NSQ) return;
    float h  = h_paras[p];
    float s  = 1.f / (1.f + expf(-h));
    float hs = s * 0.6f + 0.2f;            // H_MIN + sig*(H_MAX-H_MIN)
    g_hs[p]  = hs;
    g_Eys[p] = 1.0f + 0.1f * tanhf(hs);
    float coupl = 0.5f + 0.5f * (1.f / (1.f + expf(-hs)));

    int i = p / NN, j = p % NN;
    const float* base = E0 + (size_t)(BORD + 8 * i) * SIDE + (BORD + 8 * j);
    float sum = 0.f;
    #pragma unroll
    for (int pi = 0; pi < 8; pi++) {
        float4 a = *(const float4*)(base + pi * SIDE);
        float4 b = *(const float4*)(base + pi * SIDE + 4);
        sum += (a.x + a.y) + (a.z + a.w) + (b.x + b.y) + (b.z + b.w);
    }
    g_U0[p] = make_float2(sum * (1.f / 64.f) * coupl, 0.f);
}

// ---------------- kernel 2: fused 3-layer MLP (mode 0=neff, 1=c, 2=k) -------
// 128 rows/block; 256 threads; 8x8 tiles via f32x2 packed FMA (pairs over rows).
// Edge MLPs (mode!=0) use hw tanh.approx; neff (mode 0) keeps accurate tanhf.
// smem 34.5KB (red aliases h1s) + launch_bounds(256,2) -> 2 CTAs/SM so one
// block's fill/epilogue overlaps the other's FMA-bound inner loop.
__global__ __launch_bounds__(256, 2) void mlp_kernel(int mode,
    const float* __restrict__ w1, const float* __restrict__ b1,
    const float* __restrict__ w2, const float* __restrict__ b2,
    const float* __restrict__ w3, const float* __restrict__ b3,
    const float* __restrict__ dis, const int* __restrict__ coo)
{
    __shared__ float h1s[32 * 128];
    __shared__ float w2s[32 * 128];
    __shared__ float xs[4 * 128];
    float* red = h1s;          // reuse: h1s dead after last inner-loop barrier

    int tid  = threadIdx.x;
    int base = blockIdx.x * 128;

    if (tid < 128) {
        int e = base + tid;
        if (mode == 0) {
            xs[tid] = g_hs[e];
        } else {
            int r = coo[e];
            int c = coo[NNZ + e];
            xs[tid]       = g_hs[r];
            xs[128 + tid] = g_hs[c];
            xs[256 + tid] = dis[2 * e];
            xs[384 + tid] = dis[2 * e + 1];
        }
    }
    __syncthreads();

    int tx = tid & 15, ty = tid >> 4;
    u64 acc2[4][8];
    #pragma unroll
    for (int p = 0; p < 4; p++)
        #pragma unroll
        for (int j = 0; j < 8; j++) acc2[p][j] = 0ull;

    for (int kb = 0; kb < 4; kb++) {
        // fill h1 chunk (layer-1 + tanh) and w2 chunk
        #pragma unroll
        for (int it = 0; it < 16; it++) {
            int idx = tid + it * 256;           // 0..4095
            int kk  = idx >> 7;                 // 0..31
            int e   = idx & 127;                // 0..127
            int k   = kb * 32 + kk;
            float a = b1[k] + xs[e] * w1[k];
            if (mode != 0) {
                a += xs[128 + e] * w1[128 + k] + xs[256 + e] * w1[256 + k]
                   + xs[384 + e] * w1[384 + k];
                h1s[kk * 128 + e] = tanha(a);
            } else {
                h1s[kk * 128 + e] = tanhf(a);
            }
            w2s[idx] = w2[kb * 4096 + idx];
        }
        __syncthreads();

        #pragma unroll 4
        for (int k = 0; k < 32; k++) {
            ulonglong2 A0 = *(const ulonglong2*)&h1s[k * 128 + tx * 8];
            ulonglong2 A1 = *(const ulonglong2*)&h1s[k * 128 + tx * 8 + 4];
            float4 c0 = *(const float4*)&w2s[k * 128 + ty * 8];
            float4 c1 = *(const float4*)&w2s[k * 128 + ty * 8 + 4];
            u64 ap[4] = {A0.x, A0.y, A1.x, A1.y};
            u64 bp[8] = {dup2(c0.x), dup2(c0.y), dup2(c0.z), dup2(c0.w),
                         dup2(c1.x), dup2(c1.y), dup2(c1.z), dup2(c1.w)};
            #pragma unroll
            for (int p = 0; p < 4; p++)
                #pragma unroll
                for (int j = 0; j < 8; j++)
                    acc2[p][j] = fma2(ap[p], bp[j], acc2[p][j]);
        }
        __syncthreads();
    }

    // layer 3: tanh + dot with w3, partial reduce over ty groups
    #pragma unroll
    for (int i = 0; i < 8; i++) {
        float part = 0.f;
        #pragma unroll
        for (int j = 0; j < 8; j++) {
            u64 v = acc2[i >> 1][j];
            float pre = ((i & 1) ? hi32(v) : lo32(v)) + b2[ty * 8 + j];
            float h2 = (mode != 0) ? tanha(pre) : tanhf(pre);
            part = fmaf(h2, w3[ty * 8 + j], part);
        }
        red[ty * 128 + tx * 8 + i] = part;
    }
    __syncthreads();
    if (tid < 128) {
        float s = b3[0];
        #pragma unroll
        for (int t = 0; t < 16; t++) s += red[t * 128 + tid];
        int e = base + tid;
        if (mode == 0)      g_neff[e] = s;
        else if (mode == 1) g_craw[e] = s;
        else                g_kraw[e] = s;
    }
}

// ---------------- kernel 3: edge coefficients -------------------------------
__global__ __launch_bounds__(256) void coeff_kernel(const float* __restrict__ mask,
                                                    const float* __restrict__ is_center)
{
    int e = blockIdx.x * 256 + threadIdx.x;
    if (e >= NNZ) return;
    float msk = mask[e];
    float ic  = is_center[e];
    float c   = msk * 0.05f * tanhf(g_craw[e]) + ic;
    float kv  = msk * 0.10f * tanhf(g_kraw[e]);
    int   r   = e / NOFF;                 // row (center point) by construction
    g_m[e]  = KCONST * g_neff[r] * c + kv;
    g_ci[e] = 2.0f * ic - c;
}

// ---------------- kernel 4: Euler loop --------------------------------------
// Out-of-grid taps have exactly-zero coefficients, so zero halos are correct.

#define CL_ARRIVE() asm volatile("barrier.cluster.arrive.aligned;" ::: "memory")
#define CL_WAIT()   asm volatile("barrier.cluster.wait.aligned;"   ::: "memory")

// 2x2-point register-tiled 13-tap stencil. 14 conflict-free LDS.128.
// Tap order o=0..12 identical to the edge/coefficient order.
__device__ __forceinline__ void sten2x2(const float cf[4][13],
                                        const float2* __restrict__ buf,
                                        int s, int c0, float2* __restrict__ out)
{
    float2 wm2[2], wm1[6], w0[6], wp1[6], wp2[6], wp3[2];
    {
        const float2* b;
        b = buf + (s - 2) * 100;
        *(float4*)&wm2[0] = *(const float4*)&b[c0];
        b = buf + (s - 1) * 100;
        *(float4*)&wm1[0] = *(const float4*)&b[c0 - 2];
        *(float4*)&wm1[2] = *(const float4*)&b[c0];
        *(float4*)&wm1[4] = *(const float4*)&b[c0 + 2];
        b = buf + s * 100;
        *(float4*)&w0[0]  = *(const float4*)&b[c0 - 2];
        *(float4*)&w0[2]  = *(const float4*)&b[c0];
        *(float4*)&w0[4]  = *(const float4*)&b[c0 + 2];
        b = buf + (s + 1) * 100;
        *(float4*)&wp1[0] = *(const float4*)&b[c0 - 2];
        *(float4*)&wp1[2] = *(const float4*)&b[c0];
        *(float4*)&wp1[4] = *(const float4*)&b[c0 + 2];
        b = buf + (s + 2) * 100;
        *(float4*)&wp2[0] = *(const float4*)&b[c0 - 2];
        *(float4*)&wp2[2] = *(const float4*)&b[c0];
        *(float4*)&wp2[4] = *(const float4*)&b[c0 + 2];
        b = buf + (s + 3) * 100;
        *(float4*)&wp3[0] = *(const float4*)&b[c0];
    }

#define ACC(o, v) { acc.x = fmaf(f[o], (v).x, acc.x); acc.y = fmaf(f[o], (v).y, acc.y); }
    #pragma unroll
    for (int k = 0; k < 2; k++) {
        {
            const float* f = cf[k];
            float2 acc = make_float2(0.f, 0.f);
            ACC(0,  w0 [k + 2]); ACC(1,  wp1[k + 2]); ACC(2,  wm1[k + 2]);
            ACC(3,  w0 [k + 3]); ACC(4,  w0 [k + 1]); ACC(5,  wp1[k + 3]);
            ACC(6,  wp1[k + 1]); ACC(7,  wm1[k + 3]); ACC(8,  wm1[k + 1]);
            ACC(9,  wp2[k + 2]); ACC(10, wm2[k]);     ACC(11, w0 [k + 4]);
            ACC(12, w0 [k]);
            out[k] = acc;
        }
        {
            const float* f = cf[2 + k];
            float2 acc = make_float2(0.f, 0.f);
            ACC(0,  wp1[k + 2]); ACC(1,  wp2[k + 2]); ACC(2,  w0 [k + 2]);
            ACC(3,  wp1[k + 3]); ACC(4,  wp1[k + 1]); ACC(5,  wp2[k + 3]);
            ACC(6,  wp2[k + 1]); ACC(7,  w0 [k + 3]); ACC(8,  w0 [k + 1]);
            ACC(9,  wp3[k]);     ACC(10, wm1[k + 2]); ACC(11, wp1[k + 4]);
            ACC(12, wp1[k]);
            out[2 + k] = acc;
        }
    }
#undef ACC
}

// --- 16-CTA cluster, ONE exchange/step via redundant t-halo compute ---------
__global__ void __launch_bounds__(240, 1)
euler16_kernel(const int* __restrict__ steps_ptr)
{
    __shared__ float2 u_s[14 * 100];
    __shared__ float2 t_s[10 * 100];

    int tid   = threadIdx.x;
    int rank  = blockIdx.x;
    int steps = *steps_ptr;
    float dz  = 1.5f / (float)steps;

    for (int idx = tid; idx < 1400; idx += 240) {
        int su = idx / 100, c = idx % 100;
        int gi = rank * 6 + su - 4;
        int gj = c - 2;
        float2 v = make_float2(0.f, 0.f);
        if (gi >= 0 && gi < NN && gj >= 0 && gj < NN) v = g_U0[gi * NN + gj];
        u_s[idx] = v;
    }
    for (int idx = tid; idx < 1000; idx += 240)
        t_s[idx] = make_float2(0.f, 0.f);

    int tj = tid % 48;
    int ti = tid / 48;
    int lr = 2 * ti - 2;
    int j0 = 2 * tj;
    int c0 = j0 + 2;
    int su = lr + 4;
    int st = lr + 2;
    bool own = (ti >= 1 && ti <= 3);

    float m[4][13], ci[4][13];
    #pragma unroll
    for (int pt = 0; pt < 4; pt++) {
        int grow = rank * 6 + lr + (pt >> 1);
        int col  = j0 + (pt & 1);
        bool val = (grow >= 0) && (grow < NN);
        int p    = val ? (grow * NN + col) : 0;
        #pragma unroll
        for (int o = 0; o < NOFF; o++)
            m[pt][o] = val ? g_m[p * NOFF + o] : 0.f;
    }
    float2 uv[4];
    if (own) {
        #pragma unroll
        for (int pt = 0; pt < 4; pt++) {
            int p = (rank * 6 + lr + (pt >> 1)) * NN + (j0 + (pt & 1));
            #pragma unroll
            for (int o = 0; o < NOFF; o++)
                ci[pt][o] = g_ci[p * NOFF + o];
        }
        int pr0 = (rank * 6 + lr) * NN + j0;
        uv[0] = g_U0[pr0];
        uv[1] = g_U0[pr0 + 1];
        uv[2] = g_U0[pr0 + NN];
        uv[3] = g_U0[pr0 + NN + 1];
    }

    cg::cluster_group cl = cg::this_cluster();
    float2* up_u = (rank > 0)  ? cl.map_shared_rank(u_s, rank - 1) : (float2*)0;
    float2* dn_u = (rank < 15) ? cl.map_shared_rank(u_s, rank + 1) : (float2*)0;

    bool push_up = (rank > 0)  && (ti == 1 || ti == 2);
    bool push_dn = (rank < 15) && (ti == 2 || ti == 3);
    int  up_r0 = (ti == 1 ? 10 : 12) * 100 + c0;
    int  dn_r0 = (ti == 2 ? 0 : 2) * 100 + c0;

    __syncthreads();
    CL_ARRIVE(); CL_WAIT();

    float2 tv[4], vv[4];
    for (int st_i = 0; st_i < steps; st_i++) {
        if (!(ti == 2 && st_i > 0)) {
            sten2x2(m, u_s, su, c0, tv);
            *(float4*)&t_s[st * 100 + c0]       = *(float4*)&tv[0];
            *(float4*)&t_s[(st + 1) * 100 + c0] = *(float4*)&tv[2];
        }
        __syncthreads();

        if (own) {
            sten2x2(ci, t_s, st, c0, vv);
            #pragma unroll
            for (int q = 0; q < 4; q++) {
                uv[q].x = fmaf(-dz, vv[q].y, uv[q].x);
                uv[q].y = fmaf( dz, vv[q].x, uv[q].y);
            }
        }
        if (st_i + 1 == steps) break;

        if (own) {
            *(float4*)&u_s[su * 100 + c0]       = *(float4*)&uv[0];
            *(float4*)&u_s[(su + 1) * 100 + c0] = *(float4*)&uv[2];
            if (push_up) {
                *(float4*)&up_u[up_r0]       = *(float4*)&uv[0];
                *(float4*)&up_u[up_r0 + 100] = *(float4*)&uv[2];
            }
            if (push_dn) {
                *(float4*)&dn_u[dn_r0]       = *(float4*)&uv[0];
                *(float4*)&dn_u[dn_r0 + 100] = *(float4*)&uv[2];
            }
        }
        CL_ARRIVE();
        __syncthreads();

        if (ti == 2) {
            sten2x2(m, u_s, su, c0, tv);
            *(float4*)&t_s[st * 100 + c0]       = *(float4*)&tv[0];
            *(float4*)&t_s[(st + 1) * 100 + c0] = *(float4*)&tv[2];
        }
        CL_WAIT();
    }

    if (own) {
        int pr0 = (rank * 6 + lr) * NN + j0;
        g_Uz[pr0]          = uv[0];
        g_Uz[pr0 + 1]      = uv[1];
        g_Uz[pr0 + NN]     = uv[2];
        g_Uz[pr0 + NN + 1] = uv[3];
    }
}

// --- 8-CTA fallback (proven): 12 rows/CTA, 2 points/thread, cluster.sync ----
__device__ __forceinline__ float2 sten13(const float* __restrict__ cf,
                                         const float2* __restrict__ buf,
                                         int s, int c)
{
    const int DI[13] = {0, 1, -1, 0, 0, 1, 1, -1, -1, 2, -2, 0, 0};
    const int DJ[13] = {0, 0, 0, 1, -1, 1, -1, 1, -1, 0, 0, 2, -2};
    float2 acc = make_float2(0.f, 0.f);
    #pragma unroll
    for (int o = 0; o < 13; o++) {
        float2 v = buf[(s + DI[o]) * 100 + (c + DJ[o])];
        acc.x = fmaf(cf[o], v.x, acc.x);
        acc.y = fmaf(cf[o], v.y, acc.y);
    }
    return acc;
}

__global__ void __cluster_dims__(8, 1, 1) __launch_bounds__(576, 1)
euler8_kernel(const int* __restrict__ steps_ptr)
{
    __shared__ float2 u_s[16 * 100];
    __shared__ float2 t_s[16 * 100];

    cg::cluster_group cl = cg::this_cluster();
    int tid   = threadIdx.x;
    int rank  = blockIdx.x;
    int steps = *steps_ptr;
    float dz  = 1.5f / (float)steps;

    for (int idx = tid; idx < 1600; idx += 576) {
        int s = idx / 100, c = idx % 100;
        int gi = rank * 12 + s - 2;
        int gj = c - 2;
        float2 v = make_float2(0.f, 0.f);
        if (gi >= 0 && gi < NN && gj >= 0 && gj < NN) v = g_U0[gi * NN + gj];
        u_s[idx] = v;
        t_s[idx] = make_float2(0.f, 0.f);
    }

    int li0 = tid / NN, lj = tid % NN;
    int li1 = li0 + 6;
    int s0  = li0 + 2, s1 = li1 + 2, c = lj + 2;
    int p0  = (rank * 12 + li0) * NN + lj;
    int p1  = p0 + 6 * NN;

    float m0[13], ci0[13], m1[13], ci1[13];
    #pragma unroll
    for (int o = 0; o < 13; o++) {
        m0[o]  = g_m [p0 * NOFF + o];
        ci0[o] = g_ci[p0 * NOFF + o];
        m1[o]  = g_m [p1 * NOFF + o];
        ci1[o] = g_ci[p1 * NOFF + o];
    }

    float2* up_u = (rank > 0) ? cl.map_shared_rank(u_s, rank - 1) : (float2*)0;
    float2* up_t = (rank > 0) ? cl.map_shared_rank(t_s, rank - 1) : (float2*)0;
    float2* dn_u = (rank < 7) ? cl.map_shared_rank(u_s, rank + 1) : (float2*)0;
    float2* dn_t = (rank < 7) ? cl.map_shared_rank(t_s, rank + 1) : (float2*)0;

    bool push_up = (rank > 0) && (li0 < 2);
    bool push_dn = (rank < 7) && (li0 >= 4);
    int  up_off  = (li0 + 14) * 100 + c;
    int  dn_off  = (li1 - 10) * 100 + c;

    cl.sync();

    for (int st = 0; st < steps; st++) {
        float2 t0 = sten13(m0, u_s, s0, c);
        float2 t1 = sten13(m1, u_s, s1, c);
        t_s[s0 * 100 + c] = t0;
        t_s[s1 * 100 + c] = t1;
        if (push_up) up_t[up_off] = t0;
        if (push_dn) dn_t[dn_off] = t1;
        cl.sync();

        float2 v0 = sten13(ci0, t_s, s0, c);
        float2 v1 = sten13(ci1, t_s, s1, c);
        float2 u0 = u_s[s0 * 100 + c];
        float2 u1 = u_s[s1 * 100 + c];
        u0.x = fmaf(-dz, v0.y, u0.x); u0.y = fmaf(dz, v0.x, u0.y);
        u1.x = fmaf(-dz, v1.y, u1.x); u1.y = fmaf(dz, v1.x, u1.y);
        u_s[s0 * 100 + c] = u0;
        u_s[s1 * 100 + c] = u1;
        if (push_up) up_u[up_off] = u0;
        if (push_dn) dn_u[dn_off] = u1;
        cl.sync();
    }

    g_Uz[p0] = u_s[s0 * 100 + c];
    g_Uz[p1] = u_s[s1 * 100 + c];
}

// ---------------- kernel 5: outer-product expansion -------------------------
__global__ __launch_bounds__(256) void expand_kernel(const float* __restrict__ prof_re,
                                                     const float* __restrict__ prof_im,
                                                     float* __restrict__ out)
{
    int gid = blockIdx.x * 256 + threadIdx.x;
    if (gid >= OUTPLANE) return;
    int y = gid / OUTSIDE, x = gid - y * OUTSIDE;
    int i = y >> 3, p = y & 7;
    int j = x >> 3, q = x & 7;
    int cell = i * NN + j;
    float2 u = g_Uz[cell];
    float  e = g_Eys[cell];
    float gr = u.x * e, gi = u.y * e;
    float pr = prof_re[p * 8 + q];
    float pi = prof_im[p * 8 + q];
    out[gid]            = gr * pr - gi * pi;
    out[OUTPLANE + gid] = gr * pi + gi * pr;
}

// ---------------- launch ----------------------------------------------------
extern "C" void kernel_launch(void* const* d_in, const int* in_sizes, int n_in,
                              void* d_out, int out_size)
{
    const float* h_paras = (const float*)d_in[0];
    const float* E0      = (const float*)d_in[1];
    const float* w1n = (const float*)d_in[2];
    const float* b1n = (const float*)d_in[3];
    const float* w2n = (const float*)d_in[4];
    const float* b2n = (const float*)d_in[5];
    const float* w3n = (const float*)d_in[6];
    const float* b3n = (const float*)d_in[7];
    const float* w1c = (const float*)d_in[8];
    const float* b1c = (const float*)d_in[9];
    const float* w2c = (const float*)d_in[10];
    const float* b2c = (const float*)d_in[11];
    const float* w3c = (const float*)d_in[12];
    const float* b3c = (const float*)d_in[13];
    const float* w1k = (const float*)d_in[14];
    const float* b1k = (const float*)d_in[15];
    const float* w2k = (const float*)d_in[16];
    const float* b2k = (const float*)d_in[17];
    const float* w3k = (const float*)d_in[18];
    const float* b3k = (const float*)d_in[19];
    const float* prof_re = (const float*)d_in[20];
    const float* prof_im = (const float*)d_in[21];
    const float* dis     = (const float*)d_in[22];
    const float* mask    = (const float*)d_in[23];
    const float* is_ctr  = (const float*)d_in[24];
    const int*   coo     = (const int*)d_in[25];
    const int*   steps   = (const int*)d_in[26];
    float* out = (float*)d_out;

    prep_kernel<<<(NSQ + 255) / 256, 256>>>(h_paras, E0);
    mlp_kernel<<<NSQ / 128, 256>>>(0, w1n, b1n, w2n, b2n, w3n, b3n, dis, coo);
    mlp_kernel<<<NNZ / 128, 256>>>(1, w1c, b1c, w2c, b2c, w3c, b3c, dis, coo);
    mlp_kernel<<<NNZ / 128, 256>>>(2, w1k, b1k, w2k, b2k, w3k, b3k, dis, coo);
    coeff_kernel<<<(NNZ + 255) / 256, 256>>>(mask, is_ctr);

    // Euler: try 16-CTA cluster (nonportable), deterministic fallback to 8-CTA.
    cudaError_t err = cudaFuncSetAttribute(
        euler16_kernel, cudaFuncAttributeNonPortableClusterSizeAllowed, 1);
    if (err == cudaSuccess) {
        cudaLaunchConfig_t cfg = {};
        cfg.gridDim  = dim3(16, 1, 1);
        cfg.blockDim = dim3(240, 1, 1);
        cfg.dynamicSmemBytes = 0;
        cfg.stream = 0;
        cudaLaunchAttribute attrs[1];
        attrs[0].id = cudaLaunchAttributeClusterDimension;
        attrs[0].val.clusterDim.x = 16;
        attrs[0].val.clusterDim.y = 1;
        attrs[0].val.clusterDim.z = 1;
        cfg.attrs = attrs;
        cfg.numAttrs = 1;
        err = cudaLaunchKernelEx(&cfg, euler16_kernel, steps);
    }
    if (err != cudaSuccess) {
        cudaGetLastError();   // clear sticky state from the failed attempt
        euler8_kernel<<<8, 576>>>(steps);
    }

    expand_kernel<<<(OUTPLANE + 255) / 256, 256>>>(prof_re, prof_im, out);
}

// round 13
// speedup vs baseline: 1.5802x; 1.0384x over previous
#include <cuda_runtime.h>
#include <cuda_bf16.h>
#include <mma.h>
#include <cooperative_groups.h>
#include <math.h>
#include <stdint.h>

namespace cg = cooperative_groups;
using namespace nvcuda;

#define NN      96
#define NSQ     9216
#define NOFF    13
#define NNZ     119808
#define SIDE    816
#define BORD    24
#define KCONST  6.683942601602444f   /* 2*pi/0.94 */
#define OUTSIDE 768
#define OUTPLANE (OUTSIDE*OUTSIDE)

typedef unsigned long long u64;

// ---------------- scratch (static device globals; no allocation) ------------
__device__ float  g_hs[NSQ];
__device__ float  g_Eys[NSQ];
__device__ float  g_neff[NSQ];
__device__ float2 g_U0[NSQ];
__device__ float2 g_Uz[NSQ];
__device__ float  g_craw[NNZ];
__device__ float  g_kraw[NNZ];
__device__ float  g_m[NNZ];
__device__ float  g_ci[NNZ];

// ---------------- packed fp32x2 + approx tanh helpers ------------------------
__device__ __forceinline__ u64 fma2(u64 a, u64 b, u64 c)
{
    u64 d;
    asm("fma.rn.f32x2 %0, %1, %2, %3;" : "=l"(d) : "l"(a), "l"(b), "l"(c));
    return d;
}
__device__ __forceinline__ u64 dup2(float x)
{
    u64 d;
    unsigned r = __float_as_uint(x);
    asm("mov.b64 %0, {%1, %1};" : "=l"(d) : "r"(r));
    return d;
}
__device__ __forceinline__ float lo32(u64 v) { return __uint_as_float((unsigned)v); }
__device__ __forceinline__ float hi32(u64 v) { return __uint_as_float((unsigned)(v >> 32)); }
__device__ __forceinline__ float tanha(float x)
{
    float y;
    asm("tanh.approx.f32 %0, %1;" : "=f"(y) : "f"(x));
    return y;
}

// ---------------- kernel 1: hs / Eys / U0 (8x8 pooling) ---------------------
__global__ __launch_bounds__(256) void prep_kernel(const float* __restrict__ h_paras,
                                                   const float* __restrict__ E0)
{
    int p = blockIdx.x * 256 + threadIdx.x;
    if (p >= NSQ) return;
    float h  = h_paras[p];
    float s  = 1.f / (1.f + expf(-h));
    float hs = s * 0.6f + 0.2f;
    g_hs[p]  = hs;
    g_Eys[p] = 1.0f + 0.1f * tanhf(hs);
    float coupl = 0.5f + 0.5f * (1.f / (1.f + expf(-hs)));

    int i = p / NN, j = p % NN;
    const float* base = E0 + (size_t)(BORD + 8 * i) * SIDE + (BORD + 8 * j);
    float sum = 0.f;
    #pragma unroll
    for (int pi = 0; pi < 8; pi++) {
        float4 a = *(const float4*)(base + pi * SIDE);
        float4 b = *(const float4*)(base + pi * SIDE + 4);
        sum += (a.x + a.y) + (a.z + a.w) + (b.x + b.y) + (b.z + b.w);
    }
    g_U0[p] = make_float2(sum * (1.f / 64.f) * coupl, 0.f);
}

// ---------------- kernel 2a: fp32 MLP (mode 0 neff; fallback for 1/2) -------
__global__ __launch_bounds__(256, 2) void mlp_kernel(int mode,
    const float* __restrict__ w1, const float* __restrict__ b1,
    const float* __restrict__ w2, const float* __restrict__ b2,
    const float* __restrict__ w3, const float* __restrict__ b3,
    const float* __restrict__ dis, const int* __restrict__ coo)
{
    __shared__ float h1s[32 * 128];
    __shared__ float w2s[32 * 128];
    __shared__ float xs[4 * 128];
    float* red = h1s;

    int tid  = threadIdx.x;
    int base = blockIdx.x * 128;

    if (tid < 128) {
        int e = base + tid;
        if (mode == 0) {
            xs[tid] = g_hs[e];
        } else {
            int r = coo[e];
            int c = coo[NNZ + e];
            xs[tid]       = g_hs[r];
            xs[128 + tid] = g_hs[c];
            xs[256 + tid] = dis[2 * e];
            xs[384 + tid] = dis[2 * e + 1];
        }
    }
    __syncthreads();

    int tx = tid & 15, ty = tid >> 4;
    u64 acc2[4][8];
    #pragma unroll
    for (int p = 0; p < 4; p++)
        #pragma unroll
        for (int j = 0; j < 8; j++) acc2[p][j] = 0ull;

    for (int kb = 0; kb < 4; kb++) {
        #pragma unroll
        for (int it = 0; it < 16; it++) {
            int idx = tid + it * 256;
            int kk  = idx >> 7;
            int e   = idx & 127;
            int k   = kb * 32 + kk;
            float a = b1[k] + xs[e] * w1[k];
            if (mode != 0) {
                a += xs[128 + e] * w1[128 + k] + xs[256 + e] * w1[256 + k]
                   + xs[384 + e] * w1[384 + k];
                h1s[kk * 128 + e] = tanha(a);
            } else {
                h1s[kk * 128 + e] = tanhf(a);
            }
            w2s[idx] = w2[kb * 4096 + idx];
        }
        __syncthreads();

        #pragma unroll 4
        for (int k = 0; k < 32; k++) {
            ulonglong2 A0 = *(const ulonglong2*)&h1s[k * 128 + tx * 8];
            ulonglong2 A1 = *(const ulonglong2*)&h1s[k * 128 + tx * 8 + 4];
            float4 c0 = *(const float4*)&w2s[k * 128 + ty * 8];
            float4 c1 = *(const float4*)&w2s[k * 128 + ty * 8 + 4];
            u64 ap[4] = {A0.x, A0.y, A1.x, A1.y};
            u64 bp[8] = {dup2(c0.x), dup2(c0.y), dup2(c0.z), dup2(c0.w),
                         dup2(c1.x), dup2(c1.y), dup2(c1.z), dup2(c1.w)};
            #pragma unroll
            for (int p = 0; p < 4; p++)
                #pragma unroll
                for (int j = 0; j < 8; j++)
                    acc2[p][j] = fma2(ap[p], bp[j], acc2[p][j]);
        }
        __syncthreads();
    }

    #pragma unroll
    for (int i = 0; i < 8; i++) {
        float part = 0.f;
        #pragma unroll
        for (int j = 0; j < 8; j++) {
            u64 v = acc2[i >> 1][j];
            float pre = ((i & 1) ? hi32(v) : lo32(v)) + b2[ty * 8 + j];
            float h2 = (mode != 0) ? tanha(pre) : tanhf(pre);
            part = fmaf(h2, w3[ty * 8 + j], part);
        }
        red[ty * 128 + tx * 8 + i] = part;
    }
    __syncthreads();
    if (tid < 128) {
        float s = b3[0];
        #pragma unroll
        for (int t = 0; t < 16; t++) s += red[t * 128 + tid];
        int e = base + tid;
        if (mode == 0)      g_neff[e] = s;
        else if (mode == 1) g_craw[e] = s;
        else                g_kraw[e] = s;
    }
}

// ---------------- kernel 2b: wmma bf16-split edge MLP (modes 1/2) -----------
// A = layer-1 output (128 edges x 128 k), stored k-major (col_major for wmma),
// split hi/lo bf16. B = w2 (k-major row_major). D = AhiBhi + AhiBlo + AloBhi,
// fp32 accumulate in fragments. K chunked by 32 (2 wmma k-steps per chunk).
#define WM_LD    136                 /* padded leading dim (elements)        */
#define WM_XS    0                   /* float[512]          = 2048 B         */
#define WM_AHI   2048                /* bf16[32][136]       = 8704 B         */
#define WM_ALO   (WM_AHI + 8704)
#define WM_BHI   (WM_ALO + 8704)
#define WM_BLO   (WM_BHI + 8704)
#define WM_STAGE (WM_BLO + 8704)     /* float[8][256]       = 8192 B         */
#define WM_SMEM  (WM_STAGE + 8192)   /* 45056 B total                        */

__global__ __launch_bounds__(256, 2) void mlp_wmma_kernel(int mode,
    const float* __restrict__ w1, const float* __restrict__ b1,
    const float* __restrict__ w2, const float* __restrict__ b2,
    const float* __restrict__ w3, const float* __restrict__ b3,
    const float* __restrict__ dis, const int* __restrict__ coo)
{
    extern __shared__ char dsm[];
    float*          xs  = (float*)(dsm + WM_XS);
    __nv_bfloat16*  Ahi = (__nv_bfloat16*)(dsm + WM_AHI);
    __nv_bfloat16*  Alo = (__nv_bfloat16*)(dsm + WM_ALO);
    __nv_bfloat16*  Bhi = (__nv_bfloat16*)(dsm + WM_BHI);
    __nv_bfloat16*  Blo = (__nv_bfloat16*)(dsm + WM_BLO);

    int tid  = threadIdx.x;
    int wid  = tid >> 5;
    int lane = tid & 31;
    int base = blockIdx.x * 128;

    if (tid < 128) {
        int e = base + tid;
        int r = coo[e];
        int c = coo[NNZ + e];
        xs[tid]       = g_hs[r];
        xs[128 + tid] = g_hs[c];
        xs[256 + tid] = dis[2 * e];
        xs[384 + tid] = dis[2 * e + 1];
    }
    __syncthreads();

    wmma::fragment<wmma::accumulator, 16, 16, 16, float> acc[8];
    #pragma unroll
    for (int nt = 0; nt < 8; nt++) wmma::fill_fragment(acc[nt], 0.f);

    for (int kb = 0; kb < 4; kb++) {
        // fill: layer-1 + tanh + split (A), w2 chunk + split (B); k-major,
        // consecutive-e stores -> conflict-free
        #pragma unroll
        for (int it = 0; it < 16; it++) {
            int idx = tid + it * 256;           // 0..4095
            int kk  = idx >> 7;                 // 0..31
            int e   = idx & 127;                // 0..127  (edge row / B col)
            int k   = kb * 32 + kk;
            float a = b1[k] + xs[e] * w1[k]
                    + xs[128 + e] * w1[128 + k] + xs[256 + e] * w1[256 + k]
                    + xs[384 + e] * w1[384 + k];
            float h = tanha(a);
            __nv_bfloat16 ah = __float2bfloat16(h);
            __nv_bfloat16 al = __float2bfloat16(h - __bfloat162float(ah));
            Ahi[kk * WM_LD + e] = ah;
            Alo[kk * WM_LD + e] = al;

            float wv = w2[kb * 4096 + idx];     // w2[(kb*32+kk)*128 + e]
            __nv_bfloat16 bh = __float2bfloat16(wv);
            __nv_bfloat16 bl = __float2bfloat16(wv - __bfloat162float(bh));
            Bhi[kk * WM_LD + e] = bh;
            Blo[kk * WM_LD + e] = bl;
        }
        __syncthreads();

        #pragma unroll
        for (int kk = 0; kk < 32; kk += 16) {
            wmma::fragment<wmma::matrix_a, 16, 16, 16, __nv_bfloat16, wmma::col_major> a_hi, a_lo;
            wmma::load_matrix_sync(a_hi, Ahi + kk * WM_LD + wid * 16, WM_LD);
            wmma::load_matrix_sync(a_lo, Alo + kk * WM_LD + wid * 16, WM_LD);
            #pragma unroll
            for (int nt = 0; nt < 8; nt++) {
                wmma::fragment<wmma::matrix_b, 16, 16, 16, __nv_bfloat16, wmma::row_major> b_hi, b_lo;
                wmma::load_matrix_sync(b_hi, Bhi + kk * WM_LD + nt * 16, WM_LD);
                wmma::load_matrix_sync(b_lo, Blo + kk * WM_LD + nt * 16, WM_LD);
                wmma::mma_sync(acc[nt], a_hi, b_hi, acc[nt]);
                wmma::mma_sync(acc[nt], a_hi, b_lo, acc[nt]);
                wmma::mma_sync(acc[nt], a_lo, b_hi, acc[nt]);
            }
        }
        __syncthreads();
    }

    // epilogue: per-warp staging, tanh + w3 dot, shfl pair-reduce
    {
        float* stage = (float*)(dsm + WM_STAGE) + wid * 256;
        int r  = lane >> 1;          // row within warp tile 0..15
        int hf = lane & 1;           // column half
        float row_acc = 0.f;
        #pragma unroll
        for (int nt = 0; nt < 8; nt++) {
            wmma::store_matrix_sync(stage, acc[nt], 16, wmma::mem_row_major);
            __syncwarp();
            float part = 0.f;
            #pragma unroll
            for (int j = 0; j < 8; j++) {
                int col = nt * 16 + hf * 8 + j;
                float v = stage[r * 16 + hf * 8 + j] + b2[col];
                part = fmaf(tanha(v), w3[col], part);
            }
            row_acc += part;
            __syncwarp();
        }
        float other = __shfl_xor_sync(0xFFFFFFFFu, row_acc, 1);
        if (hf == 0) {
            float s = b3[0] + row_acc + other;
            int e = base + wid * 16 + r;
            if (mode == 1) g_craw[e] = s;
            else           g_kraw[e] = s;
        }
    }
}

// ---------------- kernel 3: edge coefficients -------------------------------
__global__ __launch_bounds__(256) void coeff_kernel(const float* __restrict__ mask,
                                                    const float* __restrict__ is_center)
{
    int e = blockIdx.x * 256 + threadIdx.x;
    if (e >= NNZ) return;
    float msk = mask[e];
    float ic  = is_center[e];
    float c   = msk * 0.05f * tanhf(g_craw[e]) + ic;
    float kv  = msk * 0.10f * tanhf(g_kraw[e]);
    int   r   = e / NOFF;
    g_m[e]  = KCONST * g_neff[r] * c + kv;
    g_ci[e] = 2.0f * ic - c;
}

// ---------------- kernel 4: Euler loop (R9 proven) --------------------------
#define CL_ARRIVE() asm volatile("barrier.cluster.arrive.aligned;" ::: "memory")
#define CL_WAIT()   asm volatile("barrier.cluster.wait.aligned;"   ::: "memory")

__device__ __forceinline__ void sten2x2(const float cf[4][13],
                                        const float2* __restrict__ buf,
                                        int s, int c0, float2* __restrict__ out)
{
    float2 wm2[2], wm1[6], w0[6], wp1[6], wp2[6], wp3[2];
    {
        const float2* b;
        b = buf + (s - 2) * 100;
        *(float4*)&wm2[0] = *(const float4*)&b[c0];
        b = buf + (s - 1) * 100;
        *(float4*)&wm1[0] = *(const float4*)&b[c0 - 2];
        *(float4*)&wm1[2] = *(const float4*)&b[c0];
        *(float4*)&wm1[4] = *(const float4*)&b[c0 + 2];
        b = buf + s * 100;
        *(float4*)&w0[0]  = *(const float4*)&b[c0 - 2];
        *(float4*)&w0[2]  = *(const float4*)&b[c0];
        *(float4*)&w0[4]  = *(const float4*)&b[c0 + 2];
        b = buf + (s + 1) * 100;
        *(float4*)&wp1[0] = *(const float4*)&b[c0 - 2];
        *(float4*)&wp1[2] = *(const float4*)&b[c0];
        *(float4*)&wp1[4] = *(const float4*)&b[c0 + 2];
        b = buf + (s + 2) * 100;
        *(float4*)&wp2[0] = *(const float4*)&b[c0 - 2];
        *(float4*)&wp2[2] = *(const float4*)&b[c0];
        *(float4*)&wp2[4] = *(const float4*)&b[c0 + 2];
        b = buf + (s + 3) * 100;
        *(float4*)&wp3[0] = *(const float4*)&b[c0];
    }

#define ACC(o, v) { acc.x = fmaf(f[o], (v).x, acc.x); acc.y = fmaf(f[o], (v).y, acc.y); }
    #pragma unroll
    for (int k = 0; k < 2; k++) {
        {
            const float* f = cf[k];
            float2 acc = make_float2(0.f, 0.f);
            ACC(0,  w0 [k + 2]); ACC(1,  wp1[k + 2]); ACC(2,  wm1[k + 2]);
            ACC(3,  w0 [k + 3]); ACC(4,  w0 [k + 1]); ACC(5,  wp1[k + 3]);
            ACC(6,  wp1[k + 1]); ACC(7,  wm1[k + 3]); ACC(8,  wm1[k + 1]);
            ACC(9,  wp2[k + 2]); ACC(10, wm2[k]);     ACC(11, w0 [k + 4]);
            ACC(12, w0 [k]);
            out[k] = acc;
        }
        {
            const float* f = cf[2 + k];
            float2 acc = make_float2(0.f, 0.f);
            ACC(0,  wp1[k + 2]); ACC(1,  wp2[k + 2]); ACC(2,  w0 [k + 2]);
            ACC(3,  wp1[k + 3]); ACC(4,  wp1[k + 1]); ACC(5,  wp2[k + 3]);
            ACC(6,  wp2[k + 1]); ACC(7,  w0 [k + 3]); ACC(8,  w0 [k + 1]);
            ACC(9,  wp3[k]);     ACC(10, wm1[k + 2]); ACC(11, wp1[k + 4]);
            ACC(12, wp1[k]);
            out[2 + k] = acc;
        }
    }
#undef ACC
}

__global__ void __launch_bounds__(240, 1)
euler16_kernel(const int* __restrict__ steps_ptr)
{
    __shared__ float2 u_s[14 * 100];
    __shared__ float2 t_s[10 * 100];

    int tid   = threadIdx.x;
    int rank  = blockIdx.x;
    int steps = *steps_ptr;
    float dz  = 1.5f / (float)steps;

    for (int idx = tid; idx < 1400; idx += 240) {
        int su = idx / 100, c = idx % 100;
        int gi = rank * 6 + su - 4;
        int gj = c - 2;
        float2 v = make_float2(0.f, 0.f);
        if (gi >= 0 && gi < NN && gj >= 0 && gj < NN) v = g_U0[gi * NN + gj];
        u_s[idx] = v;
    }
    for (int idx = tid; idx < 1000; idx += 240)
        t_s[idx] = make_float2(0.f, 0.f);

    int tj = tid % 48;
    int ti = tid / 48;
    int lr = 2 * ti - 2;
    int j0 = 2 * tj;
    int c0 = j0 + 2;
    int su = lr + 4;
    int st = lr + 2;
    bool own = (ti >= 1 && ti <= 3);

    float m[4][13], ci[4][13];
    #pragma unroll
    for (int pt = 0; pt < 4; pt++) {
        int grow = rank * 6 + lr + (pt >> 1);
        int col  = j0 + (pt & 1);
        bool val = (grow >= 0) && (grow < NN);
        int p    = val ? (grow * NN + col) : 0;
        #pragma unroll
        for (int o = 0; o < NOFF; o++)
            m[pt][o] = val ? g_m[p * NOFF + o] : 0.f;
    }
    float2 uv[4];
    if (own) {
        #pragma unroll
        for (int pt = 0; pt < 4; pt++) {
            int p = (rank * 6 + lr + (pt >> 1)) * NN + (j0 + (pt & 1));
            #pragma unroll
            for (int o = 0; o < NOFF; o++)
                ci[pt][o] = g_ci[p * NOFF + o];
        }
        int pr0 = (rank * 6 + lr) * NN + j0;
        uv[0] = g_U0[pr0];
        uv[1] = g_U0[pr0 + 1];
        uv[2] = g_U0[pr0 + NN];
        uv[3] = g_U0[pr0 + NN + 1];
    }

    cg::cluster_group cl = cg::this_cluster();
    float2* up_u = (rank > 0)  ? cl.map_shared_rank(u_s, rank - 1) : (float2*)0;
    float2* dn_u = (rank < 15) ? cl.map_shared_rank(u_s, rank + 1) : (float2*)0;

    bool push_up = (rank > 0)  && (ti == 1 || ti == 2);
    bool push_dn = (rank < 15) && (ti == 2 || ti == 3);
    int  up_r0 = (ti == 1 ? 10 : 12) * 100 + c0;
    int  dn_r0 = (ti == 2 ? 0 : 2) * 100 + c0;

    __syncthreads();
    CL_ARRIVE(); CL_WAIT();

    float2 tv[4], vv[4];
    for (int st_i = 0; st_i < steps; st_i++) {
        if (!(ti == 2 && st_i > 0)) {
            sten2x2(m, u_s, su, c0, tv);
            *(float4*)&t_s[st * 100 + c0]       = *(float4*)&tv[0];
            *(float4*)&t_s[(st + 1) * 100 + c0] = *(float4*)&tv[2];
        }
        __syncthreads();

        if (own) {
            sten2x2(ci, t_s, st, c0, vv);
            #pragma unroll
            for (int q = 0; q < 4; q++) {
                uv[q].x = fmaf(-dz, vv[q].y, uv[q].x);
                uv[q].y = fmaf( dz, vv[q].x, uv[q].y);
            }
        }
        if (st_i + 1 == steps) break;

        if (own) {
            *(float4*)&u_s[su * 100 + c0]       = *(float4*)&uv[0];
            *(float4*)&u_s[(su + 1) * 100 + c0] = *(float4*)&uv[2];
            if (push_up) {
                *(float4*)&up_u[up_r0]       = *(float4*)&uv[0];
                *(float4*)&up_u[up_r0 + 100] = *(float4*)&uv[2];
            }
            if (push_dn) {
                *(float4*)&dn_u[dn_r0]       = *(float4*)&uv[0];
                *(float4*)&dn_u[dn_r0 + 100] = *(float4*)&uv[2];
            }
        }
        CL_ARRIVE();
        __syncthreads();

        if (ti == 2) {
            sten2x2(m, u_s, su, c0, tv);
            *(float4*)&t_s[st * 100 + c0]       = *(float4*)&tv[0];
            *(float4*)&t_s[(st + 1) * 100 + c0] = *(float4*)&tv[2];
        }
        CL_WAIT();
    }

    if (own) {
        int pr0 = (rank * 6 + lr) * NN + j0;
        g_Uz[pr0]          = uv[0];
        g_Uz[pr0 + 1]      = uv[1];
        g_Uz[pr0 + NN]     = uv[2];
        g_Uz[pr0 + NN + 1] = uv[3];
    }
}

// --- 8-CTA fallback ----------------------------------------------------------
__device__ __forceinline__ float2 sten13(const float* __restrict__ cf,
                                         const float2* __restrict__ buf,
                                         int s, int c)
{
    const int DI[13] = {0, 1, -1, 0, 0, 1, 1, -1, -1, 2, -2, 0, 0};
    const int DJ[13] = {0, 0, 0, 1, -1, 1, -1, 1, -1, 0, 0, 2, -2};
    float2 acc = make_float2(0.f, 0.f);
    #pragma unroll
    for (int o = 0; o < 13; o++) {
        float2 v = buf[(s + DI[o]) * 100 + (c + DJ[o])];
        acc.x = fmaf(cf[o], v.x, acc.x);
        acc.y = fmaf(cf[o], v.y, acc.y);
    }
    return acc;
}

__global__ void __cluster_dims__(8, 1, 1) __launch_bounds__(576, 1)
euler8_kernel(const int* __restrict__ steps_ptr)
{
    __shared__ float2 u_s[16 * 100];
    __shared__ float2 t_s[16 * 100];

    cg::cluster_group cl = cg::this_cluster();
    int tid   = threadIdx.x;
    int rank  = blockIdx.x;
    int steps = *steps_ptr;
    float dz  = 1.5f / (float)steps;

    for (int idx = tid; idx < 1600; idx += 576) {
        int s = idx / 100, c = idx % 100;
        int gi = rank * 12 + s - 2;
        int gj = c - 2;
        float2 v = make_float2(0.f, 0.f);
        if (gi >= 0 && gi < NN && gj >= 0 && gj < NN) v = g_U0[gi * NN + gj];
        u_s[idx] = v;
        t_s[idx] = make_float2(0.f, 0.f);
    }

    int li0 = tid / NN, lj = tid % NN;
    int li1 = li0 + 6;
    int s0  = li0 + 2, s1 = li1 + 2, c = lj + 2;
    int p0  = (rank * 12 + li0) * NN + lj;
    int p1  = p0 + 6 * NN;

    float m0[13], ci0[13], m1[13], ci1[13];
    #pragma unroll
    for (int o = 0; o < 13; o++) {
        m0[o]  = g_m [p0 * NOFF + o];
        ci0[o] = g_ci[p0 * NOFF + o];
        m1[o]  = g_m [p1 * NOFF + o];
        ci1[o] = g_ci[p1 * NOFF + o];
    }

    float2* up_u = (rank > 0) ? cl.map_shared_rank(u_s, rank - 1) : (float2*)0;
    float2* up_t = (rank > 0) ? cl.map_shared_rank(t_s, rank - 1) : (float2*)0;
    float2* dn_u = (rank < 7) ? cl.map_shared_rank(u_s, rank + 1) : (float2*)0;
    float2* dn_t = (rank < 7) ? cl.map_shared_rank(t_s, rank + 1) : (float2*)0;

    bool push_up = (rank > 0) && (li0 < 2);
    bool push_dn = (rank < 7) && (li0 >= 4);
    int  up_off  = (li0 + 14) * 100 + c;
    int  dn_off  = (li1 - 10) * 100 + c;

    cl.sync();

    for (int st = 0; st < steps; st++) {
        float2 t0 = sten13(m0, u_s, s0, c);
        float2 t1 = sten13(m1, u_s, s1, c);
        t_s[s0 * 100 + c] = t0;
        t_s[s1 * 100 + c] = t1;
        if (push_up) up_t[up_off] = t0;
        if (push_dn) dn_t[dn_off] = t1;
        cl.sync();

        float2 v0 = sten13(ci0, t_s, s0, c);
        float2 v1 = sten13(ci1, t_s, s1, c);
        float2 u0 = u_s[s0 * 100 + c];
        float2 u1 = u_s[s1 * 100 + c];
        u0.x = fmaf(-dz, v0.y, u0.x); u0.y = fmaf(dz, v0.x, u0.y);
        u1.x = fmaf(-dz, v1.y, u1.x); u1.y = fmaf(dz, v1.x, u1.y);
        u_s[s0 * 100 + c] = u0;
        u_s[s1 * 100 + c] = u1;
        if (push_up) up_u[up_off] = u0;
        if (push_dn) dn_u[dn_off] = u1;
        cl.sync();
    }

    g_Uz[p0] = u_s[s0 * 100 + c];
    g_Uz[p1] = u_s[s1 * 100 + c];
}

// ---------------- kernel 5: outer-product expansion -------------------------
__global__ __launch_bounds__(256) void expand_kernel(const float* __restrict__ prof_re,
                                                     const float* __restrict__ prof_im,
                                                     float* __restrict__ out)
{
    int gid = blockIdx.x * 256 + threadIdx.x;
    if (gid >= OUTPLANE) return;
    int y = gid / OUTSIDE, x = gid - y * OUTSIDE;
    int i = y >> 3, p = y & 7;
    int j = x >> 3, q = x & 7;
    int cell = i * NN + j;
    float2 u = g_Uz[cell];
    float  e = g_Eys[cell];
    float gr = u.x * e, gi = u.y * e;
    float pr = prof_re[p * 8 + q];
    float pi = prof_im[p * 8 + q];
    out[gid]            = gr * pr - gi * pi;
    out[OUTPLANE + gid] = gr * pi + gi * pr;
}

// ---------------- launch ----------------------------------------------------
extern "C" void kernel_launch(void* const* d_in, const int* in_sizes, int n_in,
                              void* d_out, int out_size)
{
    const float* h_paras = (const float*)d_in[0];
    const float* E0      = (const float*)d_in[1];
    const float* w1n = (const float*)d_in[2];
    const float* b1n = (const float*)d_in[3];
    const float* w2n = (const float*)d_in[4];
    const float* b2n = (const float*)d_in[5];
    const float* w3n = (const float*)d_in[6];
    const float* b3n = (const float*)d_in[7];
    const float* w1c = (const float*)d_in[8];
    const float* b1c = (const float*)d_in[9];
    const float* w2c = (const float*)d_in[10];
    const float* b2c = (const float*)d_in[11];
    const float* w3c = (const float*)d_in[12];
    const float* b3c = (const float*)d_in[13];
    const float* w1k = (const float*)d_in[14];
    const float* b1k = (const float*)d_in[15];
    const float* w2k = (const float*)d_in[16];
    const float* b2k = (const float*)d_in[17];
    const float* w3k = (const float*)d_in[18];
    const float* b3k = (const float*)d_in[19];
    const float* prof_re = (const float*)d_in[20];
    const float* prof_im = (const float*)d_in[21];
    const float* dis     = (const float*)d_in[22];
    const float* mask    = (const float*)d_in[23];
    const float* is_ctr  = (const float*)d_in[24];
    const int*   coo     = (const int*)d_in[25];
    const int*   steps   = (const int*)d_in[26];
    float* out = (float*)d_out;

    prep_kernel<<<(NSQ + 255) / 256, 256>>>(h_paras, E0);
    mlp_kernel<<<NSQ / 128, 256>>>(0, w1n, b1n, w2n, b2n, w3n, b3n, dis, coo);

    cudaError_t aerr = cudaFuncSetAttribute(
        mlp_wmma_kernel, cudaFuncAttributeMaxDynamicSharedMemorySize, WM_SMEM);
    if (aerr == cudaSuccess) {
        mlp_wmma_kernel<<<NNZ / 128, 256, WM_SMEM>>>(1, w1c, b1c, w2c, b2c, w3c, b3c, dis, coo);
        mlp_wmma_kernel<<<NNZ / 128, 256, WM_SMEM>>>(2, w1k, b1k, w2k, b2k, w3k, b3k, dis, coo);
    } else {
        cudaGetLastError();
        mlp_kernel<<<NNZ / 128, 256>>>(1, w1c, b1c, w2c, b2c, w3c, b3c, dis, coo);
        mlp_kernel<<<NNZ / 128, 256>>>(2, w1k, b1k, w2k, b2k, w3k, b3k, dis, coo);
    }
    coeff_kernel<<<(NNZ + 255) / 256, 256>>>(mask, is_ctr);

    cudaError_t err = cudaFuncSetAttribute(
        euler16_kernel, cudaFuncAttributeNonPortableClusterSizeAllowed, 1);
    if (err == cudaSuccess) {
        cudaLaunchConfig_t cfg = {};
        cfg.gridDim  = dim3(16, 1, 1);
        cfg.blockDim = dim3(240, 1, 1);
        cfg.dynamicSmemBytes = 0;
        cfg.stream = 0;
        cudaLaunchAttribute attrs[1];
        attrs[0].id = cudaLaunchAttributeClusterDimension;
        attrs[0].val.clusterDim.x = 16;
        attrs[0].val.clusterDim.y = 1;
        attrs[0].val.clusterDim.z = 1;
        cfg.attrs = attrs;
        cfg.numAttrs = 1;
        err = cudaLaunchKernelEx(&cfg, euler16_kernel, steps);
    }
    if (err != cudaSuccess) {
        cudaGetLastError();
        euler8_kernel<<<8, 576>>>(steps);
    }

    expand_kernel<<<(OUTPLANE + 255) / 256, 256>>>(prof_re, prof_im, out);
}

// round 14
// speedup vs baseline: 1.7070x; 1.0802x over previous
#include <cuda_runtime.h>
#include <cuda_bf16.h>
#include <mma.h>
#include <cooperative_groups.h>
#include <math.h>
#include <stdint.h>

namespace cg = cooperative_groups;
using namespace nvcuda;

#define NN      96
#define NSQ     9216
#define NOFF    13
#define NNZ     119808
#define SIDE    816
#define BORD    24
#define KCONST  6.683942601602444f   /* 2*pi/0.94 */
#define OUTSIDE 768
#define OUTPLANE (OUTSIDE*OUTSIDE)
#define NEDGEBLK 936                 /* NNZ / 128 */

typedef unsigned long long u64;

// ---------------- scratch (static device globals; no allocation) ------------
__device__ float  g_hs[NSQ];
__device__ float  g_Eys[NSQ];
__device__ float  g_neff[NSQ];
__device__ float2 g_U0[NSQ];
__device__ float2 g_Uz[NSQ];
__device__ float  g_craw[NNZ];
__device__ float  g_kraw[NNZ];
__device__ float  g_m[NNZ];
__device__ float  g_ci[NNZ];

// ---------------- helpers ----------------------------------------------------
__device__ __forceinline__ u64 fma2(u64 a, u64 b, u64 c)
{
    u64 d;
    asm("fma.rn.f32x2 %0, %1, %2, %3;" : "=l"(d) : "l"(a), "l"(b), "l"(c));
    return d;
}
__device__ __forceinline__ u64 dup2(float x)
{
    u64 d;
    unsigned r = __float_as_uint(x);
    asm("mov.b64 %0, {%1, %1};" : "=l"(d) : "r"(r));
    return d;
}
__device__ __forceinline__ float lo32(u64 v) { return __uint_as_float((unsigned)v); }
__device__ __forceinline__ float hi32(u64 v) { return __uint_as_float((unsigned)(v >> 32)); }
__device__ __forceinline__ float tanha(float x)
{
    float y;
    asm("tanh.approx.f32 %0, %1;" : "=f"(y) : "f"(x));
    return y;
}
// pack truncated-bf16 of (f0, f1) -> (hi1<<16)|hi0
__device__ __forceinline__ unsigned pack_hi2(float f0, float f1)
{
    unsigned d;
    asm("prmt.b32 %0, %1, %2, 0x7632;"
        : "=r"(d) : "r"(__float_as_uint(f0)), "r"(__float_as_uint(f1)));
    return d;
}
// rn-bf16x2 of (lo0, lo1) -> (bf16(lo1)<<16)|bf16(lo0)
__device__ __forceinline__ unsigned pack_lo2(float lo0, float lo1)
{
    unsigned d;
    asm("cvt.rn.bf16x2.f32 %0, %1, %2;" : "=r"(d) : "f"(lo1), "f"(lo0));
    return d;
}
__device__ __forceinline__ float trunc16(float f)
{
    return __uint_as_float(__float_as_uint(f) & 0xFFFF0000u);
}

// ---------------- kernel 1: hs / Eys / U0 (8x8 pooling) ---------------------
__global__ __launch_bounds__(256) void prep_kernel(const float* __restrict__ h_paras,
                                                   const float* __restrict__ E0)
{
    int p = blockIdx.x * 256 + threadIdx.x;
    if (p >= NSQ) return;
    float h  = h_paras[p];
    float s  = 1.f / (1.f + expf(-h));
    float hs = s * 0.6f + 0.2f;
    g_hs[p]  = hs;
    g_Eys[p] = 1.0f + 0.1f * tanhf(hs);
    float coupl = 0.5f + 0.5f * (1.f / (1.f + expf(-hs)));

    int i = p / NN, j = p % NN;
    const float* base = E0 + (size_t)(BORD + 8 * i) * SIDE + (BORD + 8 * j);
    float sum = 0.f;
    #pragma unroll
    for (int pi = 0; pi < 8; pi++) {
        float4 a = *(const float4*)(base + pi * SIDE);
        float4 b = *(const float4*)(base + pi * SIDE + 4);
        sum += (a.x + a.y) + (a.z + a.w) + (b.x + b.y) + (b.z + b.w);
    }
    g_U0[p] = make_float2(sum * (1.f / 64.f) * coupl, 0.f);
}

// ---------------- kernel 2a: fp32 MLP (mode 0 neff; fallback for 1/2) -------
__global__ __launch_bounds__(256, 2) void mlp_kernel(int mode,
    const float* __restrict__ w1, const float* __restrict__ b1,
    const float* __restrict__ w2, const float* __restrict__ b2,
    const float* __restrict__ w3, const float* __restrict__ b3,
    const float* __restrict__ dis, const int* __restrict__ coo)
{
    __shared__ float h1s[32 * 128];
    __shared__ float w2s[32 * 128];
    __shared__ float xs[4 * 128];
    float* red = h1s;

    int tid  = threadIdx.x;
    int base = blockIdx.x * 128;

    if (tid < 128) {
        int e = base + tid;
        if (mode == 0) {
            xs[tid] = g_hs[e];
        } else {
            int r = coo[e];
            int c = coo[NNZ + e];
            xs[tid]       = g_hs[r];
            xs[128 + tid] = g_hs[c];
            xs[256 + tid] = dis[2 * e];
            xs[384 + tid] = dis[2 * e + 1];
        }
    }
    __syncthreads();

    int tx = tid & 15, ty = tid >> 4;
    u64 acc2[4][8];
    #pragma unroll
    for (int p = 0; p < 4; p++)
        #pragma unroll
        for (int j = 0; j < 8; j++) acc2[p][j] = 0ull;

    for (int kb = 0; kb < 4; kb++) {
        #pragma unroll
        for (int it = 0; it < 16; it++) {
            int idx = tid + it * 256;
            int kk  = idx >> 7;
            int e   = idx & 127;
            int k   = kb * 32 + kk;
            float a = b1[k] + xs[e] * w1[k];
            if (mode != 0) {
                a += xs[128 + e] * w1[128 + k] + xs[256 + e] * w1[256 + k]
                   + xs[384 + e] * w1[384 + k];
                h1s[kk * 128 + e] = tanha(a);
            } else {
                h1s[kk * 128 + e] = tanhf(a);
            }
            w2s[idx] = w2[kb * 4096 + idx];
        }
        __syncthreads();

        #pragma unroll 4
        for (int k = 0; k < 32; k++) {
            ulonglong2 A0 = *(const ulonglong2*)&h1s[k * 128 + tx * 8];
            ulonglong2 A1 = *(const ulonglong2*)&h1s[k * 128 + tx * 8 + 4];
            float4 c0 = *(const float4*)&w2s[k * 128 + ty * 8];
            float4 c1 = *(const float4*)&w2s[k * 128 + ty * 8 + 4];
            u64 ap[4] = {A0.x, A0.y, A1.x, A1.y};
            u64 bp[8] = {dup2(c0.x), dup2(c0.y), dup2(c0.z), dup2(c0.w),
                         dup2(c1.x), dup2(c1.y), dup2(c1.z), dup2(c1.w)};
            #pragma unroll
            for (int p = 0; p < 4; p++)
                #pragma unroll
                for (int j = 0; j < 8; j++)
                    acc2[p][j] = fma2(ap[p], bp[j], acc2[p][j]);
        }
        __syncthreads();
    }

    #pragma unroll
    for (int i = 0; i < 8; i++) {
        float part = 0.f;
        #pragma unroll
        for (int j = 0; j < 8; j++) {
            u64 v = acc2[i >> 1][j];
            float pre = ((i & 1) ? hi32(v) : lo32(v)) + b2[ty * 8 + j];
            float h2 = (mode != 0) ? tanha(pre) : tanhf(pre);
            part = fmaf(h2, w3[ty * 8 + j], part);
        }
        red[ty * 128 + tx * 8 + i] = part;
    }
    __syncthreads();
    if (tid < 128) {
        float s = b3[0];
        #pragma unroll
        for (int t = 0; t < 16; t++) s += red[t * 128 + tid];
        int e = base + tid;
        if (mode == 0)      g_neff[e] = s;
        else if (mode == 1) g_craw[e] = s;
        else                g_kraw[e] = s;
    }
}

// ---------------- kernel 2b: merged wmma bf16-split edge MLPs ---------------
// Grid = 2*936: blocks [0,936) compute c-MLP, [936,1872) compute k-MLP.
// A row-major [128 e][32 k] (AL=40), B row-major [32 k][128 n] (BL=136),
// hi = truncated bf16 (prmt-packed), lo = rn bf16 of residual.
// D = AhiBhi + AhiBlo + AloBhi, fp32 wmma accumulate.
#define WM_AL    40
#define WM_BL    136
#define WM_XS    0                     /* float[512]              2048 B */
#define WM_AHI   2048                  /* bf16[128][40]          10240 B */
#define WM_ALO   12288
#define WM_BHI   22528                 /* bf16[32][136]           8704 B */
#define WM_BLO   31232
#define WM_STAGE 39936                 /* float[8][256]           8192 B */
#define WM_SMEM  48128

__global__ __launch_bounds__(256, 2) void mlp_wmma_kernel(
    const float* __restrict__ w1c, const float* __restrict__ b1c,
    const float* __restrict__ w2c, const float* __restrict__ b2c,
    const float* __restrict__ w3c, const float* __restrict__ b3c,
    const float* __restrict__ w1k, const float* __restrict__ b1k,
    const float* __restrict__ w2k, const float* __restrict__ b2k,
    const float* __restrict__ w3k, const float* __restrict__ b3k,
    const float* __restrict__ dis, const int* __restrict__ coo)
{
    extern __shared__ char dsm[];
    float*          xs  = (float*)(dsm + WM_XS);
    __nv_bfloat16*  Ahi = (__nv_bfloat16*)(dsm + WM_AHI);
    __nv_bfloat16*  Alo = (__nv_bfloat16*)(dsm + WM_ALO);
    __nv_bfloat16*  Bhi = (__nv_bfloat16*)(dsm + WM_BHI);
    __nv_bfloat16*  Blo = (__nv_bfloat16*)(dsm + WM_BLO);

    int  tid   = threadIdx.x;
    int  wid   = tid >> 5;
    int  lane  = tid & 31;
    bool is_k  = (blockIdx.x >= NEDGEBLK);
    int  base  = (is_k ? blockIdx.x - NEDGEBLK : blockIdx.x) * 128;

    const float* w1 = is_k ? w1k : w1c;
    const float* b1 = is_k ? b1k : b1c;
    const float* w2 = is_k ? w2k : w2c;
    const float* b2 = is_k ? b2k : b2c;
    const float* w3 = is_k ? w3k : w3c;
    const float* b3 = is_k ? b3k : b3c;

    if (tid < 128) {
        int e = base + tid;
        int r = coo[e];
        int c = coo[NNZ + e];
        xs[tid]       = g_hs[r];
        xs[128 + tid] = g_hs[c];
        xs[256 + tid] = dis[2 * e];
        xs[384 + tid] = dis[2 * e + 1];
    }
    __syncthreads();

    // per-thread A-fill coordinates: e = tid>>1, k-half = (tid&1)*16
    int ea  = tid >> 1;
    int khh = (tid & 1) << 4;
    float x0 = xs[ea], x1 = xs[128 + ea], x2 = xs[256 + ea], x3 = xs[384 + ea];

    wmma::fragment<wmma::accumulator, 16, 16, 16, float> acc[8];
    #pragma unroll
    for (int nt = 0; nt < 8; nt++) wmma::fill_fragment(acc[nt], 0.f);

    for (int kb = 0; kb < 4; kb++) {
        // ---- A fill: layer-1 + tanh + split, packed pair stores ----
        #pragma unroll
        for (int i = 0; i < 16; i += 2) {
            int kl = khh + i;
            int k  = kb * 32 + kl;
            float f0 = b1[k]     + x0 * w1[k]     + x1 * w1[128 + k]
                     + x2 * w1[256 + k]           + x3 * w1[384 + k];
            float f1 = b1[k + 1] + x0 * w1[k + 1] + x1 * w1[129 + k]
                     + x2 * w1[257 + k]           + x3 * w1[385 + k];
            f0 = tanha(f0);
            f1 = tanha(f1);
            unsigned hi2 = pack_hi2(f0, f1);
            unsigned lo2 = pack_lo2(f0 - trunc16(f0), f1 - trunc16(f1));
            *(unsigned*)&Ahi[ea * WM_AL + kl] = hi2;
            *(unsigned*)&Alo[ea * WM_AL + kl] = lo2;
        }
        // ---- B fill: w2 chunk, float4 loads, packed stores ----
        #pragma unroll
        for (int it = 0; it < 4; it++) {
            int flat = (it * 256 + tid) * 4;          // 0..4095 step 4
            float4 wv = *(const float4*)&w2[kb * 4096 + flat];
            int kr = flat >> 7;
            int n  = flat & 127;
            uint2 hi = make_uint2(pack_hi2(wv.x, wv.y), pack_hi2(wv.z, wv.w));
            uint2 lo = make_uint2(pack_lo2(wv.x - trunc16(wv.x), wv.y - trunc16(wv.y)),
                                  pack_lo2(wv.z - trunc16(wv.z), wv.w - trunc16(wv.w)));
            *(uint2*)&Bhi[kr * WM_BL + n] = hi;
            *(uint2*)&Blo[kr * WM_BL + n] = lo;
        }
        __syncthreads();

        #pragma unroll
        for (int kk = 0; kk < 32; kk += 16) {
            wmma::fragment<wmma::matrix_a, 16, 16, 16, __nv_bfloat16, wmma::row_major> a_hi, a_lo;
            wmma::load_matrix_sync(a_hi, Ahi + (wid * 16) * WM_AL + kk, WM_AL);
            wmma::load_matrix_sync(a_lo, Alo + (wid * 16) * WM_AL + kk, WM_AL);
            #pragma unroll
            for (int nt = 0; nt < 8; nt++) {
                wmma::fragment<wmma::matrix_b, 16, 16, 16, __nv_bfloat16, wmma::row_major> b_hi, b_lo;
                wmma::load_matrix_sync(b_hi, Bhi + kk * WM_BL + nt * 16, WM_BL);
                wmma::load_matrix_sync(b_lo, Blo + kk * WM_BL + nt * 16, WM_BL);
                wmma::mma_sync(acc[nt], a_hi, b_hi, acc[nt]);
                wmma::mma_sync(acc[nt], a_hi, b_lo, acc[nt]);
                wmma::mma_sync(acc[nt], a_lo, b_hi, acc[nt]);
            }
        }
        __syncthreads();
    }

    // epilogue: per-warp staging, tanh + w3 dot, shfl pair-reduce
    {
        float* stage = (float*)(dsm + WM_STAGE) + wid * 256;
        int r  = lane >> 1;
        int hf = lane & 1;
        float row_acc = 0.f;
        #pragma unroll
        for (int nt = 0; nt < 8; nt++) {
            wmma::store_matrix_sync(stage, acc[nt], 16, wmma::mem_row_major);
            __syncwarp();
            float part = 0.f;
            #pragma unroll
            for (int j = 0; j < 8; j++) {
                int col = nt * 16 + hf * 8 + j;
                float v = stage[r * 16 + hf * 8 + j] + b2[col];
                part = fmaf(tanha(v), w3[col], part);
            }
            row_acc += part;
            __syncwarp();
        }
        float other = __shfl_xor_sync(0xFFFFFFFFu, row_acc, 1);
        if (hf == 0) {
            float s = b3[0] + row_acc + other;
            int e = base + wid * 16 + r;
            if (is_k) g_kraw[e] = s;
            else      g_craw[e] = s;
        }
    }
}

// ---------------- kernel 3: edge coefficients -------------------------------
__global__ __launch_bounds__(256) void coeff_kernel(const float* __restrict__ mask,
                                                    const float* __restrict__ is_center)
{
    int e = blockIdx.x * 256 + threadIdx.x;
    if (e >= NNZ) return;
    float msk = mask[e];
    float ic  = is_center[e];
    float c   = msk * 0.05f * tanhf(g_craw[e]) + ic;
    float kv  = msk * 0.10f * tanhf(g_kraw[e]);
    int   r   = e / NOFF;
    g_m[e]  = KCONST * g_neff[r] * c + kv;
    g_ci[e] = 2.0f * ic - c;
}

// ---------------- kernel 4: Euler loop (R9 proven) --------------------------
#define CL_ARRIVE() asm volatile("barrier.cluster.arrive.aligned;" ::: "memory")
#define CL_WAIT()   asm volatile("barrier.cluster.wait.aligned;"   ::: "memory")

__device__ __forceinline__ void sten2x2(const float cf[4][13],
                                        const float2* __restrict__ buf,
                                        int s, int c0, float2* __restrict__ out)
{
    float2 wm2[2], wm1[6], w0[6], wp1[6], wp2[6], wp3[2];
    {
        const float2* b;
        b = buf + (s - 2) * 100;
        *(float4*)&wm2[0] = *(const float4*)&b[c0];
        b = buf + (s - 1) * 100;
        *(float4*)&wm1[0] = *(const float4*)&b[c0 - 2];
        *(float4*)&wm1[2] = *(const float4*)&b[c0];
        *(float4*)&wm1[4] = *(const float4*)&b[c0 + 2];
        b = buf + s * 100;
        *(float4*)&w0[0]  = *(const float4*)&b[c0 - 2];
        *(float4*)&w0[2]  = *(const float4*)&b[c0];
        *(float4*)&w0[4]  = *(const float4*)&b[c0 + 2];
        b = buf + (s + 1) * 100;
        *(float4*)&wp1[0] = *(const float4*)&b[c0 - 2];
        *(float4*)&wp1[2] = *(const float4*)&b[c0];
        *(float4*)&wp1[4] = *(const float4*)&b[c0 + 2];
        b = buf + (s + 2) * 100;
        *(float4*)&wp2[0] = *(const float4*)&b[c0 - 2];
        *(float4*)&wp2[2] = *(const float4*)&b[c0];
        *(float4*)&wp2[4] = *(const float4*)&b[c0 + 2];
        b = buf + (s + 3) * 100;
        *(float4*)&wp3[0] = *(const float4*)&b[c0];
    }

#define ACC(o, v) { acc.x = fmaf(f[o], (v).x, acc.x); acc.y = fmaf(f[o], (v).y, acc.y); }
    #pragma unroll
    for (int k = 0; k < 2; k++) {
        {
            const float* f = cf[k];
            float2 acc = make_float2(0.f, 0.f);
            ACC(0,  w0 [k + 2]); ACC(1,  wp1[k + 2]); ACC(2,  wm1[k + 2]);
            ACC(3,  w0 [k + 3]); ACC(4,  w0 [k + 1]); ACC(5,  wp1[k + 3]);
            ACC(6,  wp1[k + 1]); ACC(7,  wm1[k + 3]); ACC(8,  wm1[k + 1]);
            ACC(9,  wp2[k + 2]); ACC(10, wm2[k]);     ACC(11, w0 [k + 4]);
            ACC(12, w0 [k]);
            out[k] = acc;
        }
        {
            const float* f = cf[2 + k];
            float2 acc = make_float2(0.f, 0.f);
            ACC(0,  wp1[k + 2]); ACC(1,  wp2[k + 2]); ACC(2,  w0 [k + 2]);
            ACC(3,  wp1[k + 3]); ACC(4,  wp1[k + 1]); ACC(5,  wp2[k + 3]);
            ACC(6,  wp2[k + 1]); ACC(7,  w0 [k + 3]); ACC(8,  w0 [k + 1]);
            ACC(9,  wp3[k]);     ACC(10, wm1[k + 2]); ACC(11, wp1[k + 4]);
            ACC(12, wp1[k]);
            out[2 + k] = acc;
        }
    }
#undef ACC
}

__global__ void __launch_bounds__(240, 1)
euler16_kernel(const int* __restrict__ steps_ptr)
{
    __shared__ float2 u_s[14 * 100];
    __shared__ float2 t_s[10 * 100];

    int tid   = threadIdx.x;
    int rank  = blockIdx.x;
    int steps = *steps_ptr;
    float dz  = 1.5f / (float)steps;

    for (int idx = tid; idx < 1400; idx += 240) {
        int su = idx / 100, c = idx % 100;
        int gi = rank * 6 + su - 4;
        int gj = c - 2;
        float2 v = make_float2(0.f, 0.f);
        if (gi >= 0 && gi < NN && gj >= 0 && gj < NN) v = g_U0[gi * NN + gj];
        u_s[idx] = v;
    }
    for (int idx = tid; idx < 1000; idx += 240)
        t_s[idx] = make_float2(0.f, 0.f);

    int tj = tid % 48;
    int ti = tid / 48;
    int lr = 2 * ti - 2;
    int j0 = 2 * tj;
    int c0 = j0 + 2;
    int su = lr + 4;
    int st = lr + 2;
    bool own = (ti >= 1 && ti <= 3);

    float m[4][13], ci[4][13];
    #pragma unroll
    for (int pt = 0; pt < 4; pt++) {
        int grow = rank * 6 + lr + (pt >> 1);
        int col  = j0 + (pt & 1);
        bool val = (grow >= 0) && (grow < NN);
        int p    = val ? (grow * NN + col) : 0;
        #pragma unroll
        for (int o = 0; o < NOFF; o++)
            m[pt][o] = val ? g_m[p * NOFF + o] : 0.f;
    }
    float2 uv[4];
    if (own) {
        #pragma unroll
        for (int pt = 0; pt < 4; pt++) {
            int p = (rank * 6 + lr + (pt >> 1)) * NN + (j0 + (pt & 1));
            #pragma unroll
            for (int o = 0; o < NOFF; o++)
                ci[pt][o] = g_ci[p * NOFF + o];
        }
        int pr0 = (rank * 6 + lr) * NN + j0;
        uv[0] = g_U0[pr0];
        uv[1] = g_U0[pr0 + 1];
        uv[2] = g_U0[pr0 + NN];
        uv[3] = g_U0[pr0 + NN + 1];
    }

    cg::cluster_group cl = cg::this_cluster();
    float2* up_u = (rank > 0)  ? cl.map_shared_rank(u_s, rank - 1) : (float2*)0;
    float2* dn_u = (rank < 15) ? cl.map_shared_rank(u_s, rank + 1) : (float2*)0;

    bool push_up = (rank > 0)  && (ti == 1 || ti == 2);
    bool push_dn = (rank < 15) && (ti == 2 || ti == 3);
    int  up_r0 = (ti == 1 ? 10 : 12) * 100 + c0;
    int  dn_r0 = (ti == 2 ? 0 : 2) * 100 + c0;

    __syncthreads();
    CL_ARRIVE(); CL_WAIT();

    float2 tv[4], vv[4];
    for (int st_i = 0; st_i < steps; st_i++) {
        if (!(ti == 2 && st_i > 0)) {
            sten2x2(m, u_s, su, c0, tv);
            *(float4*)&t_s[st * 100 + c0]       = *(float4*)&tv[0];
            *(float4*)&t_s[(st + 1) * 100 + c0] = *(float4*)&tv[2];
        }
        __syncthreads();

        if (own) {
            sten2x2(ci, t_s, st, c0, vv);
            #pragma unroll
            for (int q = 0; q < 4; q++) {
                uv[q].x = fmaf(-dz, vv[q].y, uv[q].x);
                uv[q].y = fmaf( dz, vv[q].x, uv[q].y);
            }
        }
        if (st_i + 1 == steps) break;

        if (own) {
            *(float4*)&u_s[su * 100 + c0]       = *(float4*)&uv[0];
            *(float4*)&u_s[(su + 1) * 100 + c0] = *(float4*)&uv[2];
            if (push_up) {
                *(float4*)&up_u[up_r0]       = *(float4*)&uv[0];
                *(float4*)&up_u[up_r0 + 100] = *(float4*)&uv[2];
            }
            if (push_dn) {
                *(float4*)&dn_u[dn_r0]       = *(float4*)&uv[0];
                *(float4*)&dn_u[dn_r0 + 100] = *(float4*)&uv[2];
            }
        }
        CL_ARRIVE();
        __syncthreads();

        if (ti == 2) {
            sten2x2(m, u_s, su, c0, tv);
            *(float4*)&t_s[st * 100 + c0]       = *(float4*)&tv[0];
            *(float4*)&t_s[(st + 1) * 100 + c0] = *(float4*)&tv[2];
        }
        CL_WAIT();
    }

    if (own) {
        int pr0 = (rank * 6 + lr) * NN + j0;
        g_Uz[pr0]          = uv[0];
        g_Uz[pr0 + 1]      = uv[1];
        g_Uz[pr0 + NN]     = uv[2];
        g_Uz[pr0 + NN + 1] = uv[3];
    }
}

// --- 8-CTA fallback ----------------------------------------------------------
__device__ __forceinline__ float2 sten13(const float* __restrict__ cf,
                                         const float2* __restrict__ buf,
                                         int s, int c)
{
    const int DI[13] = {0, 1, -1, 0, 0, 1, 1, -1, -1, 2, -2, 0, 0};
    const int DJ[13] = {0, 0, 0, 1, -1, 1, -1, 1, -1, 0, 0, 2, -2};
    float2 acc = make_float2(0.f, 0.f);
    #pragma unroll
    for (int o = 0; o < 13; o++) {
        float2 v = buf[(s + DI[o]) * 100 + (c + DJ[o])];
        acc.x = fmaf(cf[o], v.x, acc.x);
        acc.y = fmaf(cf[o], v.y, acc.y);
    }
    return acc;
}

__global__ void __cluster_dims__(8, 1, 1) __launch_bounds__(576, 1)
euler8_kernel(const int* __restrict__ steps_ptr)
{
    __shared__ float2 u_s[16 * 100];
    __shared__ float2 t_s[16 * 100];

    cg::cluster_group cl = cg::this_cluster();
    int tid   = threadIdx.x;
    int rank  = blockIdx.x;
    int steps = *steps_ptr;
    float dz  = 1.5f / (float)steps;

    for (int idx = tid; idx < 1600; idx += 576) {
        int s = idx / 100, c = idx % 100;
        int gi = rank * 12 + s - 2;
        int gj = c - 2;
        float2 v = make_float2(0.f, 0.f);
        if (gi >= 0 && gi < NN && gj >= 0 && gj < NN) v = g_U0[gi * NN + gj];
        u_s[idx] = v;
        t_s[idx] = make_float2(0.f, 0.f);
    }

    int li0 = tid / NN, lj = tid % NN;
    int li1 = li0 + 6;
    int s0  = li0 + 2, s1 = li1 + 2, c = lj + 2;
    int p0  = (rank * 12 + li0) * NN + lj;
    int p1  = p0 + 6 * NN;

    float m0[13], ci0[13], m1[13], ci1[13];
    #pragma unroll
    for (int o = 0; o < 13; o++) {
        m0[o]  = g_m [p0 * NOFF + o];
        ci0[o] = g_ci[p0 * NOFF + o];
        m1[o]  = g_m [p1 * NOFF + o];
        ci1[o] = g_ci[p1 * NOFF + o];
    }

    float2* up_u = (rank > 0) ? cl.map_shared_rank(u_s, rank - 1) : (float2*)0;
    float2* up_t = (rank > 0) ? cl.map_shared_rank(t_s, rank - 1) : (float2*)0;
    float2* dn_u = (rank < 7) ? cl.map_shared_rank(u_s, rank + 1) : (float2*)0;
    float2* dn_t = (rank < 7) ? cl.map_shared_rank(t_s, rank + 1) : (float2*)0;

    bool push_up = (rank > 0) && (li0 < 2);
    bool push_dn = (rank < 7) && (li0 >= 4);
    int  up_off  = (li0 + 14) * 100 + c;
    int  dn_off  = (li1 - 10) * 100 + c;

    cl.sync();

    for (int st = 0; st < steps; st++) {
        float2 t0 = sten13(m0, u_s, s0, c);
        float2 t1 = sten13(m1, u_s, s1, c);
        t_s[s0 * 100 + c] = t0;
        t_s[s1 * 100 + c] = t1;
        if (push_up) up_t[up_off] = t0;
        if (push_dn) dn_t[dn_off] = t1;
        cl.sync();

        float2 v0 = sten13(ci0, t_s, s0, c);
        float2 v1 = sten13(ci1, t_s, s1, c);
        float2 u0 = u_s[s0 * 100 + c];
        float2 u1 = u_s[s1 * 100 + c];
        u0.x = fmaf(-dz, v0.y, u0.x); u0.y = fmaf(dz, v0.x, u0.y);
        u1.x = fmaf(-dz, v1.y, u1.x); u1.y = fmaf(dz, v1.x, u1.y);
        u_s[s0 * 100 + c] = u0;
        u_s[s1 * 100 + c] = u1;
        if (push_up) up_u[up_off] = u0;
        if (push_dn) dn_u[dn_off] = u1;
        cl.sync();
    }

    g_Uz[p0] = u_s[s0 * 100 + c];
    g_Uz[p1] = u_s[s1 * 100 + c];
}

// ---------------- kernel 5: outer-product expansion -------------------------
__global__ __launch_bounds__(256) void expand_kernel(const float* __restrict__ prof_re,
                                                     const float* __restrict__ prof_im,
                                                     float* __restrict__ out)
{
    int gid = blockIdx.x * 256 + threadIdx.x;
    if (gid >= OUTPLANE) return;
    int y = gid / OUTSIDE, x = gid - y * OUTSIDE;
    int i = y >> 3, p = y & 7;
    int j = x >> 3, q = x & 7;
    int cell = i * NN + j;
    float2 u = g_Uz[cell];
    float  e = g_Eys[cell];
    float gr = u.x * e, gi = u.y * e;
    float pr = prof_re[p * 8 + q];
    float pi = prof_im[p * 8 + q];
    out[gid]            = gr * pr - gi * pi;
    out[OUTPLANE + gid] = gr * pi + gi * pr;
}

// ---------------- launch ----------------------------------------------------
extern "C" void kernel_launch(void* const* d_in, const int* in_sizes, int n_in,
                              void* d_out, int out_size)
{
    const float* h_paras = (const float*)d_in[0];
    const float* E0      = (const float*)d_in[1];
    const float* w1n = (const float*)d_in[2];
    const float* b1n = (const float*)d_in[3];
    const float* w2n = (const float*)d_in[4];
    const float* b2n = (const float*)d_in[5];
    const float* w3n = (const float*)d_in[6];
    const float* b3n = (const float*)d_in[7];
    const float* w1c = (const float*)d_in[8];
    const float* b1c = (const float*)d_in[9];
    const float* w2c = (const float*)d_in[10];
    const float* b2c = (const float*)d_in[11];
    const float* w3c = (const float*)d_in[12];
    const float* b3c = (const float*)d_in[13];
    const float* w1k = (const float*)d_in[14];
    const float* b1k = (const float*)d_in[15];
    const float* w2k = (const float*)d_in[16];
    const float* b2k = (const float*)d_in[17];
    const float* w3k = (const float*)d_in[18];
    const float* b3k = (const float*)d_in[19];
    const float* prof_re = (const float*)d_in[20];
    const float* prof_im = (const float*)d_in[21];
    const float* dis     = (const float*)d_in[22];
    const float* mask    = (const float*)d_in[23];
    const float* is_ctr  = (const float*)d_in[24];
    const int*   coo     = (const int*)d_in[25];
    const int*   steps   = (const int*)d_in[26];
    float* out = (float*)d_out;

    prep_kernel<<<(NSQ + 255) / 256, 256>>>(h_paras, E0);
    mlp_kernel<<<NSQ / 128, 256>>>(0, w1n, b1n, w2n, b2n, w3n, b3n, dis, coo);

    cudaError_t aerr = cudaFuncSetAttribute(
        mlp_wmma_kernel, cudaFuncAttributeMaxDynamicSharedMemorySize, WM_SMEM);
    if (aerr == cudaSuccess) {
        mlp_wmma_kernel<<<2 * NEDGEBLK, 256, WM_SMEM>>>(
            w1c, b1c, w2c, b2c, w3c, b3c,
            w1k, b1k, w2k, b2k, w3k, b3k, dis, coo);
    } else {
        cudaGetLastError();
        mlp_kernel<<<NEDGEBLK, 256>>>(1, w1c, b1c, w2c, b2c, w3c, b3c, dis, coo);
        mlp_kernel<<<NEDGEBLK, 256>>>(2, w1k, b1k, w2k, b2k, w3k, b3k, dis, coo);
    }
    coeff_kernel<<<(NNZ + 255) / 256, 256>>>(mask, is_ctr);

    cudaError_t err = cudaFuncSetAttribute(
        euler16_kernel, cudaFuncAttributeNonPortableClusterSizeAllowed, 1);
    if (err == cudaSuccess) {
        cudaLaunchConfig_t cfg = {};
        cfg.gridDim  = dim3(16, 1, 1);
        cfg.blockDim = dim3(240, 1, 1);
        cfg.dynamicSmemBytes = 0;
        cfg.stream = 0;
        cudaLaunchAttribute attrs[1];
        attrs[0].id = cudaLaunchAttributeClusterDimension;
        attrs[0].val.clusterDim.x = 16;
        attrs[0].val.clusterDim.y = 1;
        attrs[0].val.clusterDim.z = 1;
        cfg.attrs = attrs;
        cfg.numAttrs = 1;
        err = cudaLaunchKernelEx(&cfg, euler16_kernel, steps);
    }
    if (err != cudaSuccess) {
        cudaGetLastError();
        euler8_kernel<<<8, 576>>>(steps);
    }

    expand_kernel<<<(OUTPLANE + 255) / 256, 256>>>(prof_re, prof_im, out);
}

// round 15
// speedup vs baseline: 1.7212x; 1.0083x over previous
#include <cuda_runtime.h>
#include <cuda_bf16.h>
#include <mma.h>
#include <cooperative_groups.h>
#include <math.h>
#include <stdint.h>

namespace cg = cooperative_groups;
using namespace nvcuda;

#define NN      96
#define NSQ     9216
#define NOFF    13
#define NNZ     119808
#define SIDE    816
#define BORD    24
#define KCONST  6.683942601602444f   /* 2*pi/0.94 */
#define OUTSIDE 768
#define OUTPLANE (OUTSIDE*OUTSIDE)
#define NEDGEBLK 936                 /* NNZ / 128 */

typedef unsigned long long u64;

// ---------------- scratch (static device globals; no allocation) ------------
__device__ float  g_hs[NSQ];
__device__ float  g_Eys[NSQ];
__device__ float  g_neff[NSQ];
__device__ float2 g_U0[NSQ];
__device__ float2 g_Uz[NSQ];
__device__ float  g_craw[NNZ];
__device__ float  g_kraw[NNZ];
__device__ float  g_m[NNZ];
__device__ float  g_ci[NNZ];
// pre-split w2 (bf16x2 packed pairs): 16384 floats -> 8192 uints per MLP
__device__ unsigned g_w2hi_c[8192];
__device__ unsigned g_w2lo_c[8192];
__device__ unsigned g_w2hi_k[8192];
__device__ unsigned g_w2lo_k[8192];

// ---------------- helpers ----------------------------------------------------
__device__ __forceinline__ u64 fma2(u64 a, u64 b, u64 c)
{
    u64 d;
    asm("fma.rn.f32x2 %0, %1, %2, %3;" : "=l"(d) : "l"(a), "l"(b), "l"(c));
    return d;
}
__device__ __forceinline__ u64 dup2(float x)
{
    u64 d;
    unsigned r = __float_as_uint(x);
    asm("mov.b64 %0, {%1, %1};" : "=l"(d) : "r"(r));
    return d;
}
__device__ __forceinline__ float lo32(u64 v) { return __uint_as_float((unsigned)v); }
__device__ __forceinline__ float hi32(u64 v) { return __uint_as_float((unsigned)(v >> 32)); }
__device__ __forceinline__ float tanha(float x)
{
    float y;
    asm("tanh.approx.f32 %0, %1;" : "=f"(y) : "f"(x));
    return y;
}
// pack truncated-bf16 of (f0, f1) -> (hi1<<16)|hi0
__device__ __forceinline__ unsigned pack_hi2(float f0, float f1)
{
    unsigned d;
    asm("prmt.b32 %0, %1, %2, 0x7632;"
        : "=r"(d) : "r"(__float_as_uint(f0)), "r"(__float_as_uint(f1)));
    return d;
}
// rn-bf16x2 of (lo0, lo1) -> (bf16(lo1)<<16)|bf16(lo0)
__device__ __forceinline__ unsigned pack_lo2(float lo0, float lo1)
{
    unsigned d;
    asm("cvt.rn.bf16x2.f32 %0, %1, %2;" : "=r"(d) : "f"(lo1), "f"(lo0));
    return d;
}
__device__ __forceinline__ float trunc16(float f)
{
    return __uint_as_float(__float_as_uint(f) & 0xFFFF0000u);
}

// ---------------- kernel 0: pre-split w2 into bf16 hi/lo --------------------
__global__ __launch_bounds__(256) void splitw2_kernel(const float* __restrict__ w2c,
                                                      const float* __restrict__ w2k)
{
    int i = blockIdx.x * 256 + threadIdx.x;      // pair index 0..8191
    if (i >= 8192) return;
    float2 c = *(const float2*)&w2c[2 * i];
    g_w2hi_c[i] = pack_hi2(c.x, c.y);
    g_w2lo_c[i] = pack_lo2(c.x - trunc16(c.x), c.y - trunc16(c.y));
    float2 k = *(const float2*)&w2k[2 * i];
    g_w2hi_k[i] = pack_hi2(k.x, k.y);
    g_w2lo_k[i] = pack_lo2(k.x - trunc16(k.x), k.y - trunc16(k.y));
}

// ---------------- kernel 1: hs / Eys / U0 (8x8 pooling) ---------------------
__global__ __launch_bounds__(256) void prep_kernel(const float* __restrict__ h_paras,
                                                   const float* __restrict__ E0)
{
    int p = blockIdx.x * 256 + threadIdx.x;
    if (p >= NSQ) return;
    float h  = h_paras[p];
    float s  = 1.f / (1.f + expf(-h));
    float hs = s * 0.6f + 0.2f;
    g_hs[p]  = hs;
    g_Eys[p] = 1.0f + 0.1f * tanhf(hs);
    float coupl = 0.5f + 0.5f * (1.f / (1.f + expf(-hs)));

    int i = p / NN, j = p % NN;
    const float* base = E0 + (size_t)(BORD + 8 * i) * SIDE + (BORD + 8 * j);
    float sum = 0.f;
    #pragma unroll
    for (int pi = 0; pi < 8; pi++) {
        float4 a = *(const float4*)(base + pi * SIDE);
        float4 b = *(const float4*)(base + pi * SIDE + 4);
        sum += (a.x + a.y) + (a.z + a.w) + (b.x + b.y) + (b.z + b.w);
    }
    g_U0[p] = make_float2(sum * (1.f / 64.f) * coupl, 0.f);
}

// ---------------- kernel 2a: fp32 MLP (mode 0 neff; fallback for 1/2) -------
__global__ __launch_bounds__(256, 2) void mlp_kernel(int mode,
    const float* __restrict__ w1, const float* __restrict__ b1,
    const float* __restrict__ w2, const float* __restrict__ b2,
    const float* __restrict__ w3, const float* __restrict__ b3,
    const float* __restrict__ dis, const int* __restrict__ coo)
{
    __shared__ float h1s[32 * 128];
    __shared__ float w2s[32 * 128];
    __shared__ float xs[4 * 128];
    float* red = h1s;

    int tid  = threadIdx.x;
    int base = blockIdx.x * 128;

    if (tid < 128) {
        int e = base + tid;
        if (mode == 0) {
            xs[tid] = g_hs[e];
        } else {
            int r = coo[e];
            int c = coo[NNZ + e];
            xs[tid]       = g_hs[r];
            xs[128 + tid] = g_hs[c];
            xs[256 + tid] = dis[2 * e];
            xs[384 + tid] = dis[2 * e + 1];
        }
    }
    __syncthreads();

    int tx = tid & 15, ty = tid >> 4;
    u64 acc2[4][8];
    #pragma unroll
    for (int p = 0; p < 4; p++)
        #pragma unroll
        for (int j = 0; j < 8; j++) acc2[p][j] = 0ull;

    for (int kb = 0; kb < 4; kb++) {
        #pragma unroll
        for (int it = 0; it < 16; it++) {
            int idx = tid + it * 256;
            int kk  = idx >> 7;
            int e   = idx & 127;
            int k   = kb * 32 + kk;
            float a = b1[k] + xs[e] * w1[k];
            if (mode != 0) {
                a += xs[128 + e] * w1[128 + k] + xs[256 + e] * w1[256 + k]
                   + xs[384 + e] * w1[384 + k];
                h1s[kk * 128 + e] = tanha(a);
            } else {
                h1s[kk * 128 + e] = tanhf(a);
            }
            w2s[idx] = w2[kb * 4096 + idx];
        }
        __syncthreads();

        #pragma unroll 4
        for (int k = 0; k < 32; k++) {
            ulonglong2 A0 = *(const ulonglong2*)&h1s[k * 128 + tx * 8];
            ulonglong2 A1 = *(const ulonglong2*)&h1s[k * 128 + tx * 8 + 4];
            float4 c0 = *(const float4*)&w2s[k * 128 + ty * 8];
            float4 c1 = *(const float4*)&w2s[k * 128 + ty * 8 + 4];
            u64 ap[4] = {A0.x, A0.y, A1.x, A1.y};
            u64 bp[8] = {dup2(c0.x), dup2(c0.y), dup2(c0.z), dup2(c0.w),
                         dup2(c1.x), dup2(c1.y), dup2(c1.z), dup2(c1.w)};
            #pragma unroll
            for (int p = 0; p < 4; p++)
                #pragma unroll
                for (int j = 0; j < 8; j++)
                    acc2[p][j] = fma2(ap[p], bp[j], acc2[p][j]);
        }
        __syncthreads();
    }

    #pragma unroll
    for (int i = 0; i < 8; i++) {
        float part = 0.f;
        #pragma unroll
        for (int j = 0; j < 8; j++) {
            u64 v = acc2[i >> 1][j];
            float pre = ((i & 1) ? hi32(v) : lo32(v)) + b2[ty * 8 + j];
            float h2 = (mode != 0) ? tanha(pre) : tanhf(pre);
            part = fmaf(h2, w3[ty * 8 + j], part);
        }
        red[ty * 128 + tx * 8 + i] = part;
    }
    __syncthreads();
    if (tid < 128) {
        float s = b3[0];
        #pragma unroll
        for (int t = 0; t < 16; t++) s += red[t * 128 + tid];
        int e = base + tid;
        if (mode == 0)      g_neff[e] = s;
        else if (mode == 1) g_craw[e] = s;
        else                g_kraw[e] = s;
    }
}

// ---------------- kernel 2b: merged wmma bf16-split edge MLPs ---------------
// Grid = 2*936: blocks [0,936) = c-MLP, [936,1872) = k-MLP.
// A row-major [128 e][32 k] (AL=40), B row-major [32 k][128 n] (BL=136).
// B is pre-split (splitw2_kernel); A split inline. Layer-1 via packed fma2.
#define WM_AL    40
#define WM_BL    136
#define WM_XS    0                     /* float[512]              2048 B */
#define WM_AHI   2048                  /* bf16[128][40]          10240 B */
#define WM_ALO   12288
#define WM_BHI   22528                 /* bf16[32][136]           8704 B */
#define WM_BLO   31232
#define WM_STAGE 39936                 /* float[8][256]           8192 B */
#define WM_SMEM  48128

__global__ __launch_bounds__(256, 2) void mlp_wmma_kernel(
    const float* __restrict__ w1c, const float* __restrict__ b1c,
    const float* __restrict__ b2c, const float* __restrict__ w3c,
    const float* __restrict__ b3c,
    const float* __restrict__ w1k, const float* __restrict__ b1k,
    const float* __restrict__ b2k, const float* __restrict__ w3k,
    const float* __restrict__ b3k,
    const float* __restrict__ dis, const int* __restrict__ coo)
{
    extern __shared__ char dsm[];
    float*          xs  = (float*)(dsm + WM_XS);
    __nv_bfloat16*  Ahi = (__nv_bfloat16*)(dsm + WM_AHI);
    __nv_bfloat16*  Alo = (__nv_bfloat16*)(dsm + WM_ALO);
    __nv_bfloat16*  Bhi = (__nv_bfloat16*)(dsm + WM_BHI);
    __nv_bfloat16*  Blo = (__nv_bfloat16*)(dsm + WM_BLO);

    int  tid   = threadIdx.x;
    int  wid   = tid >> 5;
    int  lane  = tid & 31;
    bool is_k  = (blockIdx.x >= NEDGEBLK);
    int  base  = (is_k ? blockIdx.x - NEDGEBLK : blockIdx.x) * 128;

    const float*    w1   = is_k ? w1k : w1c;
    const float*    b1   = is_k ? b1k : b1c;
    const float*    b2   = is_k ? b2k : b2c;
    const float*    w3   = is_k ? w3k : w3c;
    const float*    b3   = is_k ? b3k : b3c;
    const unsigned* w2hi = is_k ? g_w2hi_k : g_w2hi_c;
    const unsigned* w2lo = is_k ? g_w2lo_k : g_w2lo_c;

    if (tid < 128) {
        int e = base + tid;
        int r = coo[e];
        int c = coo[NNZ + e];
        xs[tid]       = g_hs[r];
        xs[128 + tid] = g_hs[c];
        xs[256 + tid] = dis[2 * e];
        xs[384 + tid] = dis[2 * e + 1];
    }
    __syncthreads();

    // per-thread A-fill coordinates: e = tid>>1, k-half = (tid&1)*16
    int ea  = tid >> 1;
    int khh = (tid & 1) << 4;
    u64 x0 = dup2(xs[ea]);
    u64 x1 = dup2(xs[128 + ea]);
    u64 x2 = dup2(xs[256 + ea]);
    u64 x3 = dup2(xs[384 + ea]);

    wmma::fragment<wmma::accumulator, 16, 16, 16, float> acc[8];
    #pragma unroll
    for (int nt = 0; nt < 8; nt++) wmma::fill_fragment(acc[nt], 0.f);

    for (int kb = 0; kb < 4; kb++) {
        // ---- A fill: layer-1 (packed fma2) + tanh + split ----
        #pragma unroll
        for (int i = 0; i < 16; i += 2) {
            int kl = khh + i;
            int k  = kb * 32 + kl;
            u64 a2 = *(const u64*)&b1[k];
            a2 = fma2(x0, *(const u64*)&w1[k],       a2);
            a2 = fma2(x1, *(const u64*)&w1[128 + k], a2);
            a2 = fma2(x2, *(const u64*)&w1[256 + k], a2);
            a2 = fma2(x3, *(const u64*)&w1[384 + k], a2);
            float f0 = tanha(lo32(a2));
            float f1 = tanha(hi32(a2));
            unsigned hi2 = pack_hi2(f0, f1);
            unsigned lo2 = pack_lo2(f0 - trunc16(f0), f1 - trunc16(f1));
            *(unsigned*)&Ahi[ea * WM_AL + kl] = hi2;
            *(unsigned*)&Alo[ea * WM_AL + kl] = lo2;
        }
        // ---- B fill: pre-split bf16, uint4 copy ----
        #pragma unroll
        for (int it = 0; it < 2; it++) {
            int idx4 = kb * 512 + it * 256 + tid;     // uint4 index
            uint4 hv = *(const uint4*)&w2hi[idx4 * 4];
            uint4 lv = *(const uint4*)&w2lo[idx4 * 4];
            int f  = idx4 * 8;                        // flat bf16 index
            int kr = (f >> 7) & 31;
            int n  = f & 127;
            *(uint4*)&Bhi[kr * WM_BL + n] = hv;
            *(uint4*)&Blo[kr * WM_BL + n] = lv;
        }
        __syncthreads();

        #pragma unroll
        for (int kk = 0; kk < 32; kk += 16) {
            wmma::fragment<wmma::matrix_a, 16, 16, 16, __nv_bfloat16, wmma::row_major> a_hi, a_lo;
            wmma::load_matrix_sync(a_hi, Ahi + (wid * 16) * WM_AL + kk, WM_AL);
            wmma::load_matrix_sync(a_lo, Alo + (wid * 16) * WM_AL + kk, WM_AL);
            #pragma unroll
            for (int nt = 0; nt < 8; nt++) {
                wmma::fragment<wmma::matrix_b, 16, 16, 16, __nv_bfloat16, wmma::row_major> b_hi, b_lo;
                wmma::load_matrix_sync(b_hi, Bhi + kk * WM_BL + nt * 16, WM_BL);
                wmma::load_matrix_sync(b_lo, Blo + kk * WM_BL + nt * 16, WM_BL);
                wmma::mma_sync(acc[nt], a_hi, b_hi, acc[nt]);
                wmma::mma_sync(acc[nt], a_hi, b_lo, acc[nt]);
                wmma::mma_sync(acc[nt], a_lo, b_hi, acc[nt]);
            }
        }
        __syncthreads();
    }

    // epilogue: per-warp staging, tanh + w3 dot, shfl pair-reduce
    {
        float* stage = (float*)(dsm + WM_STAGE) + wid * 256;
        int r  = lane >> 1;
        int hf = lane & 1;
        float row_acc = 0.f;
        #pragma unroll
        for (int nt = 0; nt < 8; nt++) {
            wmma::store_matrix_sync(stage, acc[nt], 16, wmma::mem_row_major);
            __syncwarp();
            float part = 0.f;
            #pragma unroll
            for (int j = 0; j < 8; j++) {
                int col = nt * 16 + hf * 8 + j;
                float v = stage[r * 16 + hf * 8 + j] + b2[col];
                part = fmaf(tanha(v), w3[col], part);
            }
            row_acc += part;
            __syncwarp();
        }
        float other = __shfl_xor_sync(0xFFFFFFFFu, row_acc, 1);
        if (hf == 0) {
            float s = b3[0] + row_acc + other;
            int e = base + wid * 16 + r;
            if (is_k) g_kraw[e] = s;
            else      g_craw[e] = s;
        }
    }
}

// ---------------- kernel 3: edge coefficients -------------------------------
__global__ __launch_bounds__(256) void coeff_kernel(const float* __restrict__ mask,
                                                    const float* __restrict__ is_center)
{
    int e = blockIdx.x * 256 + threadIdx.x;
    if (e >= NNZ) return;
    float msk = mask[e];
    float ic  = is_center[e];
    float c   = msk * 0.05f * tanhf(g_craw[e]) + ic;
    float kv  = msk * 0.10f * tanhf(g_kraw[e]);
    int   r   = e / NOFF;
    g_m[e]  = KCONST * g_neff[r] * c + kv;
    g_ci[e] = 2.0f * ic - c;
}

// ---------------- kernel 4: Euler loop (R9 proven) --------------------------
#define CL_ARRIVE() asm volatile("barrier.cluster.arrive.aligned;" ::: "memory")
#define CL_WAIT()   asm volatile("barrier.cluster.wait.aligned;"   ::: "memory")

__device__ __forceinline__ void sten2x2(const float cf[4][13],
                                        const float2* __restrict__ buf,
                                        int s, int c0, float2* __restrict__ out)
{
    float2 wm2[2], wm1[6], w0[6], wp1[6], wp2[6], wp3[2];
    {
        const float2* b;
        b = buf + (s - 2) * 100;
        *(float4*)&wm2[0] = *(const float4*)&b[c0];
        b = buf + (s - 1) * 100;
        *(float4*)&wm1[0] = *(const float4*)&b[c0 - 2];
        *(float4*)&wm1[2] = *(const float4*)&b[c0];
        *(float4*)&wm1[4] = *(const float4*)&b[c0 + 2];
        b = buf + s * 100;
        *(float4*)&w0[0]  = *(const float4*)&b[c0 - 2];
        *(float4*)&w0[2]  = *(const float4*)&b[c0];
        *(float4*)&w0[4]  = *(const float4*)&b[c0 + 2];
        b = buf + (s + 1) * 100;
        *(float4*)&wp1[0] = *(const float4*)&b[c0 - 2];
        *(float4*)&wp1[2] = *(const float4*)&b[c0];
        *(float4*)&wp1[4] = *(const float4*)&b[c0 + 2];
        b = buf + (s + 2) * 100;
        *(float4*)&wp2[0] = *(const float4*)&b[c0 - 2];
        *(float4*)&wp2[2] = *(const float4*)&b[c0];
        *(float4*)&wp2[4] = *(const float4*)&b[c0 + 2];
        b = buf + (s + 3) * 100;
        *(float4*)&wp3[0] = *(const float4*)&b[c0];
    }

#define ACC(o, v) { acc.x = fmaf(f[o], (v).x, acc.x); acc.y = fmaf(f[o], (v).y, acc.y); }
    #pragma unroll
    for (int k = 0; k < 2; k++) {
        {
            const float* f = cf[k];
            float2 acc = make_float2(0.f, 0.f);
            ACC(0,  w0 [k + 2]); ACC(1,  wp1[k + 2]); ACC(2,  wm1[k + 2]);
            ACC(3,  w0 [k + 3]); ACC(4,  w0 [k + 1]); ACC(5,  wp1[k + 3]);
            ACC(6,  wp1[k + 1]); ACC(7,  wm1[k + 3]); ACC(8,  wm1[k + 1]);
            ACC(9,  wp2[k + 2]); ACC(10, wm2[k]);     ACC(11, w0 [k + 4]);
            ACC(12, w0 [k]);
            out[k] = acc;
        }
        {
            const float* f = cf[2 + k];
            float2 acc = make_float2(0.f, 0.f);
            ACC(0,  wp1[k + 2]); ACC(1,  wp2[k + 2]); ACC(2,  w0 [k + 2]);
            ACC(3,  wp1[k + 3]); ACC(4,  wp1[k + 1]); ACC(5,  wp2[k + 3]);
            ACC(6,  wp2[k + 1]); ACC(7,  w0 [k + 3]); ACC(8,  w0 [k + 1]);
            ACC(9,  wp3[k]);     ACC(10, wm1[k + 2]); ACC(11, wp1[k + 4]);
            ACC(12, wp1[k]);
            out[2 + k] = acc;
        }
    }
#undef ACC
}

__global__ void __launch_bounds__(240, 1)
euler16_kernel(const int* __restrict__ steps_ptr)
{
    __shared__ float2 u_s[14 * 100];
    __shared__ float2 t_s[10 * 100];

    int tid   = threadIdx.x;
    int rank  = blockIdx.x;
    int steps = *steps_ptr;
    float dz  = 1.5f / (float)steps;

    for (int idx = tid; idx < 1400; idx += 240) {
        int su = idx / 100, c = idx % 100;
        int gi = rank * 6 + su - 4;
        int gj = c - 2;
        float2 v = make_float2(0.f, 0.f);
        if (gi >= 0 && gi < NN && gj >= 0 && gj < NN) v = g_U0[gi * NN + gj];
        u_s[idx] = v;
    }
    for (int idx = tid; idx < 1000; idx += 240)
        t_s[idx] = make_float2(0.f, 0.f);

    int tj = tid % 48;
    int ti = tid / 48;
    int lr = 2 * ti - 2;
    int j0 = 2 * tj;
    int c0 = j0 + 2;
    int su = lr + 4;
    int st = lr + 2;
    bool own = (ti >= 1 && ti <= 3);

    float m[4][13], ci[4][13];
    #pragma unroll
    for (int pt = 0; pt < 4; pt++) {
        int grow = rank * 6 + lr + (pt >> 1);
        int col  = j0 + (pt & 1);
        bool val = (grow >= 0) && (grow < NN);
        int p    = val ? (grow * NN + col) : 0;
        #pragma unroll
        for (int o = 0; o < NOFF; o++)
            m[pt][o] = val ? g_m[p * NOFF + o] : 0.f;
    }
    float2 uv[4];
    if (own) {
        #pragma unroll
        for (int pt = 0; pt < 4; pt++) {
            int p = (rank * 6 + lr + (pt >> 1)) * NN + (j0 + (pt & 1));
            #pragma unroll
            for (int o = 0; o < NOFF; o++)
                ci[pt][o] = g_ci[p * NOFF + o];
        }
        int pr0 = (rank * 6 + lr) * NN + j0;
        uv[0] = g_U0[pr0];
        uv[1] = g_U0[pr0 + 1];
        uv[2] = g_U0[pr0 + NN];
        uv[3] = g_U0[pr0 + NN + 1];
    }

    cg::cluster_group cl = cg::this_cluster();
    float2* up_u = (rank > 0)  ? cl.map_shared_rank(u_s, rank - 1) : (float2*)0;
    float2* dn_u = (rank < 15) ? cl.map_shared_rank(u_s, rank + 1) : (float2*)0;

    bool push_up = (rank > 0)  && (ti == 1 || ti == 2);
    bool push_dn = (rank < 15) && (ti == 2 || ti == 3);
    int  up_r0 = (ti == 1 ? 10 : 12) * 100 + c0;
    int  dn_r0 = (ti == 2 ? 0 : 2) * 100 + c0;

    __syncthreads();
    CL_ARRIVE(); CL_WAIT();

    float2 tv[4], vv[4];
    for (int st_i = 0; st_i < steps; st_i++) {
        if (!(ti == 2 && st_i > 0)) {
            sten2x2(m, u_s, su, c0, tv);
            *(float4*)&t_s[st * 100 + c0]       = *(float4*)&tv[0];
            *(float4*)&t_s[(st + 1) * 100 + c0] = *(float4*)&tv[2];
        }
        __syncthreads();

        if (own) {
            sten2x2(ci, t_s, st, c0, vv);
            #pragma unroll
            for (int q = 0; q < 4; q++) {
                uv[q].x = fmaf(-dz, vv[q].y, uv[q].x);
                uv[q].y = fmaf( dz, vv[q].x, uv[q].y);
            }
        }
        if (st_i + 1 == steps) break;

        if (own) {
            *(float4*)&u_s[su * 100 + c0]       = *(float4*)&uv[0];
            *(float4*)&u_s[(su + 1) * 100 + c0] = *(float4*)&uv[2];
            if (push_up) {
                *(float4*)&up_u[up_r0]       = *(float4*)&uv[0];
                *(float4*)&up_u[up_r0 + 100] = *(float4*)&uv[2];
            }
            if (push_dn) {
                *(float4*)&dn_u[dn_r0]       = *(float4*)&uv[0];
                *(float4*)&dn_u[dn_r0 + 100] = *(float4*)&uv[2];
            }
        }
        CL_ARRIVE();
        __syncthreads();

        if (ti == 2) {
            sten2x2(m, u_s, su, c0, tv);
            *(float4*)&t_s[st * 100 + c0]       = *(float4*)&tv[0];
            *(float4*)&t_s[(st + 1) * 100 + c0] = *(float4*)&tv[2];
        }
        CL_WAIT();
    }

    if (own) {
        int pr0 = (rank * 6 + lr) * NN + j0;
        g_Uz[pr0]          = uv[0];
        g_Uz[pr0 + 1]      = uv[1];
        g_Uz[pr0 + NN]     = uv[2];
        g_Uz[pr0 + NN + 1] = uv[3];
    }
}

// --- 8-CTA fallback ----------------------------------------------------------
__device__ __forceinline__ float2 sten13(const float* __restrict__ cf,
                                         const float2* __restrict__ buf,
                                         int s, int c)
{
    const int DI[13] = {0, 1, -1, 0, 0, 1, 1, -1, -1, 2, -2, 0, 0};
    const int DJ[13] = {0, 0, 0, 1, -1, 1, -1, 1, -1, 0, 0, 2, -2};
    float2 acc = make_float2(0.f, 0.f);
    #pragma unroll
    for (int o = 0; o < 13; o++) {
        float2 v = buf[(s + DI[o]) * 100 + (c + DJ[o])];
        acc.x = fmaf(cf[o], v.x, acc.x);
        acc.y = fmaf(cf[o], v.y, acc.y);
    }
    return acc;
}

__global__ void __cluster_dims__(8, 1, 1) __launch_bounds__(576, 1)
euler8_kernel(const int* __restrict__ steps_ptr)
{
    __shared__ float2 u_s[16 * 100];
    __shared__ float2 t_s[16 * 100];

    cg::cluster_group cl = cg::this_cluster();
    int tid   = threadIdx.x;
    int rank  = blockIdx.x;
    int steps = *steps_ptr;
    float dz  = 1.5f / (float)steps;

    for (int idx = tid; idx < 1600; idx += 576) {
        int s = idx / 100, c = idx % 100;
        int gi = rank * 12 + s - 2;
        int gj = c - 2;
        float2 v = make_float2(0.f, 0.f);
        if (gi >= 0 && gi < NN && gj >= 0 && gj < NN) v = g_U0[gi * NN + gj];
        u_s[idx] = v;
        t_s[idx] = make_float2(0.f, 0.f);
    }

    int li0 = tid / NN, lj = tid % NN;
    int li1 = li0 + 6;
    int s0  = li0 + 2, s1 = li1 + 2, c = lj + 2;
    int p0  = (rank * 12 + li0) * NN + lj;
    int p1  = p0 + 6 * NN;

    float m0[13], ci0[13], m1[13], ci1[13];
    #pragma unroll
    for (int o = 0; o < 13; o++) {
        m0[o]  = g_m [p0 * NOFF + o];
        ci0[o] = g_ci[p0 * NOFF + o];
        m1[o]  = g_m [p1 * NOFF + o];
        ci1[o] = g_ci[p1 * NOFF + o];
    }

    float2* up_u = (rank > 0) ? cl.map_shared_rank(u_s, rank - 1) : (float2*)0;
    float2* up_t = (rank > 0) ? cl.map_shared_rank(t_s, rank - 1) : (float2*)0;
    float2* dn_u = (rank < 7) ? cl.map_shared_rank(u_s, rank + 1) : (float2*)0;
    float2* dn_t = (rank < 7) ? cl.map_shared_rank(t_s, rank + 1) : (float2*)0;

    bool push_up = (rank > 0) && (li0 < 2);
    bool push_dn = (rank < 7) && (li0 >= 4);
    int  up_off  = (li0 + 14) * 100 + c;
    int  dn_off  = (li1 - 10) * 100 + c;

    cl.sync();

    for (int st = 0; st < steps; st++) {
        float2 t0 = sten13(m0, u_s, s0, c);
        float2 t1 = sten13(m1, u_s, s1, c);
        t_s[s0 * 100 + c] = t0;
        t_s[s1 * 100 + c] = t1;
        if (push_up) up_t[up_off] = t0;
        if (push_dn) dn_t[dn_off] = t1;
        cl.sync();

        float2 v0 = sten13(ci0, t_s, s0, c);
        float2 v1 = sten13(ci1, t_s, s1, c);
        float2 u0 = u_s[s0 * 100 + c];
        float2 u1 = u_s[s1 * 100 + c];
        u0.x = fmaf(-dz, v0.y, u0.x); u0.y = fmaf(dz, v0.x, u0.y);
        u1.x = fmaf(-dz, v1.y, u1.x); u1.y = fmaf(dz, v1.x, u1.y);
        u_s[s0 * 100 + c] = u0;
        u_s[s1 * 100 + c] = u1;
        if (push_up) up_u[up_off] = u0;
        if (push_dn) dn_u[dn_off] = u1;
        cl.sync();
    }

    g_Uz[p0] = u_s[s0 * 100 + c];
    g_Uz[p1] = u_s[s1 * 100 + c];
}

// ---------------- kernel 5: outer-product expansion -------------------------
__global__ __launch_bounds__(256) void expand_kernel(const float* __restrict__ prof_re,
                                                     const float* __restrict__ prof_im,
                                                     float* __restrict__ out)
{
    int gid = blockIdx.x * 256 + threadIdx.x;
    if (gid >= OUTPLANE) return;
    int y = gid / OUTSIDE, x = gid - y * OUTSIDE;
    int i = y >> 3, p = y & 7;
    int j = x >> 3, q = x & 7;
    int cell = i * NN + j;
    float2 u = g_Uz[cell];
    float  e = g_Eys[cell];
    float gr = u.x * e, gi = u.y * e;
    float pr = prof_re[p * 8 + q];
    float pi = prof_im[p * 8 + q];
    out[gid]            = gr * pr - gi * pi;
    out[OUTPLANE + gid] = gr * pi + gi * pr;
}

// ---------------- launch ----------------------------------------------------
extern "C" void kernel_launch(void* const* d_in, const int* in_sizes, int n_in,
                              void* d_out, int out_size)
{
    const float* h_paras = (const float*)d_in[0];
    const float* E0      = (const float*)d_in[1];
    const float* w1n = (const float*)d_in[2];
    const float* b1n = (const float*)d_in[3];
    const float* w2n = (const float*)d_in[4];
    const float* b2n = (const float*)d_in[5];
    const float* w3n = (const float*)d_in[6];
    const float* b3n = (const float*)d_in[7];
    const float* w1c = (const float*)d_in[8];
    const float* b1c = (const float*)d_in[9];
    const float* w2c = (const float*)d_in[10];
    const float* b2c = (const float*)d_in[11];
    const float* w3c = (const float*)d_in[12];
    const float* b3c = (const float*)d_in[13];
    const float* w1k = (const float*)d_in[14];
    const float* b1k = (const float*)d_in[15];
    const float* w2k = (const float*)d_in[16];
    const float* b2k = (const float*)d_in[17];
    const float* w3k = (const float*)d_in[18];
    const float* b3k = (const float*)d_in[19];
    const float* prof_re = (const float*)d_in[20];
    const float* prof_im = (const float*)d_in[21];
    const float* dis     = (const float*)d_in[22];
    const float* mask    = (const float*)d_in[23];
    const float* is_ctr  = (const float*)d_in[24];
    const int*   coo     = (const int*)d_in[25];
    const int*   steps   = (const int*)d_in[26];
    float* out = (float*)d_out;

    prep_kernel<<<(NSQ + 255) / 256, 256>>>(h_paras, E0);
    splitw2_kernel<<<32, 256>>>(w2c, w2k);
    mlp_kernel<<<NSQ / 128, 256>>>(0, w1n, b1n, w2n, b2n, w3n, b3n, dis, coo);

    cudaError_t aerr = cudaFuncSetAttribute(
        mlp_wmma_kernel, cudaFuncAttributeMaxDynamicSharedMemorySize, WM_SMEM);
    if (aerr == cudaSuccess) {
        mlp_wmma_kernel<<<2 * NEDGEBLK, 256, WM_SMEM>>>(
            w1c, b1c, b2c, w3c, b3c,
            w1k, b1k, b2k, w3k, b3k, dis, coo);
    } else {
        cudaGetLastError();
        mlp_kernel<<<NEDGEBLK, 256>>>(1, w1c, b1c, w2c, b2c, w3c, b3c, dis, coo);
        mlp_kernel<<<NEDGEBLK, 256>>>(2, w1k, b1k, w2k, b2k, w3k, b3k, dis, coo);
    }
    coeff_kernel<<<(NNZ + 255) / 256, 256>>>(mask, is_ctr);

    cudaError_t err = cudaFuncSetAttribute(
        euler16_kernel, cudaFuncAttributeNonPortableClusterSizeAllowed, 1);
    if (err == cudaSuccess) {
        cudaLaunchConfig_t cfg = {};
        cfg.gridDim  = dim3(16, 1, 1);
        cfg.blockDim = dim3(240, 1, 1);
        cfg.dynamicSmemBytes = 0;
        cfg.stream = 0;
        cudaLaunchAttribute attrs[1];
        attrs[0].id = cudaLaunchAttributeClusterDimension;
        attrs[0].val.clusterDim.x = 16;
        attrs[0].val.clusterDim.y = 1;
        attrs[0].val.clusterDim.z = 1;
        cfg.attrs = attrs;
        cfg.numAttrs = 1;
        err = cudaLaunchKernelEx(&cfg, euler16_kernel, steps);
    }
    if (err != cudaSuccess) {
        cudaGetLastError();
        euler8_kernel<<<8, 576>>>(steps);
    }

    expand_kernel<<<(OUTPLANE + 255) / 256, 256>>>(prof_re, prof_im, out);
}

// round 17
// speedup vs baseline: 1.8719x; 1.0876x over previous
#include <cuda_runtime.h>
#include <cuda_bf16.h>
#include <mma.h>
#include <cooperative_groups.h>
#include <math.h>
#include <stdint.h>

namespace cg = cooperative_groups;
using namespace nvcuda;

#define NN      96
#define NSQ     9216
#define NOFF    13
#define NNZ     119808
#define SIDE    816
#define BORD    24
#define KCONST  6.683942601602444f   /* 2*pi/0.94 */
#define OUTSIDE 768
#define OUTPLANE (OUTSIDE*OUTSIDE)
#define NEDGEBLK 936                 /* NNZ / 128 */

typedef unsigned long long u64;

// ---------------- scratch (static device globals; no allocation) ------------
__device__ float  g_hs[NSQ];
__device__ float  g_Eys[NSQ];
__device__ float  g_neff[NSQ];
__device__ float2 g_U0[NSQ];
__device__ float2 g_Uz[NSQ];
__device__ float  g_craw[NNZ];
__device__ float  g_kraw[NNZ];
__device__ float  g_m[NNZ];
__device__ float  g_ci[NNZ];
// pre-split w2 (bf16x2 packed pairs): 16384 floats -> 8192 uints per MLP
__device__ unsigned g_w2hi_c[8192];
__device__ unsigned g_w2lo_c[8192];
__device__ unsigned g_w2hi_k[8192];
__device__ unsigned g_w2lo_k[8192];

// ---------------- helpers ----------------------------------------------------
__device__ __forceinline__ u64 fma2(u64 a, u64 b, u64 c)
{
    u64 d;
    asm("fma.rn.f32x2 %0, %1, %2, %3;" : "=l"(d) : "l"(a), "l"(b), "l"(c));
    return d;
}
__device__ __forceinline__ u64 dup2(float x)
{
    u64 d;
    unsigned r = __float_as_uint(x);
    asm("mov.b64 %0, {%1, %1};" : "=l"(d) : "r"(r));
    return d;
}
__device__ __forceinline__ float lo32(u64 v) { return __uint_as_float((unsigned)v); }
__device__ __forceinline__ float hi32(u64 v) { return __uint_as_float((unsigned)(v >> 32)); }
__device__ __forceinline__ float tanha(float x)
{
    float y;
    asm("tanh.approx.f32 %0, %1;" : "=f"(y) : "f"(x));
    return y;
}
// pack truncated-bf16 of (f0, f1) -> (hi1<<16)|hi0
__device__ __forceinline__ unsigned pack_hi2(float f0, float f1)
{
    unsigned d;
    asm("prmt.b32 %0, %1, %2, 0x7632;"
        : "=r"(d) : "r"(__float_as_uint(f0)), "r"(__float_as_uint(f1)));
    return d;
}
// rn-bf16x2 of (lo0, lo1) -> (bf16(lo1)<<16)|bf16(lo0)
__device__ __forceinline__ unsigned pack_lo2(float lo0, float lo1)
{
    unsigned d;
    asm("cvt.rn.bf16x2.f32 %0, %1, %2;" : "=r"(d) : "f"(lo1), "f"(lo0));
    return d;
}
__device__ __forceinline__ float trunc16(float f)
{
    return __uint_as_float(__float_as_uint(f) & 0xFFFF0000u);
}

// ---------------- kernel 0: pre-split w2 into bf16 hi/lo --------------------
__global__ __launch_bounds__(256) void splitw2_kernel(const float* __restrict__ w2c,
                                                      const float* __restrict__ w2k)
{
    int i = blockIdx.x * 256 + threadIdx.x;      // pair index 0..8191
    if (i >= 8192) return;
    float2 c = *(const float2*)&w2c[2 * i];
    g_w2hi_c[i] = pack_hi2(c.x, c.y);
    g_w2lo_c[i] = pack_lo2(c.x - trunc16(c.x), c.y - trunc16(c.y));
    float2 k = *(const float2*)&w2k[2 * i];
    g_w2hi_k[i] = pack_hi2(k.x, k.y);
    g_w2lo_k[i] = pack_lo2(k.x - trunc16(k.x), k.y - trunc16(k.y));
}

// ---------------- kernel 1: hs / Eys / U0 (8x8 pooling) ---------------------
__global__ __launch_bounds__(256) void prep_kernel(const float* __restrict__ h_paras,
                                                   const float* __restrict__ E0)
{
    int p = blockIdx.x * 256 + threadIdx.x;
    if (p >= NSQ) return;
    float h  = h_paras[p];
    float s  = 1.f / (1.f + expf(-h));
    float hs = s * 0.6f + 0.2f;
    g_hs[p]  = hs;
    g_Eys[p] = 1.0f + 0.1f * tanhf(hs);
    float coupl = 0.5f + 0.5f * (1.f / (1.f + expf(-hs)));

    int i = p / NN, j = p % NN;
    const float* base = E0 + (size_t)(BORD + 8 * i) * SIDE + (BORD + 8 * j);
    float sum = 0.f;
    #pragma unroll
    for (int pi = 0; pi < 8; pi++) {
        float4 a = *(const float4*)(base + pi * SIDE);
        float4 b = *(const float4*)(base + pi * SIDE + 4);
        sum += (a.x + a.y) + (a.z + a.w) + (b.x + b.y) + (b.z + b.w);
    }
    g_U0[p] = make_float2(sum * (1.f / 64.f) * coupl, 0.f);
}

// ---------------- kernel 2a: fp32 MLP (mode 0 neff; fallback for 1/2) -------
__global__ __launch_bounds__(256, 2) void mlp_kernel(int mode,
    const float* __restrict__ w1, const float* __restrict__ b1,
    const float* __restrict__ w2, const float* __restrict__ b2,
    const float* __restrict__ w3, const float* __restrict__ b3,
    const float* __restrict__ dis, const int* __restrict__ coo)
{
    __shared__ float h1s[32 * 128];
    __shared__ float w2s[32 * 128];
    __shared__ float xs[4 * 128];
    float* red = h1s;

    int tid  = threadIdx.x;
    int base = blockIdx.x * 128;

    if (tid < 128) {
        int e = base + tid;
        if (mode == 0) {
            xs[tid] = g_hs[e];
        } else {
            int r = coo[e];
            int c = coo[NNZ + e];
            xs[tid]       = g_hs[r];
            xs[128 + tid] = g_hs[c];
            xs[256 + tid] = dis[2 * e];
            xs[384 + tid] = dis[2 * e + 1];
        }
    }
    __syncthreads();

    int tx = tid & 15, ty = tid >> 4;
    u64 acc2[4][8];
    #pragma unroll
    for (int p = 0; p < 4; p++)
        #pragma unroll
        for (int j = 0; j < 8; j++) acc2[p][j] = 0ull;

    for (int kb = 0; kb < 4; kb++) {
        #pragma unroll
        for (int it = 0; it < 16; it++) {
            int idx = tid + it * 256;
            int kk  = idx >> 7;
            int e   = idx & 127;
            int k   = kb * 32 + kk;
            float a = b1[k] + xs[e] * w1[k];
            if (mode != 0) {
                a += xs[128 + e] * w1[128 + k] + xs[256 + e] * w1[256 + k]
                   + xs[384 + e] * w1[384 + k];
                h1s[kk * 128 + e] = tanha(a);
            } else {
                h1s[kk * 128 + e] = tanhf(a);
            }
            w2s[idx] = w2[kb * 4096 + idx];
        }
        __syncthreads();

        #pragma unroll 4
        for (int k = 0; k < 32; k++) {
            ulonglong2 A0 = *(const ulonglong2*)&h1s[k * 128 + tx * 8];
            ulonglong2 A1 = *(const ulonglong2*)&h1s[k * 128 + tx * 8 + 4];
            float4 c0 = *(const float4*)&w2s[k * 128 + ty * 8];
            float4 c1 = *(const float4*)&w2s[k * 128 + ty * 8 + 4];
            u64 ap[4] = {A0.x, A0.y, A1.x, A1.y};
            u64 bp[8] = {dup2(c0.x), dup2(c0.y), dup2(c0.z), dup2(c0.w),
                         dup2(c1.x), dup2(c1.y), dup2(c1.z), dup2(c1.w)};
            #pragma unroll
            for (int p = 0; p < 4; p++)
                #pragma unroll
                for (int j = 0; j < 8; j++)
                    acc2[p][j] = fma2(ap[p], bp[j], acc2[p][j]);
        }
        __syncthreads();
    }

    #pragma unroll
    for (int i = 0; i < 8; i++) {
        float part = 0.f;
        #pragma unroll
        for (int j = 0; j < 8; j++) {
            u64 v = acc2[i >> 1][j];
            float pre = ((i & 1) ? hi32(v) : lo32(v)) + b2[ty * 8 + j];
            float h2 = (mode != 0) ? tanha(pre) : tanhf(pre);
            part = fmaf(h2, w3[ty * 8 + j], part);
        }
        red[ty * 128 + tx * 8 + i] = part;
    }
    __syncthreads();
    if (tid < 128) {
        float s = b3[0];
        #pragma unroll
        for (int t = 0; t < 16; t++) s += red[t * 128 + tid];
        int e = base + tid;
        if (mode == 0)      g_neff[e] = s;
        else if (mode == 1) g_craw[e] = s;
        else                g_kraw[e] = s;
    }
}

// ---------------- kernel 2b: merged wmma bf16-split edge MLPs ---------------
// Grid = 2*936: blocks [0,936) = c-MLP, [936,1872) = k-MLP.
// Warp tiling 2M x 4N: warp (mg=wid>>1, ng=wid&1) owns M-tiles {2mg,2mg+1},
// N-tiles {4ng..4ng+3}. Cuts B-fragment LDSM redundancy 2x vs 1Mx8N.
#define WM_AL    40
#define WM_BL    136
#define WM_XS    0                     /* float[512] -> later red[256]   */
#define WM_AHI   2048                  /* bf16[128][40]          10240 B */
#define WM_ALO   12288
#define WM_BHI   22528                 /* bf16[32][136]           8704 B */
#define WM_BLO   31232
#define WM_STAGE 39936                 /* float[8][256]           8192 B */
#define WM_SMEM  48128

__global__ __launch_bounds__(256, 2) void mlp_wmma_kernel(
    const float* __restrict__ w1c, const float* __restrict__ b1c,
    const float* __restrict__ b2c, const float* __restrict__ w3c,
    const float* __restrict__ b3c,
    const float* __restrict__ w1k, const float* __restrict__ b1k,
    const float* __restrict__ b2k, const float* __restrict__ w3k,
    const float* __restrict__ b3k,
    const float* __restrict__ dis, const int* __restrict__ coo)
{
    extern __shared__ char dsm[];
    float*          xs  = (float*)(dsm + WM_XS);
    __nv_bfloat16*  Ahi = (__nv_bfloat16*)(dsm + WM_AHI);
    __nv_bfloat16*  Alo = (__nv_bfloat16*)(dsm + WM_ALO);
    __nv_bfloat16*  Bhi = (__nv_bfloat16*)(dsm + WM_BHI);
    __nv_bfloat16*  Blo = (__nv_bfloat16*)(dsm + WM_BLO);

    int  tid   = threadIdx.x;
    int  wid   = tid >> 5;
    int  lane  = tid & 31;
    bool is_k  = (blockIdx.x >= NEDGEBLK);
    int  base  = (is_k ? blockIdx.x - NEDGEBLK : blockIdx.x) * 128;

    const float*    w1   = is_k ? w1k : w1c;
    const float*    b1   = is_k ? b1k : b1c;
    const float*    b2   = is_k ? b2k : b2c;
    const float*    w3   = is_k ? w3k : w3c;
    const float*    b3   = is_k ? b3k : b3c;
    const unsigned* w2hi = is_k ? g_w2hi_k : g_w2hi_c;
    const unsigned* w2lo = is_k ? g_w2lo_k : g_w2lo_c;

    if (tid < 128) {
        int e = base + tid;
        int r = coo[e];
        int c = coo[NNZ + e];
        xs[tid]       = g_hs[r];
        xs[128 + tid] = g_hs[c];
        xs[256 + tid] = dis[2 * e];
        xs[384 + tid] = dis[2 * e + 1];
    }
    __syncthreads();

    // per-thread A-fill coordinates: e = tid>>1, k-half = (tid&1)*16
    int ea  = tid >> 1;
    int khh = (tid & 1) << 4;
    u64 x0 = dup2(xs[ea]);
    u64 x1 = dup2(xs[128 + ea]);
    u64 x2 = dup2(xs[256 + ea]);
    u64 x3 = dup2(xs[384 + ea]);

    int mg = wid >> 1;            // 0..3 -> M rows [mg*32, mg*32+32)
    int ng = wid & 1;             // 0..1 -> N cols [ng*64, ng*64+64)

    wmma::fragment<wmma::accumulator, 16, 16, 16, float> acc[2][4];
    #pragma unroll
    for (int mi = 0; mi < 2; mi++)
        #pragma unroll
        for (int ni = 0; ni < 4; ni++) wmma::fill_fragment(acc[mi][ni], 0.f);

    for (int kb = 0; kb < 4; kb++) {
        // ---- A fill: layer-1 (packed fma2) + tanh + split ----
        #pragma unroll
        for (int i = 0; i < 16; i += 2) {
            int kl = khh + i;
            int k  = kb * 32 + kl;
            u64 a2 = *(const u64*)&b1[k];
            a2 = fma2(x0, *(const u64*)&w1[k],       a2);
            a2 = fma2(x1, *(const u64*)&w1[128 + k], a2);
            a2 = fma2(x2, *(const u64*)&w1[256 + k], a2);
            a2 = fma2(x3, *(const u64*)&w1[384 + k], a2);
            float f0 = tanha(lo32(a2));
            float f1 = tanha(hi32(a2));
            unsigned hi2 = pack_hi2(f0, f1);
            unsigned lo2 = pack_lo2(f0 - trunc16(f0), f1 - trunc16(f1));
            *(unsigned*)&Ahi[ea * WM_AL + kl] = hi2;
            *(unsigned*)&Alo[ea * WM_AL + kl] = lo2;
        }
        // ---- B fill: pre-split bf16, uint4 copy ----
        #pragma unroll
        for (int it = 0; it < 2; it++) {
            int idx4 = kb * 512 + it * 256 + tid;     // uint4 index
            uint4 hv = *(const uint4*)&w2hi[idx4 * 4];
            uint4 lv = *(const uint4*)&w2lo[idx4 * 4];
            int f  = idx4 * 8;                        // flat bf16 index
            int kr = (f >> 7) & 31;
            int n  = f & 127;
            *(uint4*)&Bhi[kr * WM_BL + n] = hv;
            *(uint4*)&Blo[kr * WM_BL + n] = lv;
        }
        __syncthreads();

        #pragma unroll
        for (int kk = 0; kk < 32; kk += 16) {
            wmma::fragment<wmma::matrix_a, 16, 16, 16, __nv_bfloat16, wmma::row_major> a_hi[2], a_lo[2];
            #pragma unroll
            for (int mi = 0; mi < 2; mi++) {
                int mrow = mg * 32 + mi * 16;
                wmma::load_matrix_sync(a_hi[mi], Ahi + mrow * WM_AL + kk, WM_AL);
                wmma::load_matrix_sync(a_lo[mi], Alo + mrow * WM_AL + kk, WM_AL);
            }
            #pragma unroll
            for (int ni = 0; ni < 4; ni++) {
                int ncol = ng * 64 + ni * 16;
                wmma::fragment<wmma::matrix_b, 16, 16, 16, __nv_bfloat16, wmma::row_major> b_hi, b_lo;
                wmma::load_matrix_sync(b_hi, Bhi + kk * WM_BL + ncol, WM_BL);
                wmma::load_matrix_sync(b_lo, Blo + kk * WM_BL + ncol, WM_BL);
                #pragma unroll
                for (int mi = 0; mi < 2; mi++) {
                    wmma::mma_sync(acc[mi][ni], a_hi[mi], b_hi, acc[mi][ni]);
                    wmma::mma_sync(acc[mi][ni], a_hi[mi], b_lo, acc[mi][ni]);
                    wmma::mma_sync(acc[mi][ni], a_lo[mi], b_hi, acc[mi][ni]);
                }
            }
        }
        __syncthreads();
    }

    // epilogue: stage per acc tile, tanh + w3 dot, shfl pair-reduce,
    // then cross-warp (ng) combine via red[] overlaid on dead xs.
    float* red   = (float*)(dsm + WM_XS);     // 256 floats: [row][ng]
    float* stage = (float*)(dsm + WM_STAGE) + wid * 256;
    int r  = lane >> 1;
    int hf = lane & 1;
    #pragma unroll
    for (int mi = 0; mi < 2; mi++) {
        float row_acc = 0.f;
        #pragma unroll
        for (int ni = 0; ni < 4; ni++) {
            wmma::store_matrix_sync(stage, acc[mi][ni], 16, wmma::mem_row_major);
            __syncwarp();
            float part = 0.f;
            #pragma unroll
            for (int j = 0; j < 8; j++) {
                int col = ng * 64 + ni * 16 + hf * 8 + j;
                float v = stage[r * 16 + hf * 8 + j] + b2[col];
                part = fmaf(tanha(v), w3[col], part);
            }
            row_acc += part;
            __syncwarp();
        }
        float other = __shfl_xor_sync(0xFFFFFFFFu, row_acc, 1);
        if (hf == 0) {
            int row = mg * 32 + mi * 16 + r;
            red[row * 2 + ng] = row_acc + other;
        }
    }
    __syncthreads();
    if (tid < 128) {
        float s = b3[0] + red[tid * 2] + red[tid * 2 + 1];
        int e = base + tid;
        if (is_k) g_kraw[e] = s;
        else      g_craw[e] = s;
    }
}

// ---------------- kernel 3: edge coefficients -------------------------------
__global__ __launch_bounds__(256) void coeff_kernel(const float* __restrict__ mask,
                                                    const float* __restrict__ is_center)
{
    int e = blockIdx.x * 256 + threadIdx.x;
    if (e >= NNZ) return;
    float msk = mask[e];
    float ic  = is_center[e];
    float c   = msk * 0.05f * tanhf(g_craw[e]) + ic;
    float kv  = msk * 0.10f * tanhf(g_kraw[e]);
    int   r   = e / NOFF;
    g_m[e]  = KCONST * g_neff[r] * c + kv;
    g_ci[e] = 2.0f * ic - c;
}

// ---------------- kernel 4: Euler loop (R9 proven) --------------------------
#define CL_ARRIVE() asm volatile("barrier.cluster.arrive.aligned;" ::: "memory")
#define CL_WAIT()   asm volatile("barrier.cluster.wait.aligned;"   ::: "memory")

__device__ __forceinline__ void sten2x2(const float cf[4][13],
                                        const float2* __restrict__ buf,
                                        int s, int c0, float2* __restrict__ out)
{
    float2 wm2[2], wm1[6], w0[6], wp1[6], wp2[6], wp3[2];
    {
        const float2* b;
        b = buf + (s - 2) * 100;
        *(float4*)&wm2[0] = *(const float4*)&b[c0];
        b = buf + (s - 1) * 100;
        *(float4*)&wm1[0] = *(const float4*)&b[c0 - 2];
        *(float4*)&wm1[2] = *(const float4*)&b[c0];
        *(float4*)&wm1[4] = *(const float4*)&b[c0 + 2];
        b = buf + s * 100;
        *(float4*)&w0[0]  = *(const float4*)&b[c0 - 2];
        *(float4*)&w0[2]  = *(const float4*)&b[c0];
        *(float4*)&w0[4]  = *(const float4*)&b[c0 + 2];
        b = buf + (s + 1) * 100;
        *(float4*)&wp1[0] = *(const float4*)&b[c0 - 2];
        *(float4*)&wp1[2] = *(const float4*)&b[c0];
        *(float4*)&wp1[4] = *(const float4*)&b[c0 + 2];
        b = buf + (s + 2) * 100;
        *(float4*)&wp2[0] = *(const float4*)&b[c0 - 2];
        *(float4*)&wp2[2] = *(const float4*)&b[c0];
        *(float4*)&wp2[4] = *(const float4*)&b[c0 + 2];
        b = buf + (s + 3) * 100;
        *(float4*)&wp3[0] = *(const float4*)&b[c0];
    }

#define ACC(o, v) { acc.x = fmaf(f[o], (v).x, acc.x); acc.y = fmaf(f[o], (v).y, acc.y); }
    #pragma unroll
    for (int k = 0; k < 2; k++) {
        {
            const float* f = cf[k];
            float2 acc = make_float2(0.f, 0.f);
            ACC(0,  w0 [k + 2]); ACC(1,  wp1[k + 2]); ACC(2,  wm1[k + 2]);
            ACC(3,  w0 [k + 3]); ACC(4,  w0 [k + 1]); ACC(5,  wp1[k + 3]);
            ACC(6,  wp1[k + 1]); ACC(7,  wm1[k + 3]); ACC(8,  wm1[k + 1]);
            ACC(9,  wp2[k + 2]); ACC(10, wm2[k]);     ACC(11, w0 [k + 4]);
            ACC(12, w0 [k]);
            out[k] = acc;
        }
        {
            const float* f = cf[2 + k];
            float2 acc = make_float2(0.f, 0.f);
            ACC(0,  wp1[k + 2]); ACC(1,  wp2[k + 2]); ACC(2,  w0 [k + 2]);
            ACC(3,  wp1[k + 3]); ACC(4,  wp1[k + 1]); ACC(5,  wp2[k + 3]);
            ACC(6,  wp2[k + 1]); ACC(7,  w0 [k + 3]); ACC(8,  w0 [k + 1]);
            ACC(9,  wp3[k]);     ACC(10, wm1[k + 2]); ACC(11, wp1[k + 4]);
            ACC(12, wp1[k]);
            out[2 + k] = acc;
        }
    }
#undef ACC
}

__global__ void __launch_bounds__(240, 1)
euler16_kernel(const int* __restrict__ steps_ptr)
{
    __shared__ float2 u_s[14 * 100];
    __shared__ float2 t_s[10 * 100];

    int tid   = threadIdx.x;
    int rank  = blockIdx.x;
    int steps = *steps_ptr;
    float dz  = 1.5f / (float)steps;

    for (int idx = tid; idx < 1400; idx += 240) {
        int su = idx / 100, c = idx % 100;
        int gi = rank * 6 + su - 4;
        int gj = c - 2;
        float2 v = make_float2(0.f, 0.f);
        if (gi >= 0 && gi < NN && gj >= 0 && gj < NN) v = g_U0[gi * NN + gj];
        u_s[idx] = v;
    }
    for (int idx = tid; idx < 1000; idx += 240)
        t_s[idx] = make_float2(0.f, 0.f);

    int tj = tid % 48;
    int ti = tid / 48;
    int lr = 2 * ti - 2;
    int j0 = 2 * tj;
    int c0 = j0 + 2;
    int su = lr + 4;
    int st = lr + 2;
    bool own = (ti >= 1 && ti <= 3);

    float m[4][13], ci[4][13];
    #pragma unroll
    for (int pt = 0; pt < 4; pt++) {
        int grow = rank * 6 + lr + (pt >> 1);
        int col  = j0 + (pt & 1);
        bool val = (grow >= 0) && (grow < NN);
        int p    = val ? (grow * NN + col) : 0;
        #pragma unroll
        for (int o = 0; o < NOFF; o++)
            m[pt][o] = val ? g_m[p * NOFF + o] : 0.f;
    }
    float2 uv[4];
    if (own) {
        #pragma unroll
        for (int pt = 0; pt < 4; pt++) {
            int p = (rank * 6 + lr + (pt >> 1)) * NN + (j0 + (pt & 1));
            #pragma unroll
            for (int o = 0; o < NOFF; o++)
                ci[pt][o] = g_ci[p * NOFF + o];
        }
        int pr0 = (rank * 6 + lr) * NN + j0;
        uv[0] = g_U0[pr0];
        uv[1] = g_U0[pr0 + 1];
        uv[2] = g_U0[pr0 + NN];
        uv[3] = g_U0[pr0 + NN + 1];
    }

    cg::cluster_group cl = cg::this_cluster();
    float2* up_u = (rank > 0)  ? cl.map_shared_rank(u_s, rank - 1) : (float2*)0;
    float2* dn_u = (rank < 15) ? cl.map_shared_rank(u_s, rank + 1) : (float2*)0;

    bool push_up = (rank > 0)  && (ti == 1 || ti == 2);
    bool push_dn = (rank < 15) && (ti == 2 || ti == 3);
    int  up_r0 = (ti == 1 ? 10 : 12) * 100 + c0;
    int  dn_r0 = (ti == 2 ? 0 : 2) * 100 + c0;

    __syncthreads();
    CL_ARRIVE(); CL_WAIT();

    float2 tv[4], vv[4];
    for (int st_i = 0; st_i < steps; st_i++) {
        if (!(ti == 2 && st_i > 0)) {
            sten2x2(m, u_s, su, c0, tv);
            *(float4*)&t_s[st * 100 + c0]       = *(float4*)&tv[0];
            *(float4*)&t_s[(st + 1) * 100 + c0] = *(float4*)&tv[2];
        }
        __syncthreads();

        if (own) {
            sten2x2(ci, t_s, st, c0, vv);
            #pragma unroll
            for (int q = 0; q < 4; q++) {
                uv[q].x = fmaf(-dz, vv[q].y, uv[q].x);
                uv[q].y = fmaf( dz, vv[q].x, uv[q].y);
            }
        }
        if (st_i + 1 == steps) break;

        if (own) {
            *(float4*)&u_s[su * 100 + c0]       = *(float4*)&uv[0];
            *(float4*)&u_s[(su + 1) * 100 + c0] = *(float4*)&uv[2];
            if (push_up) {
                *(float4*)&up_u[up_r0]       = *(float4*)&uv[0];
                *(float4*)&up_u[up_r0 + 100] = *(float4*)&uv[2];
            }
            if (push_dn) {
                *(float4*)&dn_u[dn_r0]       = *(float4*)&uv[0];
                *(float4*)&dn_u[dn_r0 + 100] = *(float4*)&uv[2];
            }
        }
        CL_ARRIVE();
        __syncthreads();

        if (ti == 2) {
            sten2x2(m, u_s, su, c0, tv);
            *(float4*)&t_s[st * 100 + c0]       = *(float4*)&tv[0];
            *(float4*)&t_s[(st + 1) * 100 + c0] = *(float4*)&tv[2];
        }
        CL_WAIT();
    }

    if (own) {
        int pr0 = (rank * 6 + lr) * NN + j0;
        g_Uz[pr0]          = uv[0];
        g_Uz[pr0 + 1]      = uv[1];
        g_Uz[pr0 + NN]     = uv[2];
        g_Uz[pr0 + NN + 1] = uv[3];
    }
}

// --- 8-CTA fallback ----------------------------------------------------------
__device__ __forceinline__ float2 sten13(const float* __restrict__ cf,
                                         const float2* __restrict__ buf,
                                         int s, int c)
{
    const int DI[13] = {0, 1, -1, 0, 0, 1, 1, -1, -1, 2, -2, 0, 0};
    const int DJ[13] = {0, 0, 0, 1, -1, 1, -1, 1, -1, 0, 0, 2, -2};
    float2 acc = make_float2(0.f, 0.f);
    #pragma unroll
    for (int o = 0; o < 13; o++) {
        float2 v = buf[(s + DI[o]) * 100 + (c + DJ[o])];
        acc.x = fmaf(cf[o], v.x, acc.x);
        acc.y = fmaf(cf[o], v.y, acc.y);
    }
    return acc;
}

__global__ void __cluster_dims__(8, 1, 1) __launch_bounds__(576, 1)
euler8_kernel(const int* __restrict__ steps_ptr)
{
    __shared__ float2 u_s[16 * 100];
    __shared__ float2 t_s[16 * 100];

    cg::cluster_group cl = cg::this_cluster();
    int tid   = threadIdx.x;
    int rank  = blockIdx.x;
    int steps = *steps_ptr;
    float dz  = 1.5f / (float)steps;

    for (int idx = tid; idx < 1600; idx += 576) {
        int s = idx / 100, c = idx % 100;
        int gi = rank * 12 + s - 2;
        int gj = c - 2;
        float2 v = make_float2(0.f, 0.f);
        if (gi >= 0 && gi < NN && gj >= 0 && gj < NN) v = g_U0[gi * NN + gj];
        u_s[idx] = v;
        t_s[idx] = make_float2(0.f, 0.f);
    }

    int li0 = tid / NN, lj = tid % NN;
    int li1 = li0 + 6;
    int s0  = li0 + 2, s1 = li1 + 2, c = lj + 2;
    int p0  = (rank * 12 + li0) * NN + lj;
    int p1  = p0 + 6 * NN;

    float m0[13], ci0[13], m1[13], ci1[13];
    #pragma unroll
    for (int o = 0; o < 13; o++) {
        m0[o]  = g_m [p0 * NOFF + o];
        ci0[o] = g_ci[p0 * NOFF + o];
        m1[o]  = g_m [p1 * NOFF + o];
        ci1[o] = g_ci[p1 * NOFF + o];
    }

    float2* up_u = (rank > 0) ? cl.map_shared_rank(u_s, rank - 1) : (float2*)0;
    float2* up_t = (rank > 0) ? cl.map_shared_rank(t_s, rank - 1) : (float2*)0;
    float2* dn_u = (rank < 7) ? cl.map_shared_rank(u_s, rank + 1) : (float2*)0;
    float2* dn_t = (rank < 7) ? cl.map_shared_rank(t_s, rank + 1) : (float2*)0;

    bool push_up = (rank > 0) && (li0 < 2);
    bool push_dn = (rank < 7) && (li0 >= 4);
    int  up_off  = (li0 + 14) * 100 + c;
    int  dn_off  = (li1 - 10) * 100 + c;

    cl.sync();

    for (int st = 0; st < steps; st++) {
        float2 t0 = sten13(m0, u_s, s0, c);
        float2 t1 = sten13(m1, u_s, s1, c);
        t_s[s0 * 100 + c] = t0;
        t_s[s1 * 100 + c] = t1;
        if (push_up) up_t[up_off] = t0;
        if (push_dn) dn_t[dn_off] = t1;
        cl.sync();

        float2 v0 = sten13(ci0, t_s, s0, c);
        float2 v1 = sten13(ci1, t_s, s1, c);
        float2 u0 = u_s[s0 * 100 + c];
        float2 u1 = u_s[s1 * 100 + c];
        u0.x = fmaf(-dz, v0.y, u0.x); u0.y = fmaf(dz, v0.x, u0.y);
        u1.x = fmaf(-dz, v1.y, u1.x); u1.y = fmaf(dz, v1.x, u1.y);
        u_s[s0 * 100 + c] = u0;
        u_s[s1 * 100 + c] = u1;
        if (push_up) up_u[up_off] = u0;
        if (push_dn) dn_u[dn_off] = u1;
        cl.sync();
    }

    g_Uz[p0] = u_s[s0 * 100 + c];
    g_Uz[p1] = u_s[s1 * 100 + c];
}

// ---------------- kernel 5: outer-product expansion -------------------------
__global__ __launch_bounds__(256) void expand_kernel(const float* __restrict__ prof_re,
                                                     const float* __restrict__ prof_im,
                                                     float* __restrict__ out)
{
    int gid = blockIdx.x * 256 + threadIdx.x;
    if (gid >= OUTPLANE) return;
    int y = gid / OUTSIDE, x = gid - y * OUTSIDE;
    int i = y >> 3, p = y & 7;
    int j = x >> 3, q = x & 7;
    int cell = i * NN + j;
    float2 u = g_Uz[cell];
    float  e = g_Eys[cell];
    float gr = u.x * e, gi = u.y * e;
    float pr = prof_re[p * 8 + q];
    float pi = prof_im[p * 8 + q];
    out[gid]            = gr * pr - gi * pi;
    out[OUTPLANE + gid] = gr * pi + gi * pr;
}

// ---------------- launch ----------------------------------------------------
extern "C" void kernel_launch(void* const* d_in, const int* in_sizes, int n_in,
                              void* d_out, int out_size)
{
    const float* h_paras = (const float*)d_in[0];
    const float* E0      = (const float*)d_in[1];
    const float* w1n = (const float*)d_in[2];
    const float* b1n = (const float*)d_in[3];
    const float* w2n = (const float*)d_in[4];
    const float* b2n = (const float*)d_in[5];
    const float* w3n = (const float*)d_in[6];
    const float* b3n = (const float*)d_in[7];
    const float* w1c = (const float*)d_in[8];
    const float* b1c = (const float*)d_in[9];
    const float* w2c = (const float*)d_in[10];
    const float* b2c = (const float*)d_in[11];
    const float* w3c = (const float*)d_in[12];
    const float* b3c = (const float*)d_in[13];
    const float* w1k = (const float*)d_in[14];
    const float* b1k = (const float*)d_in[15];
    const float* w2k = (const float*)d_in[16];
    const float* b2k = (const float*)d_in[17];
    const float* w3k = (const float*)d_in[18];
    const float* b3k = (const float*)d_in[19];
    const float* prof_re = (const float*)d_in[20];
    const float* prof_im = (const float*)d_in[21];
    const float* dis     = (const float*)d_in[22];
    const float* mask    = (const float*)d_in[23];
    const float* is_ctr  = (const float*)d_in[24];
    const int*   coo     = (const int*)d_in[25];
    const int*   steps   = (const int*)d_in[26];
    float* out = (float*)d_out;

    prep_kernel<<<(NSQ + 255) / 256, 256>>>(h_paras, E0);
    splitw2_kernel<<<32, 256>>>(w2c, w2k);
    mlp_kernel<<<NSQ / 128, 256>>>(0, w1n, b1n, w2n, b2n, w3n, b3n, dis, coo);

    cudaError_t aerr = cudaFuncSetAttribute(
        mlp_wmma_kernel, cudaFuncAttributeMaxDynamicSharedMemorySize, WM_SMEM);
    if (aerr == cudaSuccess) {
        mlp_wmma_kernel<<<2 * NEDGEBLK, 256, WM_SMEM>>>(
            w1c, b1c, b2c, w3c, b3c,
            w1k, b1k, b2k, w3k, b3k, dis, coo);
    } else {
        cudaGetLastError();
        mlp_kernel<<<NEDGEBLK, 256>>>(1, w1c, b1c, w2c, b2c, w3c, b3c, dis, coo);
        mlp_kernel<<<NEDGEBLK, 256>>>(2, w1k, b1k, w2k, b2k, w3k, b3k, dis, coo);
    }
    coeff_kernel<<<(NNZ + 255) / 256, 256>>>(mask, is_ctr);

    cudaError_t err = cudaFuncSetAttribute(
        euler16_kernel, cudaFuncAttributeNonPortableClusterSizeAllowed, 1);
    if (err == cudaSuccess) {
        cudaLaunchConfig_t cfg = {};
        cfg.gridDim  = dim3(16, 1, 1);
        cfg.blockDim = dim3(240, 1, 1);
        cfg.dynamicSmemBytes = 0;
        cfg.stream = 0;
        cudaLaunchAttribute attrs[1];
        attrs[0].id = cudaLaunchAttributeClusterDimension;
        attrs[0].val.clusterDim.x = 16;
        attrs[0].val.clusterDim.y = 1;
        attrs[0].val.clusterDim.z = 1;
        cfg.attrs = attrs;
        cfg.numAttrs = 1;
        err = cudaLaunchKernelEx(&cfg, euler16_kernel, steps);
    }
    if (err != cudaSuccess) {
        cudaGetLastError();
        euler8_kernel<<<8, 576>>>(steps);
    }

    expand_kernel<<<(OUTPLANE + 255) / 256, 256>>>(prof_re, prof_im, out);
}